// round 1
// baseline (speedup 1.0000x reference)
#include <cuda_runtime.h>
#include <math.h>

// Problem constants
#define SEQ 2048
#define BB  4
#define DD  1024
#define HH  16
#define DH  64
#define MM  (SEQ*BB)   // 8192 rows for GEMMs

// Scratch (device globals: allocation-free per harness rules)
__device__ float g_q[MM*DD];
__device__ float g_k[MM*DD];
__device__ float g_v[MM*DD];
__device__ float g_att[MM*DD];

// ---------------------------------------------------------------------------
// SGEMM: C[M,N] = A[M,K] @ W[N,K]^T + bias[N]   (M=8192, N=K=1024)
// 128x128 block tile, BK=16, 256 threads, 8x8 per thread, double buffered.
// ---------------------------------------------------------------------------
#define BM 128
#define BN 128
#define BK 16
#define GP 132   // padded row stride for transposed smem tiles

__global__ __launch_bounds__(256, 2)
void sgemm_bias_kernel(const float* __restrict__ A, const float* __restrict__ W,
                       const float* __restrict__ bias, float* __restrict__ C)
{
    __shared__ float As[2][BK][GP];
    __shared__ float Bs[2][BK][GP];

    const int tid = threadIdx.x;
    const int bm = blockIdx.y * BM;
    const int bn = blockIdx.x * BN;
    const int ty = tid >> 4;     // 0..15
    const int tx = tid & 15;     // 0..15

    // ---- load tile 0 ----
    #pragma unroll
    for (int u = 0; u < 2; u++) {
        int lin = tid + u * 256;      // 0..511
        int row = lin >> 2;           // 0..127
        int kc  = lin & 3;            // float4 index along K
        float4 a = *(const float4*)(A + (size_t)(bm + row) * DD + kc * 4);
        float4 b = *(const float4*)(W + (size_t)(bn + row) * DD + kc * 4);
        As[0][kc*4+0][row] = a.x; As[0][kc*4+1][row] = a.y;
        As[0][kc*4+2][row] = a.z; As[0][kc*4+3][row] = a.w;
        Bs[0][kc*4+0][row] = b.x; Bs[0][kc*4+1][row] = b.y;
        Bs[0][kc*4+2][row] = b.z; Bs[0][kc*4+3][row] = b.w;
    }
    __syncthreads();

    float acc[8][8];
    #pragma unroll
    for (int i = 0; i < 8; i++)
        #pragma unroll
        for (int j = 0; j < 8; j++) acc[i][j] = 0.0f;

    const int NT = DD / BK;   // 64 k-tiles
    for (int t = 0; t < NT; t++) {
        const int cur = t & 1;
        float4 pa[2], pb[2];
        if (t + 1 < NT) {
            const int k0 = (t + 1) * BK;
            #pragma unroll
            for (int u = 0; u < 2; u++) {
                int lin = tid + u * 256;
                int row = lin >> 2;
                int kc  = lin & 3;
                pa[u] = *(const float4*)(A + (size_t)(bm + row) * DD + k0 + kc * 4);
                pb[u] = *(const float4*)(W + (size_t)(bn + row) * DD + k0 + kc * 4);
            }
        }

        #pragma unroll 4
        for (int kk = 0; kk < BK; kk++) {
            float4 a0 = *(const float4*)&As[cur][kk][ty*4];
            float4 a1 = *(const float4*)&As[cur][kk][64 + ty*4];
            float4 b0 = *(const float4*)&Bs[cur][kk][tx*4];
            float4 b1 = *(const float4*)&Bs[cur][kk][64 + tx*4];
            float av[8] = {a0.x,a0.y,a0.z,a0.w,a1.x,a1.y,a1.z,a1.w};
            float bv[8] = {b0.x,b0.y,b0.z,b0.w,b1.x,b1.y,b1.z,b1.w};
            #pragma unroll
            for (int i = 0; i < 8; i++)
                #pragma unroll
                for (int j = 0; j < 8; j++)
                    acc[i][j] += av[i] * bv[j];
        }

        if (t + 1 < NT) {
            const int nxt = cur ^ 1;
            #pragma unroll
            for (int u = 0; u < 2; u++) {
                int lin = tid + u * 256;
                int row = lin >> 2;
                int kc  = lin & 3;
                As[nxt][kc*4+0][row] = pa[u].x; As[nxt][kc*4+1][row] = pa[u].y;
                As[nxt][kc*4+2][row] = pa[u].z; As[nxt][kc*4+3][row] = pa[u].w;
                Bs[nxt][kc*4+0][row] = pb[u].x; Bs[nxt][kc*4+1][row] = pb[u].y;
                Bs[nxt][kc*4+2][row] = pb[u].z; Bs[nxt][kc*4+3][row] = pb[u].w;
            }
        }
        __syncthreads();
    }

    // epilogue
    const float4 bias0 = *(const float4*)(bias + bn + tx*4);
    const float4 bias1 = *(const float4*)(bias + bn + 64 + tx*4);
    #pragma unroll
    for (int i = 0; i < 8; i++) {
        int r = bm + ((i < 4) ? (ty*4 + i) : (64 + ty*4 + (i - 4)));
        float4 o0, o1;
        o0.x = acc[i][0] + bias0.x; o0.y = acc[i][1] + bias0.y;
        o0.z = acc[i][2] + bias0.z; o0.w = acc[i][3] + bias0.w;
        o1.x = acc[i][4] + bias1.x; o1.y = acc[i][5] + bias1.y;
        o1.z = acc[i][6] + bias1.z; o1.w = acc[i][7] + bias1.w;
        *(float4*)(C + (size_t)r * DD + bn + tx*4)      = o0;
        *(float4*)(C + (size_t)r * DD + bn + 64 + tx*4) = o1;
    }
}

// ---------------------------------------------------------------------------
// Flash attention (fp32, causal + zero-sink).
// Grid: (S/64, H, B). Block: 256 threads. 64x64 Q tile, 64-key tiles.
// Smem layouts are contraction-major so both GEMM stages are float4
// outer products (conflict-free LDS.128).
//   Qt[dh][row], Kt[dh][key], Vs[key][dh], Pt[key][row], all stride FS.
// Sink handled exactly by m=0, l=1 initial state.
// ---------------------------------------------------------------------------
#define FS 68
#define FLASH_SMEM (4 * 64 * FS * 4)

__global__ __launch_bounds__(256)
void flash_attn_kernel(const float* __restrict__ q, const float* __restrict__ k,
                       const float* __restrict__ v, const float* __restrict__ beta,
                       float* __restrict__ o)
{
    extern __shared__ float sm[];
    float* Qt = sm;                // [64][FS]
    float* Kt = sm + 64 * FS;      // [64][FS]
    float* Vs = sm + 2 * 64 * FS;  // [64][FS]
    float* Pt = sm + 3 * 64 * FS;  // [64][FS]

    const int tid = threadIdx.x;
    const int qb = blockIdx.x, h = blockIdx.y, b = blockIdx.z;
    const int q0 = qb * 64;
    const int ty = tid >> 4, tx = tid & 15;
    const int r0 = ty * 4, c0 = tx * 4;
    const int RSTRIDE = BB * DD;   // 4096 floats between sequence positions

    const float inv_scale = 1.0f / (expf(beta[h]) * 8.0f);  // sqrt(DH)=8

    // load + scale + transpose Q tile
    const float* qbase = q + (size_t)q0 * RSTRIDE + b * DD + h * DH;
    #pragma unroll
    for (int u = 0; u < 4; u++) {
        int lin = tid + u * 256;   // 0..1023
        int row = lin >> 4;        // 0..63
        int c4  = lin & 15;
        float4 val = *(const float4*)(qbase + (size_t)row * RSTRIDE + c4 * 4);
        int d0 = c4 * 4;
        Qt[(d0+0)*FS + row] = val.x * inv_scale;
        Qt[(d0+1)*FS + row] = val.y * inv_scale;
        Qt[(d0+2)*FS + row] = val.z * inv_scale;
        Qt[(d0+3)*FS + row] = val.w * inv_scale;
    }

    float m[4] = {0.0f, 0.0f, 0.0f, 0.0f};   // sink score 0 included
    float l[4] = {1.0f, 1.0f, 1.0f, 1.0f};   // sink's exp(0-0)
    float acc[4][4];
    #pragma unroll
    for (int i = 0; i < 4; i++)
        #pragma unroll
        for (int j = 0; j < 4; j++) acc[i][j] = 0.0f;

    for (int jt = 0; jt <= qb; jt++) {
        const int j0 = jt * 64;
        __syncthreads();   // previous iter readers done before overwrite
        const float* kbase = k + (size_t)j0 * RSTRIDE + b * DD + h * DH;
        const float* vbase = v + (size_t)j0 * RSTRIDE + b * DD + h * DH;
        #pragma unroll
        for (int u = 0; u < 4; u++) {
            int lin = tid + u * 256;
            int key = lin >> 4;
            int c4  = lin & 15;
            float4 kv = *(const float4*)(kbase + (size_t)key * RSTRIDE + c4 * 4);
            float4 vv = *(const float4*)(vbase + (size_t)key * RSTRIDE + c4 * 4);
            int d0 = c4 * 4;
            Kt[(d0+0)*FS + key] = kv.x;
            Kt[(d0+1)*FS + key] = kv.y;
            Kt[(d0+2)*FS + key] = kv.z;
            Kt[(d0+3)*FS + key] = kv.w;
            *(float4*)&Vs[key * FS + d0] = vv;
        }
        __syncthreads();

        // S = (Q/scale) K^T, 4x4 per thread, outer-product form
        float s4[4][4];
        #pragma unroll
        for (int i = 0; i < 4; i++)
            #pragma unroll
            for (int j = 0; j < 4; j++) s4[i][j] = 0.0f;

        #pragma unroll 8
        for (int kk = 0; kk < 64; kk++) {
            float4 qv = *(const float4*)&Qt[kk * FS + r0];
            float4 kv = *(const float4*)&Kt[kk * FS + c0];
            float qa[4] = {qv.x, qv.y, qv.z, qv.w};
            float ka[4] = {kv.x, kv.y, kv.z, kv.w};
            #pragma unroll
            for (int i = 0; i < 4; i++)
                #pragma unroll
                for (int j = 0; j < 4; j++)
                    s4[i][j] += qa[i] * ka[j];
        }

        if (jt == qb) {  // diagonal tile: causal mask (j0 == q0)
            #pragma unroll
            for (int i = 0; i < 4; i++)
                #pragma unroll
                for (int j = 0; j < 4; j++)
                    if (c0 + j > r0 + i) s4[i][j] = -1e30f;
        }

        // online softmax update (rows owned by 16-lane groups)
        #pragma unroll
        for (int i = 0; i < 4; i++) {
            float rm = fmaxf(fmaxf(s4[i][0], s4[i][1]), fmaxf(s4[i][2], s4[i][3]));
            rm = fmaxf(rm, __shfl_xor_sync(0xffffffffu, rm, 1, 16));
            rm = fmaxf(rm, __shfl_xor_sync(0xffffffffu, rm, 2, 16));
            rm = fmaxf(rm, __shfl_xor_sync(0xffffffffu, rm, 4, 16));
            rm = fmaxf(rm, __shfl_xor_sync(0xffffffffu, rm, 8, 16));
            float mn = fmaxf(m[i], rm);
            float alpha = __expf(m[i] - mn);
            float rs = 0.0f;
            #pragma unroll
            for (int j = 0; j < 4; j++) {
                float p = __expf(s4[i][j] - mn);
                Pt[(c0 + j) * FS + (r0 + i)] = p;
                rs += p;
            }
            rs += __shfl_xor_sync(0xffffffffu, rs, 1, 16);
            rs += __shfl_xor_sync(0xffffffffu, rs, 2, 16);
            rs += __shfl_xor_sync(0xffffffffu, rs, 4, 16);
            rs += __shfl_xor_sync(0xffffffffu, rs, 8, 16);
            l[i] = l[i] * alpha + rs;
            m[i] = mn;
            acc[i][0] *= alpha; acc[i][1] *= alpha;
            acc[i][2] *= alpha; acc[i][3] *= alpha;
        }
        __syncthreads();

        // O += P V
        #pragma unroll 8
        for (int kk = 0; kk < 64; kk++) {
            float4 pv = *(const float4*)&Pt[kk * FS + r0];
            float4 vv = *(const float4*)&Vs[kk * FS + c0];
            float pa[4] = {pv.x, pv.y, pv.z, pv.w};
            float va[4] = {vv.x, vv.y, vv.z, vv.w};
            #pragma unroll
            for (int i = 0; i < 4; i++)
                #pragma unroll
                for (int j = 0; j < 4; j++)
                    acc[i][j] += pa[i] * va[j];
        }
    }

    // epilogue: normalize and store (s, b, h*DH + dh)
    float* obase = o + (size_t)q0 * RSTRIDE + b * DD + h * DH;
    #pragma unroll
    for (int i = 0; i < 4; i++) {
        float inv = 1.0f / l[i];
        float4 r;
        r.x = acc[i][0] * inv; r.y = acc[i][1] * inv;
        r.z = acc[i][2] * inv; r.w = acc[i][3] * inv;
        *(float4*)(obase + (size_t)(r0 + i) * RSTRIDE + c0) = r;
    }
}

// ---------------------------------------------------------------------------
extern "C" void kernel_launch(void* const* d_in, const int* in_sizes, int n_in,
                              void* d_out, int out_size)
{
    const float* x    = (const float*)d_in[0];
    // d_in[1] = attn_mask: exactly causal(-1e9) + sink column; implemented structurally
    const float* beta = (const float*)d_in[2];
    const float* Wq   = (const float*)d_in[3];
    const float* bq   = (const float*)d_in[4];
    const float* Wk   = (const float*)d_in[5];
    const float* bk   = (const float*)d_in[6];
    const float* Wv   = (const float*)d_in[7];
    const float* bv   = (const float*)d_in[8];
    const float* Wo   = (const float*)d_in[9];
    const float* bo   = (const float*)d_in[10];
    float* out = (float*)d_out;

    float *dq, *dk, *dv, *datt;
    cudaGetSymbolAddress((void**)&dq,   g_q);
    cudaGetSymbolAddress((void**)&dk,   g_k);
    cudaGetSymbolAddress((void**)&dv,   g_v);
    cudaGetSymbolAddress((void**)&datt, g_att);

    dim3 gblk(256);
    dim3 ggrid(DD / BN, MM / BM);   // (8, 64)

    sgemm_bias_kernel<<<ggrid, gblk>>>(x, Wq, bq, dq);
    sgemm_bias_kernel<<<ggrid, gblk>>>(x, Wk, bk, dk);
    sgemm_bias_kernel<<<ggrid, gblk>>>(x, Wv, bv, dv);

    cudaFuncSetAttribute(flash_attn_kernel,
                         cudaFuncAttributeMaxDynamicSharedMemorySize, FLASH_SMEM);
    dim3 fgrid(SEQ / 64, HH, BB);   // (32, 16, 4)
    flash_attn_kernel<<<fgrid, gblk, FLASH_SMEM>>>(dq, dk, dv, beta, datt);

    sgemm_bias_kernel<<<ggrid, gblk>>>(datt, Wo, bo, out);
}

// round 4
// speedup vs baseline: 1.3715x; 1.3715x over previous
#include <cuda_runtime.h>
#include <cuda_bf16.h>
#include <stdint.h>
#include <math.h>

// Problem constants
#define SEQ 2048
#define BB  4
#define DD  1024
#define HH  16
#define DH  64
#define MM  (SEQ*BB)   // 8192 rows for GEMMs

// ---------------- scratch (device globals; allocation-free) ----------------
__device__ float g_q[MM*DD];
__device__ float g_k[MM*DD];
__device__ float g_v[MM*DD];
__device__ float g_att[MM*DD];
__device__ __nv_bfloat16 g_xhi[MM*DD], g_xlo[MM*DD];
__device__ __nv_bfloat16 g_ahi[MM*DD], g_alo[MM*DD];
__device__ __nv_bfloat16 g_wqh[DD*DD], g_wql[DD*DD];
__device__ __nv_bfloat16 g_wkh[DD*DD], g_wkl[DD*DD];
__device__ __nv_bfloat16 g_wvh[DD*DD], g_wvl[DD*DD];
__device__ __nv_bfloat16 g_woh[DD*DD], g_wol[DD*DD];

// ---------------- PTX helpers (baseline ISA only: sm_80-level) ----------------
static __device__ __forceinline__ uint32_t s2u(const void* p) {
    return (uint32_t)__cvta_generic_to_shared(p);
}

#define CP_ASYNC16(saddr, gptr) \
    asm volatile("cp.async.cg.shared.global [%0], [%1], 16;" :: "r"(saddr), "l"(gptr))
#define CP_COMMIT() asm volatile("cp.async.commit_group;" ::: "memory")
#define CP_WAIT(n)  asm volatile("cp.async.wait_group %0;" :: "n"(n) : "memory")

static __device__ __forceinline__ void ldsm_x4(uint32_t addr,
    uint32_t &r0, uint32_t &r1, uint32_t &r2, uint32_t &r3)
{
    asm volatile("ldmatrix.sync.aligned.m8n8.x4.shared.b16 {%0,%1,%2,%3}, [%4];"
        : "=r"(r0), "=r"(r1), "=r"(r2), "=r"(r3) : "r"(addr));
}

static __device__ __forceinline__ void mma16816(float* d,
    uint32_t a0, uint32_t a1, uint32_t a2, uint32_t a3, uint32_t b0, uint32_t b1)
{
    asm volatile("mma.sync.aligned.m16n8k16.row.col.f32.bf16.bf16.f32 "
        "{%0,%1,%2,%3}, {%4,%5,%6,%7}, {%8,%9}, {%0,%1,%2,%3};"
        : "+f"(d[0]), "+f"(d[1]), "+f"(d[2]), "+f"(d[3])
        : "r"(a0), "r"(a1), "r"(a2), "r"(a3), "r"(b0), "r"(b1));
}

// ---------------- split: fp32 -> bf16 hi + bf16 lo ----------------
__global__ void split_kernel(const float* __restrict__ src,
                             __nv_bfloat16* __restrict__ hi,
                             __nv_bfloat16* __restrict__ lo, int n4)
{
    int i = blockIdx.x * blockDim.x + threadIdx.x;
    if (i >= n4) return;
    float4 v = ((const float4*)src)[i];
    __nv_bfloat16 h0 = __float2bfloat16(v.x), h1 = __float2bfloat16(v.y);
    __nv_bfloat16 h2 = __float2bfloat16(v.z), h3 = __float2bfloat16(v.w);
    __nv_bfloat16 l0 = __float2bfloat16(v.x - __bfloat162float(h0));
    __nv_bfloat16 l1 = __float2bfloat16(v.y - __bfloat162float(h1));
    __nv_bfloat16 l2 = __float2bfloat16(v.z - __bfloat162float(h2));
    __nv_bfloat16 l3 = __float2bfloat16(v.w - __bfloat162float(h3));
    __nv_bfloat162* hp = (__nv_bfloat162*)hi;
    __nv_bfloat162* lp = (__nv_bfloat162*)lo;
    hp[i*2+0] = __nv_bfloat162(h0, h1);
    hp[i*2+1] = __nv_bfloat162(h2, h3);
    lp[i*2+0] = __nv_bfloat162(l0, l1);
    lp[i*2+1] = __nv_bfloat162(l2, l3);
}

// ---------------------------------------------------------------------------
// HMMA GEMM: C[M,N] = (Ahi+Alo)[M,K] @ (Bhi+Blo)[N,K]^T + bias  (3-pass)
// 128x128x32 CTA tile, 8 warps (2x4), warp tile 64x32, mma.sync m16n8k16 bf16.
// cp.async double-buffered smem; padded 80-byte rows (conflict-free LDSM).
// ---------------------------------------------------------------------------
#define GBK 32
#define NC  (DD / GBK)                // 32 chunks
#define RSMEM 80                      // bytes per row (32 bf16 + 8 pad)
#define TILE_B (128 * RSMEM)          // 10240 B per tile
#define BUF_B  (4 * TILE_B)           // Ah, Al, Bh, Bl = 40960 B
#define GEMM_SMEM (2 * BUF_B)         // 81920 B

__global__ __launch_bounds__(256, 1)
void gemm_mma_kernel(const __nv_bfloat16* __restrict__ Ahi,
                     const __nv_bfloat16* __restrict__ Alo,
                     const __nv_bfloat16* __restrict__ Bhi,
                     const __nv_bfloat16* __restrict__ Blo,
                     const float* __restrict__ bias, float* __restrict__ C)
{
    extern __shared__ char smc[];
    const int tid  = threadIdx.x;
    const int wid  = tid >> 5;
    const int lane = tid & 31;
    const int bn = blockIdx.x * 128;
    const int bm = blockIdx.y * 128;
    const uint32_t sb = s2u(smc);

    const int warpM = wid >> 2;        // 0..1
    const int warpN = wid & 3;         // 0..3
    const int m0 = warpM * 64;
    const int n0 = warpN * 32;

    // gmem->smem loader mapping: 512 16B segs per tile, 2 per thread
    const int lrow0 = tid >> 2;            // rows tid/4 and tid/4+64
    const int lseg  = tid & 3;             // 16B seg within 64B of data

    const __nv_bfloat16* gsrc[4] = {Ahi, Alo, Bhi, Blo};
    const int rowbase[4] = {bm, bm, bn, bn};

    // prologue: chunk 0 -> buffer 0
    #pragma unroll
    for (int t = 0; t < 4; t++) {
        const __nv_bfloat16* g = gsrc[t] + (size_t)(rowbase[t]) * DD + lseg * 8;
        uint32_t sb_t = sb + t * TILE_B + lseg * 16;
        CP_ASYNC16(sb_t + lrow0 * RSMEM,        g + (size_t)lrow0 * DD);
        CP_ASYNC16(sb_t + (lrow0 + 64) * RSMEM, g + (size_t)(lrow0 + 64) * DD);
    }
    CP_COMMIT();

    float acc[4][4][4];
    #pragma unroll
    for (int mi = 0; mi < 4; mi++)
        #pragma unroll
        for (int ni = 0; ni < 4; ni++)
            #pragma unroll
            for (int f = 0; f < 4; f++) acc[mi][ni][f] = 0.0f;

    for (int c = 0; c < NC; c++) {
        if (c + 1 < NC) {
            const int k0 = (c + 1) * GBK;
            const uint32_t bufo = ((c + 1) & 1) * BUF_B;
            #pragma unroll
            for (int t = 0; t < 4; t++) {
                const __nv_bfloat16* g = gsrc[t] + (size_t)(rowbase[t]) * DD + k0 + lseg * 8;
                uint32_t sb_t = sb + bufo + t * TILE_B + lseg * 16;
                CP_ASYNC16(sb_t + lrow0 * RSMEM,        g + (size_t)lrow0 * DD);
                CP_ASYNC16(sb_t + (lrow0 + 64) * RSMEM, g + (size_t)(lrow0 + 64) * DD);
            }
            CP_COMMIT();
            CP_WAIT(1);
        } else {
            CP_WAIT(0);
        }
        __syncthreads();

        const uint32_t bufo = (c & 1) * BUF_B;
        const uint32_t Ah = sb + bufo + 0 * TILE_B;
        const uint32_t Al = sb + bufo + 1 * TILE_B;
        const uint32_t Bh = sb + bufo + 2 * TILE_B;
        const uint32_t Bl = sb + bufo + 3 * TILE_B;

        #pragma unroll
        for (int p = 0; p < 3; p++) {
            const uint32_t aB = (p == 2) ? Al : Ah;
            const uint32_t bB = (p == 1) ? Bl : Bh;
            #pragma unroll
            for (int s = 0; s < 2; s++) {
                const uint32_t kb = s * 32;   // byte offset of k16 step
                // B frags: two x4 loads cover 4 n-tiles x (k0-7, k8-15)
                uint32_t b[4][2];
                {
                    int g = lane >> 3;               // 0..3
                    int ntl = g >> 1, half = g & 1;
                    uint32_t addr0 = bB + (uint32_t)(n0 + ntl * 8 + (lane & 7)) * RSMEM
                                   + kb + half * 16;
                    uint32_t addr1 = addr0 + 16 * RSMEM;   // n-tiles 2,3
                    ldsm_x4(addr0, b[0][0], b[0][1], b[1][0], b[1][1]);
                    ldsm_x4(addr1, b[2][0], b[2][1], b[3][0], b[3][1]);
                }
                #pragma unroll
                for (int mi = 0; mi < 4; mi++) {
                    uint32_t a0, a1, a2, a3;
                    uint32_t addr = aB + (uint32_t)(m0 + mi * 16 + (lane & 15)) * RSMEM
                                  + kb + (lane >> 4) * 16;
                    ldsm_x4(addr, a0, a1, a2, a3);
                    #pragma unroll
                    for (int ni = 0; ni < 4; ni++)
                        mma16816(acc[mi][ni], a0, a1, a2, a3, b[ni][0], b[ni][1]);
                }
            }
        }
        __syncthreads();
    }

    // epilogue: d0,d1 -> (row lane/4, cols 2*(lane%4)+{0,1}); d2,d3 -> row+8
    const int erow = lane >> 2;
    const int ecol = (lane & 3) * 2;
    #pragma unroll
    for (int mi = 0; mi < 4; mi++) {
        #pragma unroll
        for (int ni = 0; ni < 4; ni++) {
            int gr0 = bm + m0 + mi * 16 + erow;
            int gc  = bn + n0 + ni * 8 + ecol;
            float2 v0, v1;
            v0.x = acc[mi][ni][0] + bias[gc];
            v0.y = acc[mi][ni][1] + bias[gc + 1];
            v1.x = acc[mi][ni][2] + bias[gc];
            v1.y = acc[mi][ni][3] + bias[gc + 1];
            *(float2*)(C + (size_t)gr0 * DD + gc)       = v0;
            *(float2*)(C + (size_t)(gr0 + 8) * DD + gc) = v1;
        }
    }
}

// ---------------------------------------------------------------------------
// Flash attention (fp32, causal + zero-sink) — unchanged from R1 (passing).
// ---------------------------------------------------------------------------
#define FS 68
#define FLASH_SMEM (4 * 64 * FS * 4)

__global__ __launch_bounds__(256)
void flash_attn_kernel(const float* __restrict__ q, const float* __restrict__ k,
                       const float* __restrict__ v, const float* __restrict__ beta,
                       float* __restrict__ o)
{
    extern __shared__ float smf[];
    float* Qt = smf;
    float* Kt = smf + 64 * FS;
    float* Vs = smf + 2 * 64 * FS;
    float* Pt = smf + 3 * 64 * FS;

    const int tid = threadIdx.x;
    const int qb = blockIdx.x, h = blockIdx.y, b = blockIdx.z;
    const int q0 = qb * 64;
    const int ty = tid >> 4, tx = tid & 15;
    const int r0 = ty * 4, c0 = tx * 4;
    const int RSTRIDE = BB * DD;

    const float inv_scale = 1.0f / (expf(beta[h]) * 8.0f);

    const float* qbase = q + (size_t)q0 * RSTRIDE + b * DD + h * DH;
    #pragma unroll
    for (int u = 0; u < 4; u++) {
        int lin = tid + u * 256;
        int row = lin >> 4;
        int c4  = lin & 15;
        float4 val = *(const float4*)(qbase + (size_t)row * RSTRIDE + c4 * 4);
        int d0 = c4 * 4;
        Qt[(d0+0)*FS + row] = val.x * inv_scale;
        Qt[(d0+1)*FS + row] = val.y * inv_scale;
        Qt[(d0+2)*FS + row] = val.z * inv_scale;
        Qt[(d0+3)*FS + row] = val.w * inv_scale;
    }

    float m[4] = {0.0f, 0.0f, 0.0f, 0.0f};
    float l[4] = {1.0f, 1.0f, 1.0f, 1.0f};
    float acc[4][4];
    #pragma unroll
    for (int i = 0; i < 4; i++)
        #pragma unroll
        for (int j = 0; j < 4; j++) acc[i][j] = 0.0f;

    for (int jt = 0; jt <= qb; jt++) {
        const int j0 = jt * 64;
        __syncthreads();
        const float* kbase = k + (size_t)j0 * RSTRIDE + b * DD + h * DH;
        const float* vbase = v + (size_t)j0 * RSTRIDE + b * DD + h * DH;
        #pragma unroll
        for (int u = 0; u < 4; u++) {
            int lin = tid + u * 256;
            int key = lin >> 4;
            int c4  = lin & 15;
            float4 kv = *(const float4*)(kbase + (size_t)key * RSTRIDE + c4 * 4);
            float4 vv = *(const float4*)(vbase + (size_t)key * RSTRIDE + c4 * 4);
            int d0 = c4 * 4;
            Kt[(d0+0)*FS + key] = kv.x;
            Kt[(d0+1)*FS + key] = kv.y;
            Kt[(d0+2)*FS + key] = kv.z;
            Kt[(d0+3)*FS + key] = kv.w;
            *(float4*)&Vs[key * FS + d0] = vv;
        }
        __syncthreads();

        float s4[4][4];
        #pragma unroll
        for (int i = 0; i < 4; i++)
            #pragma unroll
            for (int j = 0; j < 4; j++) s4[i][j] = 0.0f;

        #pragma unroll 8
        for (int kk = 0; kk < 64; kk++) {
            float4 qv = *(const float4*)&Qt[kk * FS + r0];
            float4 kv = *(const float4*)&Kt[kk * FS + c0];
            float qa[4] = {qv.x, qv.y, qv.z, qv.w};
            float ka[4] = {kv.x, kv.y, kv.z, kv.w};
            #pragma unroll
            for (int i = 0; i < 4; i++)
                #pragma unroll
                for (int j = 0; j < 4; j++)
                    s4[i][j] += qa[i] * ka[j];
        }

        if (jt == qb) {
            #pragma unroll
            for (int i = 0; i < 4; i++)
                #pragma unroll
                for (int j = 0; j < 4; j++)
                    if (c0 + j > r0 + i) s4[i][j] = -1e30f;
        }

        #pragma unroll
        for (int i = 0; i < 4; i++) {
            float rm = fmaxf(fmaxf(s4[i][0], s4[i][1]), fmaxf(s4[i][2], s4[i][3]));
            rm = fmaxf(rm, __shfl_xor_sync(0xffffffffu, rm, 1, 16));
            rm = fmaxf(rm, __shfl_xor_sync(0xffffffffu, rm, 2, 16));
            rm = fmaxf(rm, __shfl_xor_sync(0xffffffffu, rm, 4, 16));
            rm = fmaxf(rm, __shfl_xor_sync(0xffffffffu, rm, 8, 16));
            float mn = fmaxf(m[i], rm);
            float alpha = __expf(m[i] - mn);
            float rs = 0.0f;
            #pragma unroll
            for (int j = 0; j < 4; j++) {
                float p = __expf(s4[i][j] - mn);
                Pt[(c0 + j) * FS + (r0 + i)] = p;
                rs += p;
            }
            rs += __shfl_xor_sync(0xffffffffu, rs, 1, 16);
            rs += __shfl_xor_sync(0xffffffffu, rs, 2, 16);
            rs += __shfl_xor_sync(0xffffffffu, rs, 4, 16);
            rs += __shfl_xor_sync(0xffffffffu, rs, 8, 16);
            l[i] = l[i] * alpha + rs;
            m[i] = mn;
            acc[i][0] *= alpha; acc[i][1] *= alpha;
            acc[i][2] *= alpha; acc[i][3] *= alpha;
        }
        __syncthreads();

        #pragma unroll 8
        for (int kk = 0; kk < 64; kk++) {
            float4 pv = *(const float4*)&Pt[kk * FS + r0];
            float4 vv = *(const float4*)&Vs[kk * FS + c0];
            float pa[4] = {pv.x, pv.y, pv.z, pv.w};
            float va[4] = {vv.x, vv.y, vv.z, vv.w};
            #pragma unroll
            for (int i = 0; i < 4; i++)
                #pragma unroll
                for (int j = 0; j < 4; j++)
                    acc[i][j] += pa[i] * va[j];
        }
    }

    float* obase = o + (size_t)q0 * RSTRIDE + b * DD + h * DH;
    #pragma unroll
    for (int i = 0; i < 4; i++) {
        float inv = 1.0f / l[i];
        float4 rr;
        rr.x = acc[i][0] * inv; rr.y = acc[i][1] * inv;
        rr.z = acc[i][2] * inv; rr.w = acc[i][3] * inv;
        *(float4*)(obase + (size_t)(r0 + i) * RSTRIDE + c0) = rr;
    }
}

// ---------------------------------------------------------------------------
extern "C" void kernel_launch(void* const* d_in, const int* in_sizes, int n_in,
                              void* d_out, int out_size)
{
    const float* x    = (const float*)d_in[0];
    const float* beta = (const float*)d_in[2];
    const float* Wq   = (const float*)d_in[3];
    const float* bq   = (const float*)d_in[4];
    const float* Wk   = (const float*)d_in[5];
    const float* bk   = (const float*)d_in[6];
    const float* Wv   = (const float*)d_in[7];
    const float* bv   = (const float*)d_in[8];
    const float* Wo   = (const float*)d_in[9];
    const float* bo   = (const float*)d_in[10];
    float* out = (float*)d_out;

    float *dq, *dk, *dv, *datt;
    cudaGetSymbolAddress((void**)&dq,   g_q);
    cudaGetSymbolAddress((void**)&dk,   g_k);
    cudaGetSymbolAddress((void**)&dv,   g_v);
    cudaGetSymbolAddress((void**)&datt, g_att);
    __nv_bfloat16 *xhi, *xlo, *ahi, *alo;
    __nv_bfloat16 *wqh, *wql, *wkh, *wkl, *wvh, *wvl, *woh, *wol;
    cudaGetSymbolAddress((void**)&xhi, g_xhi);
    cudaGetSymbolAddress((void**)&xlo, g_xlo);
    cudaGetSymbolAddress((void**)&ahi, g_ahi);
    cudaGetSymbolAddress((void**)&alo, g_alo);
    cudaGetSymbolAddress((void**)&wqh, g_wqh);
    cudaGetSymbolAddress((void**)&wql, g_wql);
    cudaGetSymbolAddress((void**)&wkh, g_wkh);
    cudaGetSymbolAddress((void**)&wkl, g_wkl);
    cudaGetSymbolAddress((void**)&wvh, g_wvh);
    cudaGetSymbolAddress((void**)&wvl, g_wvl);
    cudaGetSymbolAddress((void**)&woh, g_woh);
    cudaGetSymbolAddress((void**)&wol, g_wol);

    cudaFuncSetAttribute(gemm_mma_kernel,
                         cudaFuncAttributeMaxDynamicSharedMemorySize, GEMM_SMEM);
    cudaFuncSetAttribute(flash_attn_kernel,
                         cudaFuncAttributeMaxDynamicSharedMemorySize, FLASH_SMEM);

    const int nx4 = MM * DD / 4;
    const int nw4 = DD * DD / 4;

    split_kernel<<<(nx4 + 255) / 256, 256>>>(x, xhi, xlo, nx4);
    split_kernel<<<(nw4 + 255) / 256, 256>>>(Wq, wqh, wql, nw4);
    split_kernel<<<(nw4 + 255) / 256, 256>>>(Wk, wkh, wkl, nw4);
    split_kernel<<<(nw4 + 255) / 256, 256>>>(Wv, wvh, wvl, nw4);
    split_kernel<<<(nw4 + 255) / 256, 256>>>(Wo, woh, wol, nw4);

    dim3 ggrid(DD / 128, MM / 128);   // (8, 64)
    gemm_mma_kernel<<<ggrid, 256, GEMM_SMEM>>>(xhi, xlo, wqh, wql, bq, dq);
    gemm_mma_kernel<<<ggrid, 256, GEMM_SMEM>>>(xhi, xlo, wkh, wkl, bk, dk);
    gemm_mma_kernel<<<ggrid, 256, GEMM_SMEM>>>(xhi, xlo, wvh, wvl, bv, dv);

    dim3 fgrid(SEQ / 64, HH, BB);
    flash_attn_kernel<<<fgrid, 256, FLASH_SMEM>>>(dq, dk, dv, beta, datt);

    split_kernel<<<(nx4 + 255) / 256, 256>>>(datt, ahi, alo, nx4);
    gemm_mma_kernel<<<ggrid, 256, GEMM_SMEM>>>(ahi, alo, woh, wol, bo, out);
}

// round 5
// speedup vs baseline: 2.2735x; 1.6577x over previous
#include <cuda_runtime.h>
#include <cuda_bf16.h>
#include <stdint.h>
#include <math.h>

// Problem constants
#define SEQ 2048
#define BB  4
#define DD  1024
#define HH  16
#define DH  64
#define MM  (SEQ*BB)   // 8192 rows for GEMMs

// ---------------- scratch (device globals; allocation-free) ----------------
__device__ __nv_bfloat16 g_xhi[MM*DD], g_xlo[MM*DD];
__device__ __nv_bfloat16 g_wqh[DD*DD], g_wql[DD*DD];
__device__ __nv_bfloat16 g_wkh[DD*DD], g_wkl[DD*DD];
__device__ __nv_bfloat16 g_wvh[DD*DD], g_wvl[DD*DD];
__device__ __nv_bfloat16 g_woh[DD*DD], g_wol[DD*DD];
// q,k in [b,h,s,dh]; v transposed [b,h,dh,s]; att in [s,b,D] (hi/lo)
__device__ __nv_bfloat16 g_qh[MM*DD], g_ql[MM*DD];
__device__ __nv_bfloat16 g_kh[MM*DD], g_kl[MM*DD];
__device__ __nv_bfloat16 g_vh[MM*DD], g_vl[MM*DD];
__device__ __nv_bfloat16 g_ahi[MM*DD], g_alo[MM*DD];

// ---------------- PTX helpers (baseline ISA only) ----------------
static __device__ __forceinline__ uint32_t s2u(const void* p) {
    return (uint32_t)__cvta_generic_to_shared(p);
}

#define CP_ASYNC16(saddr, gptr) \
    asm volatile("cp.async.cg.shared.global [%0], [%1], 16;" :: "r"(saddr), "l"(gptr))
#define CP_COMMIT() asm volatile("cp.async.commit_group;" ::: "memory")
#define CP_WAIT(n)  asm volatile("cp.async.wait_group %0;" :: "n"(n) : "memory")

static __device__ __forceinline__ void ldsm_x4(uint32_t addr,
    uint32_t &r0, uint32_t &r1, uint32_t &r2, uint32_t &r3)
{
    asm volatile("ldmatrix.sync.aligned.m8n8.x4.shared.b16 {%0,%1,%2,%3}, [%4];"
        : "=r"(r0), "=r"(r1), "=r"(r2), "=r"(r3) : "r"(addr));
}

static __device__ __forceinline__ void mma16816(float* d,
    uint32_t a0, uint32_t a1, uint32_t a2, uint32_t a3, uint32_t b0, uint32_t b1)
{
    asm volatile("mma.sync.aligned.m16n8k16.row.col.f32.bf16.bf16.f32 "
        "{%0,%1,%2,%3}, {%4,%5,%6,%7}, {%8,%9}, {%0,%1,%2,%3};"
        : "+f"(d[0]), "+f"(d[1]), "+f"(d[2]), "+f"(d[3])
        : "r"(a0), "r"(a1), "r"(a2), "r"(a3), "r"(b0), "r"(b1));
}

static __device__ __forceinline__ uint32_t packbf(float x, float y) {
    __nv_bfloat162 t = __floats2bfloat162_rn(x, y);
    return *(uint32_t*)&t;
}
static __device__ __forceinline__ float lof(float x) {
    return x - __bfloat162float(__float2bfloat16_rn(x));
}

// ---------------- split: fp32 -> bf16 hi + bf16 lo ----------------
__global__ void split_kernel(const float* __restrict__ src,
                             __nv_bfloat16* __restrict__ hi,
                             __nv_bfloat16* __restrict__ lo, int n4)
{
    int i = blockIdx.x * blockDim.x + threadIdx.x;
    if (i >= n4) return;
    float4 v = ((const float4*)src)[i];
    __nv_bfloat162* hp = (__nv_bfloat162*)hi;
    __nv_bfloat162* lp = (__nv_bfloat162*)lo;
    hp[i*2+0] = __floats2bfloat162_rn(v.x, v.y);
    hp[i*2+1] = __floats2bfloat162_rn(v.z, v.w);
    lp[i*2+0] = __floats2bfloat162_rn(lof(v.x), lof(v.y));
    lp[i*2+1] = __floats2bfloat162_rn(lof(v.z), lof(v.w));
}

// ---------------------------------------------------------------------------
// HMMA GEMM: C = (Ahi+Alo)[M,K] @ (Bhi+Blo)[N,K]^T + bias  (3-pass)
// mode 0: fp32 out [s,b,D]
// mode 1: bf16 hi/lo out [b,h,s,dh]   (+ optional 1/(exp(beta_h)*8) scaling)
// mode 2: bf16 hi/lo out transposed [b,h,dh,s]
// ---------------------------------------------------------------------------
#define GBK 32
#define NCG (DD / GBK)
#define RSMEM 80
#define TILE_B (128 * RSMEM)
#define BUF_B  (4 * TILE_B)
#define GEMM_SMEM (2 * BUF_B)

__global__ __launch_bounds__(256, 1)
void gemm_mma_kernel(const __nv_bfloat16* __restrict__ Ahi,
                     const __nv_bfloat16* __restrict__ Alo,
                     const __nv_bfloat16* __restrict__ Bhi,
                     const __nv_bfloat16* __restrict__ Blo,
                     const float* __restrict__ bias,
                     int mode, const float* __restrict__ beta,
                     float* __restrict__ C,
                     __nv_bfloat16* __restrict__ Oh,
                     __nv_bfloat16* __restrict__ Ol)
{
    extern __shared__ char smc[];
    const int tid  = threadIdx.x;
    const int wid  = tid >> 5;
    const int lane = tid & 31;
    const int bn = blockIdx.x * 128;
    const int bm = blockIdx.y * 128;
    const uint32_t sb = s2u(smc);

    const int warpM = wid >> 2;
    const int warpN = wid & 3;
    const int m0 = warpM * 64;
    const int n0 = warpN * 32;

    const int lrow0 = tid >> 2;
    const int lseg  = tid & 3;

    const __nv_bfloat16* gsrc[4] = {Ahi, Alo, Bhi, Blo};
    const int rowbase[4] = {bm, bm, bn, bn};

    #pragma unroll
    for (int t = 0; t < 4; t++) {
        const __nv_bfloat16* g = gsrc[t] + (size_t)(rowbase[t]) * DD + lseg * 8;
        uint32_t sb_t = sb + t * TILE_B + lseg * 16;
        CP_ASYNC16(sb_t + lrow0 * RSMEM,        g + (size_t)lrow0 * DD);
        CP_ASYNC16(sb_t + (lrow0 + 64) * RSMEM, g + (size_t)(lrow0 + 64) * DD);
    }
    CP_COMMIT();

    float acc[4][4][4];
    #pragma unroll
    for (int mi = 0; mi < 4; mi++)
        #pragma unroll
        for (int ni = 0; ni < 4; ni++)
            #pragma unroll
            for (int f = 0; f < 4; f++) acc[mi][ni][f] = 0.0f;

    for (int c = 0; c < NCG; c++) {
        if (c + 1 < NCG) {
            const int k0 = (c + 1) * GBK;
            const uint32_t bufo = ((c + 1) & 1) * BUF_B;
            #pragma unroll
            for (int t = 0; t < 4; t++) {
                const __nv_bfloat16* g = gsrc[t] + (size_t)(rowbase[t]) * DD + k0 + lseg * 8;
                uint32_t sb_t = sb + bufo + t * TILE_B + lseg * 16;
                CP_ASYNC16(sb_t + lrow0 * RSMEM,        g + (size_t)lrow0 * DD);
                CP_ASYNC16(sb_t + (lrow0 + 64) * RSMEM, g + (size_t)(lrow0 + 64) * DD);
            }
            CP_COMMIT();
            CP_WAIT(1);
        } else {
            CP_WAIT(0);
        }
        __syncthreads();

        const uint32_t bufo = (c & 1) * BUF_B;
        const uint32_t Ah = sb + bufo + 0 * TILE_B;
        const uint32_t Al = sb + bufo + 1 * TILE_B;
        const uint32_t Bh = sb + bufo + 2 * TILE_B;
        const uint32_t Bl = sb + bufo + 3 * TILE_B;

        #pragma unroll
        for (int p = 0; p < 3; p++) {
            const uint32_t aB = (p == 2) ? Al : Ah;
            const uint32_t bB = (p == 1) ? Bl : Bh;
            #pragma unroll
            for (int s = 0; s < 2; s++) {
                const uint32_t kb = s * 32;
                uint32_t b[4][2];
                {
                    int g = lane >> 3;
                    int ntl = g >> 1, half = g & 1;
                    uint32_t addr0 = bB + (uint32_t)(n0 + ntl * 8 + (lane & 7)) * RSMEM
                                   + kb + half * 16;
                    uint32_t addr1 = addr0 + 16 * RSMEM;
                    ldsm_x4(addr0, b[0][0], b[0][1], b[1][0], b[1][1]);
                    ldsm_x4(addr1, b[2][0], b[2][1], b[3][0], b[3][1]);
                }
                #pragma unroll
                for (int mi = 0; mi < 4; mi++) {
                    uint32_t a0, a1, a2, a3;
                    uint32_t addr = aB + (uint32_t)(m0 + mi * 16 + (lane & 15)) * RSMEM
                                  + kb + (lane >> 4) * 16;
                    ldsm_x4(addr, a0, a1, a2, a3);
                    #pragma unroll
                    for (int ni = 0; ni < 4; ni++)
                        mma16816(acc[mi][ni], a0, a1, a2, a3, b[ni][0], b[ni][1]);
                }
            }
        }
        __syncthreads();
    }

    const int erow = lane >> 2;
    const int ecol = (lane & 3) * 2;
    #pragma unroll
    for (int mi = 0; mi < 4; mi++) {
        #pragma unroll
        for (int ni = 0; ni < 4; ni++) {
            int gr = bm + m0 + mi * 16 + erow;
            int gc = bn + n0 + ni * 8 + ecol;
            float v0x = acc[mi][ni][0] + bias[gc];
            float v0y = acc[mi][ni][1] + bias[gc + 1];
            float v1x = acc[mi][ni][2] + bias[gc];
            float v1y = acc[mi][ni][3] + bias[gc + 1];
            if (mode == 0) {
                float2 a = {v0x, v0y}, bb2 = {v1x, v1y};
                *(float2*)(C + (size_t)gr * DD + gc)       = a;
                *(float2*)(C + (size_t)(gr + 8) * DD + gc) = bb2;
            } else {
                int hh = gc >> 6, dh = gc & 63;
                if (beta) {
                    float sc = 1.0f / (__expf(beta[hh]) * 8.0f);
                    v0x *= sc; v0y *= sc; v1x *= sc; v1y *= sc;
                }
                int s0 = gr >> 2, bbi = gr & 3;   // rows gr, gr+8 -> s0, s0+2
                if (mode == 1) {
                    size_t off0 = (((size_t)bbi * HH + hh) * SEQ + s0) * DH + dh;
                    size_t off1 = off0 + 2 * DH;
                    *(uint32_t*)(Oh + off0) = packbf(v0x, v0y);
                    *(uint32_t*)(Oh + off1) = packbf(v1x, v1y);
                    *(uint32_t*)(Ol + off0) = packbf(lof(v0x), lof(v0y));
                    *(uint32_t*)(Ol + off1) = packbf(lof(v1x), lof(v1y));
                } else {
                    size_t off = (((size_t)bbi * HH + hh) * DH + dh) * SEQ + s0;
                    Oh[off]           = __float2bfloat16_rn(v0x);
                    Oh[off + SEQ]     = __float2bfloat16_rn(v0y);
                    Oh[off + 2]       = __float2bfloat16_rn(v1x);
                    Oh[off + SEQ + 2] = __float2bfloat16_rn(v1y);
                    Ol[off]           = __float2bfloat16_rn(lof(v0x));
                    Ol[off + SEQ]     = __float2bfloat16_rn(lof(v0y));
                    Ol[off + 2]       = __float2bfloat16_rn(lof(v1x));
                    Ol[off + SEQ + 2] = __float2bfloat16_rn(lof(v1y));
                }
            }
        }
    }
}

// ---------------------------------------------------------------------------
// Flash attention on mma.sync bf16, 3-pass split for QK^T and PV.
// Block = 128 threads (4 warps), 64 Q rows; warp owns 16 rows.
// K tile smem [key][dh], V tile smem [dh][key] (pre-transposed in gmem).
// ---------------------------------------------------------------------------
#define FRB 144
#define QT_B (64 * FRB)        // 9216
#define STG_B (4 * QT_B)       // 36864
#define FLASH_SMEM (2 * QT_B + 2 * STG_B)   // 92160

// B-frag x4 load (pattern identical to verified GEMM B path)
static __device__ __forceinline__ void ldsm_b(uint32_t tile, int nbase, int ksb,
                                              int lane, uint32_t* r4)
{
    int g = lane >> 3, ntl = g >> 1, half = g & 1;
    uint32_t addr = tile + (uint32_t)(nbase + ntl * 8 + (lane & 7)) * FRB
                  + ksb + half * 16;
    ldsm_x4(addr, r4[0], r4[1], r4[2], r4[3]);
}

__global__ __launch_bounds__(128)
void flash_mma_kernel(const __nv_bfloat16* __restrict__ qh_g,
                      const __nv_bfloat16* __restrict__ ql_g,
                      const __nv_bfloat16* __restrict__ kh_g,
                      const __nv_bfloat16* __restrict__ kl_g,
                      const __nv_bfloat16* __restrict__ vh_g,
                      const __nv_bfloat16* __restrict__ vl_g,
                      __nv_bfloat16* __restrict__ ahi,
                      __nv_bfloat16* __restrict__ alo)
{
    extern __shared__ char smf[];
    const int tid = threadIdx.x, lane = tid & 31, wid = tid >> 5;
    const int qb = blockIdx.x, h = blockIdx.y, b = blockIdx.z;
    const int q0 = qb * 64;
    const uint32_t sb = s2u(smf);
    const uint32_t qhS = sb, qlS = sb + QT_B;

    const size_t bh = (size_t)b * HH + h;
    const char* qhp = (const char*)(qh_g + (bh * SEQ + q0) * DH);
    const char* qlp = (const char*)(ql_g + (bh * SEQ + q0) * DH);
    const __nv_bfloat16* khp = kh_g + bh * SEQ * DH;
    const __nv_bfloat16* klp = kl_g + bh * SEQ * DH;
    const __nv_bfloat16* vhp = vh_g + bh * (size_t)DH * SEQ;
    const __nv_bfloat16* vlp = vl_g + bh * (size_t)DH * SEQ;

    // Q tiles (group 0)
    #pragma unroll
    for (int u = 0; u < 4; u++) {
        int lin = tid + u * 128; int row = lin >> 3, seg = lin & 7;
        CP_ASYNC16(qhS + row * FRB + seg * 16, qhp + row * 128 + seg * 16);
        CP_ASYNC16(qlS + row * FRB + seg * 16, qlp + row * 128 + seg * 16);
    }
    CP_COMMIT();

    // stage 0 prefetch
    {
        uint32_t base = sb + 2 * QT_B;
        #pragma unroll
        for (int u = 0; u < 4; u++) {
            int lin = tid + u * 128; int row = lin >> 3, seg = lin & 7;
            size_t koff = (size_t)row * DH + seg * 8;
            CP_ASYNC16(base + 0 * QT_B + row * FRB + seg * 16, khp + koff);
            CP_ASYNC16(base + 1 * QT_B + row * FRB + seg * 16, klp + koff);
            size_t voff = (size_t)row * SEQ + seg * 8;
            CP_ASYNC16(base + 2 * QT_B + row * FRB + seg * 16, vhp + voff);
            CP_ASYNC16(base + 3 * QT_B + row * FRB + seg * 16, vlp + voff);
        }
        CP_COMMIT();
    }
    CP_WAIT(0);
    __syncthreads();

    // Q fragments (verified A-operand ldmatrix pattern)
    const int qrow0 = wid * 16;
    uint32_t qah[4][4], qal[4][4];
    #pragma unroll
    for (int ks = 0; ks < 4; ks++) {
        uint32_t ah = qhS + (uint32_t)(qrow0 + (lane & 15)) * FRB + ks * 32 + (lane >> 4) * 16;
        uint32_t al = qlS + (uint32_t)(qrow0 + (lane & 15)) * FRB + ks * 32 + (lane >> 4) * 16;
        ldsm_x4(ah, qah[ks][0], qah[ks][1], qah[ks][2], qah[ks][3]);
        ldsm_x4(al, qal[ks][0], qal[ks][1], qal[ks][2], qal[ks][3]);
    }

    float Oa[8][4];
    #pragma unroll
    for (int nt = 0; nt < 8; nt++)
        #pragma unroll
        for (int f = 0; f < 4; f++) Oa[nt][f] = 0.0f;
    float mrow[2] = {0.0f, 0.0f};   // sink: score 0
    float lrow[2] = {1.0f, 1.0f};   // sink: exp(0-0)

    for (int jt = 0; jt <= qb; jt++) {
        const int s = jt & 1;
        if (jt < qb) {   // prefetch next stage
            uint32_t base = sb + 2 * QT_B + (s ^ 1) * STG_B;
            const int j1 = (jt + 1) * 64;
            #pragma unroll
            for (int u = 0; u < 4; u++) {
                int lin = tid + u * 128; int row = lin >> 3, seg = lin & 7;
                size_t koff = (size_t)(j1 + row) * DH + seg * 8;
                CP_ASYNC16(base + 0 * QT_B + row * FRB + seg * 16, khp + koff);
                CP_ASYNC16(base + 1 * QT_B + row * FRB + seg * 16, klp + koff);
                size_t voff = (size_t)row * SEQ + j1 + seg * 8;
                CP_ASYNC16(base + 2 * QT_B + row * FRB + seg * 16, vhp + voff);
                CP_ASYNC16(base + 3 * QT_B + row * FRB + seg * 16, vlp + voff);
            }
            CP_COMMIT();
            CP_WAIT(1);
        } else {
            CP_WAIT(0);
        }
        __syncthreads();

        const uint32_t st = sb + 2 * QT_B + s * STG_B;
        const uint32_t khT = st, klT = st + QT_B, vhT = st + 2 * QT_B, vlT = st + 3 * QT_B;

        // ---- S = Q K^T (3-pass) ----
        float S[8][4];
        #pragma unroll
        for (int nt = 0; nt < 8; nt++)
            #pragma unroll
            for (int f = 0; f < 4; f++) S[nt][f] = 0.0f;

        #pragma unroll
        for (int ks = 0; ks < 4; ks++) {
            uint32_t kh4[16], kl4[16];
            #pragma unroll
            for (int p = 0; p < 4; p++) {
                ldsm_b(khT, p * 16, ks * 32, lane, kh4 + p * 4);
                ldsm_b(klT, p * 16, ks * 32, lane, kl4 + p * 4);
            }
            #pragma unroll
            for (int nt = 0; nt < 8; nt++) {
                mma16816(S[nt], qah[ks][0], qah[ks][1], qah[ks][2], qah[ks][3],
                         kh4[2 * nt], kh4[2 * nt + 1]);
                mma16816(S[nt], qah[ks][0], qah[ks][1], qah[ks][2], qah[ks][3],
                         kl4[2 * nt], kl4[2 * nt + 1]);
                mma16816(S[nt], qal[ks][0], qal[ks][1], qal[ks][2], qal[ks][3],
                         kh4[2 * nt], kh4[2 * nt + 1]);
            }
        }

        // causal mask on diagonal tile
        if (jt == qb) {
            const int j0 = jt * 64;
            #pragma unroll
            for (int nt = 0; nt < 8; nt++) {
                #pragma unroll
                for (int e = 0; e < 4; e++) {
                    int grow = q0 + qrow0 + (lane >> 2) + ((e >= 2) ? 8 : 0);
                    int gcol = j0 + nt * 8 + (lane & 3) * 2 + (e & 1);
                    if (gcol > grow) S[nt][e] = -1e30f;
                }
            }
        }

        // ---- online softmax (rows private to quads) ----
        #pragma unroll
        for (int i = 0; i < 2; i++) {
            float rm = -1e30f;
            #pragma unroll
            for (int nt = 0; nt < 8; nt++)
                rm = fmaxf(rm, fmaxf(S[nt][2 * i], S[nt][2 * i + 1]));
            rm = fmaxf(rm, __shfl_xor_sync(0xffffffffu, rm, 1));
            rm = fmaxf(rm, __shfl_xor_sync(0xffffffffu, rm, 2));
            float mn = fmaxf(mrow[i], rm);
            float alpha = __expf(mrow[i] - mn);
            float rs = 0.0f;
            #pragma unroll
            for (int nt = 0; nt < 8; nt++) {
                float p0 = __expf(S[nt][2 * i]     - mn);
                float p1 = __expf(S[nt][2 * i + 1] - mn);
                S[nt][2 * i] = p0; S[nt][2 * i + 1] = p1;
                rs += p0 + p1;
            }
            rs += __shfl_xor_sync(0xffffffffu, rs, 1);
            rs += __shfl_xor_sync(0xffffffffu, rs, 2);
            lrow[i] = lrow[i] * alpha + rs;
            mrow[i] = mn;
            #pragma unroll
            for (int nt = 0; nt < 8; nt++) {
                Oa[nt][2 * i]     *= alpha;
                Oa[nt][2 * i + 1] *= alpha;
            }
        }

        // ---- O += P V (3-pass; P hi/lo from registers) ----
        #pragma unroll
        for (int ks = 0; ks < 4; ks++) {
            // A-frags from S ntiles 2ks, 2ks+1 (C-frag == A-frag layout)
            uint32_t ah0 = packbf(S[2 * ks][0],     S[2 * ks][1]);
            uint32_t ah1 = packbf(S[2 * ks][2],     S[2 * ks][3]);
            uint32_t ah2 = packbf(S[2 * ks + 1][0], S[2 * ks + 1][1]);
            uint32_t ah3 = packbf(S[2 * ks + 1][2], S[2 * ks + 1][3]);
            uint32_t al0 = packbf(lof(S[2 * ks][0]),     lof(S[2 * ks][1]));
            uint32_t al1 = packbf(lof(S[2 * ks][2]),     lof(S[2 * ks][3]));
            uint32_t al2 = packbf(lof(S[2 * ks + 1][0]), lof(S[2 * ks + 1][1]));
            uint32_t al3 = packbf(lof(S[2 * ks + 1][2]), lof(S[2 * ks + 1][3]));
            uint32_t vh4[16], vl4[16];
            #pragma unroll
            for (int p = 0; p < 4; p++) {
                ldsm_b(vhT, p * 16, ks * 32, lane, vh4 + p * 4);
                ldsm_b(vlT, p * 16, ks * 32, lane, vl4 + p * 4);
            }
            #pragma unroll
            for (int nt = 0; nt < 8; nt++) {
                mma16816(Oa[nt], ah0, ah1, ah2, ah3, vh4[2 * nt], vh4[2 * nt + 1]);
                mma16816(Oa[nt], ah0, ah1, ah2, ah3, vl4[2 * nt], vl4[2 * nt + 1]);
                mma16816(Oa[nt], al0, al1, al2, al3, vh4[2 * nt], vh4[2 * nt + 1]);
            }
        }
        __syncthreads();   // stage reuse safety for next prefetch
    }

    // ---- epilogue: normalize, split, store att in [s,b,D] hi/lo ----
    const float inv0 = 1.0f / lrow[0];
    const float inv1 = 1.0f / lrow[1];
    const int r = lane >> 2, c2 = (lane & 3) * 2;
    const int srow0 = q0 + qrow0 + r;
    #pragma unroll
    for (int nt = 0; nt < 8; nt++) {
        int col = h * 64 + nt * 8 + c2;
        float o00 = Oa[nt][0] * inv0, o01 = Oa[nt][1] * inv0;
        float o10 = Oa[nt][2] * inv1, o11 = Oa[nt][3] * inv1;
        size_t off0 = ((size_t)srow0 * BB + b) * DD + col;
        size_t off1 = ((size_t)(srow0 + 8) * BB + b) * DD + col;
        *(uint32_t*)(ahi + off0) = packbf(o00, o01);
        *(uint32_t*)(ahi + off1) = packbf(o10, o11);
        *(uint32_t*)(alo + off0) = packbf(lof(o00), lof(o01));
        *(uint32_t*)(alo + off1) = packbf(lof(o10), lof(o11));
    }
}

// ---------------------------------------------------------------------------
extern "C" void kernel_launch(void* const* d_in, const int* in_sizes, int n_in,
                              void* d_out, int out_size)
{
    const float* x    = (const float*)d_in[0];
    const float* beta = (const float*)d_in[2];
    const float* Wq   = (const float*)d_in[3];
    const float* bq   = (const float*)d_in[4];
    const float* Wk   = (const float*)d_in[5];
    const float* bk   = (const float*)d_in[6];
    const float* Wv   = (const float*)d_in[7];
    const float* bv   = (const float*)d_in[8];
    const float* Wo   = (const float*)d_in[9];
    const float* bo   = (const float*)d_in[10];
    float* out = (float*)d_out;

    __nv_bfloat16 *xhi, *xlo, *wqh, *wql, *wkh, *wkl, *wvh, *wvl, *woh, *wol;
    __nv_bfloat16 *qh, *ql, *kh, *kl, *vh, *vl, *ahi, *alo;
    cudaGetSymbolAddress((void**)&xhi, g_xhi);
    cudaGetSymbolAddress((void**)&xlo, g_xlo);
    cudaGetSymbolAddress((void**)&wqh, g_wqh);
    cudaGetSymbolAddress((void**)&wql, g_wql);
    cudaGetSymbolAddress((void**)&wkh, g_wkh);
    cudaGetSymbolAddress((void**)&wkl, g_wkl);
    cudaGetSymbolAddress((void**)&wvh, g_wvh);
    cudaGetSymbolAddress((void**)&wvl, g_wvl);
    cudaGetSymbolAddress((void**)&woh, g_woh);
    cudaGetSymbolAddress((void**)&wol, g_wol);
    cudaGetSymbolAddress((void**)&qh, g_qh);
    cudaGetSymbolAddress((void**)&ql, g_ql);
    cudaGetSymbolAddress((void**)&kh, g_kh);
    cudaGetSymbolAddress((void**)&kl, g_kl);
    cudaGetSymbolAddress((void**)&vh, g_vh);
    cudaGetSymbolAddress((void**)&vl, g_vl);
    cudaGetSymbolAddress((void**)&ahi, g_ahi);
    cudaGetSymbolAddress((void**)&alo, g_alo);

    cudaFuncSetAttribute(gemm_mma_kernel,
                         cudaFuncAttributeMaxDynamicSharedMemorySize, GEMM_SMEM);
    cudaFuncSetAttribute(flash_mma_kernel,
                         cudaFuncAttributeMaxDynamicSharedMemorySize, FLASH_SMEM);

    const int nx4 = MM * DD / 4;
    const int nw4 = DD * DD / 4;

    split_kernel<<<(nx4 + 255) / 256, 256>>>(x, xhi, xlo, nx4);
    split_kernel<<<(nw4 + 255) / 256, 256>>>(Wq, wqh, wql, nw4);
    split_kernel<<<(nw4 + 255) / 256, 256>>>(Wk, wkh, wkl, nw4);
    split_kernel<<<(nw4 + 255) / 256, 256>>>(Wv, wvh, wvl, nw4);
    split_kernel<<<(nw4 + 255) / 256, 256>>>(Wo, woh, wol, nw4);

    dim3 ggrid(DD / 128, MM / 128);   // (8, 64)
    // Q: bf16 [b,h,s,dh], scaled by 1/(exp(beta)*8)
    gemm_mma_kernel<<<ggrid, 256, GEMM_SMEM>>>(xhi, xlo, wqh, wql, bq,
                                               1, beta, nullptr, qh, ql);
    // K: bf16 [b,h,s,dh]
    gemm_mma_kernel<<<ggrid, 256, GEMM_SMEM>>>(xhi, xlo, wkh, wkl, bk,
                                               1, nullptr, nullptr, kh, kl);
    // V: bf16 transposed [b,h,dh,s]
    gemm_mma_kernel<<<ggrid, 256, GEMM_SMEM>>>(xhi, xlo, wvh, wvl, bv,
                                               2, nullptr, nullptr, vh, vl);

    dim3 fgrid(SEQ / 64, HH, BB);   // (32, 16, 4)
    flash_mma_kernel<<<fgrid, 128, FLASH_SMEM>>>(qh, ql, kh, kl, vh, vl, ahi, alo);

    // O = att @ Wo^T + bo  -> fp32 out
    gemm_mma_kernel<<<ggrid, 256, GEMM_SMEM>>>(ahi, alo, woh, wol, bo,
                                               0, nullptr, out, nullptr, nullptr);
}

// round 6
// speedup vs baseline: 2.5558x; 1.1242x over previous
#include <cuda_runtime.h>
#include <cuda_bf16.h>
#include <stdint.h>
#include <math.h>

// Problem constants
#define SEQ 2048
#define BB  4
#define DD  1024
#define HH  16
#define DH  64
#define MM  (SEQ*BB)   // 8192 rows for GEMMs

// ---------------- scratch (device globals; allocation-free) ----------------
__device__ __nv_bfloat16 g_xhi[MM*DD], g_xlo[MM*DD];
__device__ __nv_bfloat16 g_wqh[DD*DD], g_wql[DD*DD];
__device__ __nv_bfloat16 g_wkh[DD*DD], g_wkl[DD*DD];
__device__ __nv_bfloat16 g_wvh[DD*DD], g_wvl[DD*DD];
__device__ __nv_bfloat16 g_woh[DD*DD], g_wol[DD*DD];
// q,k in [b,h,s,dh]; v transposed [b,h,dh,s]; att in [s,b,D] (hi/lo)
__device__ __nv_bfloat16 g_qh[MM*DD], g_ql[MM*DD];
__device__ __nv_bfloat16 g_kh[MM*DD], g_kl[MM*DD];
__device__ __nv_bfloat16 g_vh[MM*DD], g_vl[MM*DD];
__device__ __nv_bfloat16 g_ahi[MM*DD], g_alo[MM*DD];

// ---------------- PTX helpers (baseline ISA only) ----------------
static __device__ __forceinline__ uint32_t s2u(const void* p) {
    return (uint32_t)__cvta_generic_to_shared(p);
}

#define CP_ASYNC16(saddr, gptr) \
    asm volatile("cp.async.cg.shared.global [%0], [%1], 16;" :: "r"(saddr), "l"(gptr))
#define CP_COMMIT() asm volatile("cp.async.commit_group;" ::: "memory")
#define CP_WAIT(n)  asm volatile("cp.async.wait_group %0;" :: "n"(n) : "memory")

static __device__ __forceinline__ void ldsm_x4(uint32_t addr,
    uint32_t &r0, uint32_t &r1, uint32_t &r2, uint32_t &r3)
{
    asm volatile("ldmatrix.sync.aligned.m8n8.x4.shared.b16 {%0,%1,%2,%3}, [%4];"
        : "=r"(r0), "=r"(r1), "=r"(r2), "=r"(r3) : "r"(addr));
}

static __device__ __forceinline__ void mma16816(float* d,
    uint32_t a0, uint32_t a1, uint32_t a2, uint32_t a3, uint32_t b0, uint32_t b1)
{
    asm volatile("mma.sync.aligned.m16n8k16.row.col.f32.bf16.bf16.f32 "
        "{%0,%1,%2,%3}, {%4,%5,%6,%7}, {%8,%9}, {%0,%1,%2,%3};"
        : "+f"(d[0]), "+f"(d[1]), "+f"(d[2]), "+f"(d[3])
        : "r"(a0), "r"(a1), "r"(a2), "r"(a3), "r"(b0), "r"(b1));
}

static __device__ __forceinline__ uint32_t packbf(float x, float y) {
    __nv_bfloat162 t = __floats2bfloat162_rn(x, y);
    return *(uint32_t*)&t;
}
static __device__ __forceinline__ float lof(float x) {
    return x - __bfloat162float(__float2bfloat16_rn(x));
}

// ---------------- splits: fp32 -> bf16 hi + bf16 lo ----------------
__global__ void split_kernel(const float* __restrict__ src,
                             __nv_bfloat16* __restrict__ hi,
                             __nv_bfloat16* __restrict__ lo, int n4)
{
    int i = blockIdx.x * blockDim.x + threadIdx.x;
    if (i >= n4) return;
    float4 v = ((const float4*)src)[i];
    __nv_bfloat162* hp = (__nv_bfloat162*)hi;
    __nv_bfloat162* lp = (__nv_bfloat162*)lo;
    hp[i*2+0] = __floats2bfloat162_rn(v.x, v.y);
    hp[i*2+1] = __floats2bfloat162_rn(v.z, v.w);
    lp[i*2+0] = __floats2bfloat162_rn(lof(v.x), lof(v.y));
    lp[i*2+1] = __floats2bfloat162_rn(lof(v.z), lof(v.w));
}

// 4 weight matrices in one launch (blockIdx.y selects the tensor)
__global__ void split4_kernel(const float* __restrict__ s0, const float* __restrict__ s1,
                              const float* __restrict__ s2, const float* __restrict__ s3,
                              __nv_bfloat16* __restrict__ h0, __nv_bfloat16* __restrict__ l0,
                              __nv_bfloat16* __restrict__ h1, __nv_bfloat16* __restrict__ l1,
                              __nv_bfloat16* __restrict__ h2, __nv_bfloat16* __restrict__ l2,
                              __nv_bfloat16* __restrict__ h3, __nv_bfloat16* __restrict__ l3,
                              int n4)
{
    int i = blockIdx.x * blockDim.x + threadIdx.x;
    if (i >= n4) return;
    const float* src; __nv_bfloat16 *hi, *lo;
    switch (blockIdx.y) {
        case 0:  src = s0; hi = h0; lo = l0; break;
        case 1:  src = s1; hi = h1; lo = l1; break;
        case 2:  src = s2; hi = h2; lo = l2; break;
        default: src = s3; hi = h3; lo = l3; break;
    }
    float4 v = ((const float4*)src)[i];
    __nv_bfloat162* hp = (__nv_bfloat162*)hi;
    __nv_bfloat162* lp = (__nv_bfloat162*)lo;
    hp[i*2+0] = __floats2bfloat162_rn(v.x, v.y);
    hp[i*2+1] = __floats2bfloat162_rn(v.z, v.w);
    lp[i*2+0] = __floats2bfloat162_rn(lof(v.x), lof(v.y));
    lp[i*2+1] = __floats2bfloat162_rn(lof(v.z), lof(v.w));
}

// ---------------------------------------------------------------------------
// HMMA GEMM: C = (Ahi+Alo)[M,K] @ (Bhi+Blo)[N,K]^T + bias  (3-pass)
// mode 0: fp32 out [s,b,D]
// mode 1: bf16 hi/lo out [b,h,s,dh]   (+ optional 1/(exp(beta_h)*8) scaling)
// mode 2: bf16 hi/lo out transposed [b,h,dh,s]
// Frags loaded ONCE per k16-step; 3 mmas issued per (mi,ni).
// ---------------------------------------------------------------------------
#define GBK 32
#define NCG (DD / GBK)
#define RSMEM 80
#define TILE_B (128 * RSMEM)
#define BUF_B  (4 * TILE_B)
#define GEMM_SMEM (2 * BUF_B)

__global__ __launch_bounds__(256, 2)
void gemm_mma_kernel(const __nv_bfloat16* __restrict__ Ahi,
                     const __nv_bfloat16* __restrict__ Alo,
                     const __nv_bfloat16* __restrict__ Bhi,
                     const __nv_bfloat16* __restrict__ Blo,
                     const float* __restrict__ bias,
                     int mode, const float* __restrict__ beta,
                     float* __restrict__ C,
                     __nv_bfloat16* __restrict__ Oh,
                     __nv_bfloat16* __restrict__ Ol)
{
    extern __shared__ char smc[];
    const int tid  = threadIdx.x;
    const int wid  = tid >> 5;
    const int lane = tid & 31;
    const int bn = blockIdx.x * 128;
    const int bm = blockIdx.y * 128;
    const uint32_t sb = s2u(smc);

    const int warpM = wid >> 2;
    const int warpN = wid & 3;
    const int m0 = warpM * 64;
    const int n0 = warpN * 32;

    const int lrow0 = tid >> 2;
    const int lseg  = tid & 3;

    const __nv_bfloat16* gsrc[4] = {Ahi, Alo, Bhi, Blo};
    const int rowbase[4] = {bm, bm, bn, bn};

    #pragma unroll
    for (int t = 0; t < 4; t++) {
        const __nv_bfloat16* g = gsrc[t] + (size_t)(rowbase[t]) * DD + lseg * 8;
        uint32_t sb_t = sb + t * TILE_B + lseg * 16;
        CP_ASYNC16(sb_t + lrow0 * RSMEM,        g + (size_t)lrow0 * DD);
        CP_ASYNC16(sb_t + (lrow0 + 64) * RSMEM, g + (size_t)(lrow0 + 64) * DD);
    }
    CP_COMMIT();

    float acc[4][4][4];
    #pragma unroll
    for (int mi = 0; mi < 4; mi++)
        #pragma unroll
        for (int ni = 0; ni < 4; ni++)
            #pragma unroll
            for (int f = 0; f < 4; f++) acc[mi][ni][f] = 0.0f;

    for (int c = 0; c < NCG; c++) {
        if (c + 1 < NCG) {
            const int k0 = (c + 1) * GBK;
            const uint32_t bufo = ((c + 1) & 1) * BUF_B;
            #pragma unroll
            for (int t = 0; t < 4; t++) {
                const __nv_bfloat16* g = gsrc[t] + (size_t)(rowbase[t]) * DD + k0 + lseg * 8;
                uint32_t sb_t = sb + bufo + t * TILE_B + lseg * 16;
                CP_ASYNC16(sb_t + lrow0 * RSMEM,        g + (size_t)lrow0 * DD);
                CP_ASYNC16(sb_t + (lrow0 + 64) * RSMEM, g + (size_t)(lrow0 + 64) * DD);
            }
            CP_COMMIT();
            CP_WAIT(1);
        } else {
            CP_WAIT(0);
        }
        __syncthreads();

        const uint32_t bufo = (c & 1) * BUF_B;
        const uint32_t AhT = sb + bufo + 0 * TILE_B;
        const uint32_t AlT = sb + bufo + 1 * TILE_B;
        const uint32_t BhT = sb + bufo + 2 * TILE_B;
        const uint32_t BlT = sb + bufo + 3 * TILE_B;

        #pragma unroll
        for (int s = 0; s < 2; s++) {
            const uint32_t kb = s * 32;
            uint32_t bh[4][2], bl[4][2];
            {
                int g = lane >> 3;
                int ntl = g >> 1, half = g & 1;
                uint32_t boff = (uint32_t)(n0 + ntl * 8 + (lane & 7)) * RSMEM
                              + kb + half * 16;
                ldsm_x4(BhT + boff,             bh[0][0], bh[0][1], bh[1][0], bh[1][1]);
                ldsm_x4(BhT + boff + 16 * RSMEM, bh[2][0], bh[2][1], bh[3][0], bh[3][1]);
                ldsm_x4(BlT + boff,             bl[0][0], bl[0][1], bl[1][0], bl[1][1]);
                ldsm_x4(BlT + boff + 16 * RSMEM, bl[2][0], bl[2][1], bl[3][0], bl[3][1]);
            }
            #pragma unroll
            for (int mi = 0; mi < 4; mi++) {
                uint32_t ah0, ah1, ah2, ah3, al0, al1, al2, al3;
                uint32_t aoff = (uint32_t)(m0 + mi * 16 + (lane & 15)) * RSMEM
                              + kb + (lane >> 4) * 16;
                ldsm_x4(AhT + aoff, ah0, ah1, ah2, ah3);
                ldsm_x4(AlT + aoff, al0, al1, al2, al3);
                #pragma unroll
                for (int ni = 0; ni < 4; ni++) {
                    mma16816(acc[mi][ni], ah0, ah1, ah2, ah3, bh[ni][0], bh[ni][1]);
                    mma16816(acc[mi][ni], ah0, ah1, ah2, ah3, bl[ni][0], bl[ni][1]);
                    mma16816(acc[mi][ni], al0, al1, al2, al3, bh[ni][0], bh[ni][1]);
                }
            }
        }
        __syncthreads();
    }

    const int erow = lane >> 2;
    const int ecol = (lane & 3) * 2;
    #pragma unroll
    for (int mi = 0; mi < 4; mi++) {
        #pragma unroll
        for (int ni = 0; ni < 4; ni++) {
            int gr = bm + m0 + mi * 16 + erow;
            int gc = bn + n0 + ni * 8 + ecol;
            float v0x = acc[mi][ni][0] + bias[gc];
            float v0y = acc[mi][ni][1] + bias[gc + 1];
            float v1x = acc[mi][ni][2] + bias[gc];
            float v1y = acc[mi][ni][3] + bias[gc + 1];
            if (mode == 0) {
                float2 a = {v0x, v0y}, bb2 = {v1x, v1y};
                *(float2*)(C + (size_t)gr * DD + gc)       = a;
                *(float2*)(C + (size_t)(gr + 8) * DD + gc) = bb2;
            } else {
                int hh = gc >> 6, dh = gc & 63;
                if (beta) {
                    float sc = 1.0f / (__expf(beta[hh]) * 8.0f);
                    v0x *= sc; v0y *= sc; v1x *= sc; v1y *= sc;
                }
                int s0 = gr >> 2, bbi = gr & 3;   // rows gr, gr+8 -> s0, s0+2
                if (mode == 1) {
                    size_t off0 = (((size_t)bbi * HH + hh) * SEQ + s0) * DH + dh;
                    size_t off1 = off0 + 2 * DH;
                    *(uint32_t*)(Oh + off0) = packbf(v0x, v0y);
                    *(uint32_t*)(Oh + off1) = packbf(v1x, v1y);
                    *(uint32_t*)(Ol + off0) = packbf(lof(v0x), lof(v0y));
                    *(uint32_t*)(Ol + off1) = packbf(lof(v1x), lof(v1y));
                } else {
                    size_t off = (((size_t)bbi * HH + hh) * DH + dh) * SEQ + s0;
                    Oh[off]           = __float2bfloat16_rn(v0x);
                    Oh[off + SEQ]     = __float2bfloat16_rn(v0y);
                    Oh[off + 2]       = __float2bfloat16_rn(v1x);
                    Oh[off + SEQ + 2] = __float2bfloat16_rn(v1y);
                    Ol[off]           = __float2bfloat16_rn(lof(v0x));
                    Ol[off + SEQ]     = __float2bfloat16_rn(lof(v0y));
                    Ol[off + 2]       = __float2bfloat16_rn(lof(v1x));
                    Ol[off + SEQ + 2] = __float2bfloat16_rn(lof(v1y));
                }
            }
        }
    }
}

// ---------------------------------------------------------------------------
// Flash attention on mma.sync bf16, 3-pass split for QK^T and PV.
// Block = 128 threads (4 warps), 64 Q rows; warp owns 16 rows.
// LPT: heaviest q-tiles (largest qb) launch first via reversed mapping.
// ---------------------------------------------------------------------------
#define FRB 144
#define QT_B (64 * FRB)        // 9216
#define STG_B (4 * QT_B)       // 36864
#define FLASH_SMEM (2 * QT_B + 2 * STG_B)   // 92160

static __device__ __forceinline__ void ldsm_b(uint32_t tile, int nbase, int ksb,
                                              int lane, uint32_t* r4)
{
    int g = lane >> 3, ntl = g >> 1, half = g & 1;
    uint32_t addr = tile + (uint32_t)(nbase + ntl * 8 + (lane & 7)) * FRB
                  + ksb + half * 16;
    ldsm_x4(addr, r4[0], r4[1], r4[2], r4[3]);
}

__global__ __launch_bounds__(128)
void flash_mma_kernel(const __nv_bfloat16* __restrict__ qh_g,
                      const __nv_bfloat16* __restrict__ ql_g,
                      const __nv_bfloat16* __restrict__ kh_g,
                      const __nv_bfloat16* __restrict__ kl_g,
                      const __nv_bfloat16* __restrict__ vh_g,
                      const __nv_bfloat16* __restrict__ vl_g,
                      __nv_bfloat16* __restrict__ ahi,
                      __nv_bfloat16* __restrict__ alo)
{
    extern __shared__ char smf[];
    const int tid = threadIdx.x, lane = tid & 31, wid = tid >> 5;
    const int qb = (int)gridDim.x - 1 - (int)blockIdx.x;   // LPT order
    const int h = blockIdx.y, b = blockIdx.z;
    const int q0 = qb * 64;
    const uint32_t sb = s2u(smf);
    const uint32_t qhS = sb, qlS = sb + QT_B;

    const size_t bh = (size_t)b * HH + h;
    const char* qhp = (const char*)(qh_g + (bh * SEQ + q0) * DH);
    const char* qlp = (const char*)(ql_g + (bh * SEQ + q0) * DH);
    const __nv_bfloat16* khp = kh_g + bh * SEQ * DH;
    const __nv_bfloat16* klp = kl_g + bh * SEQ * DH;
    const __nv_bfloat16* vhp = vh_g + bh * (size_t)DH * SEQ;
    const __nv_bfloat16* vlp = vl_g + bh * (size_t)DH * SEQ;

    // Q tiles
    #pragma unroll
    for (int u = 0; u < 4; u++) {
        int lin = tid + u * 128; int row = lin >> 3, seg = lin & 7;
        CP_ASYNC16(qhS + row * FRB + seg * 16, qhp + row * 128 + seg * 16);
        CP_ASYNC16(qlS + row * FRB + seg * 16, qlp + row * 128 + seg * 16);
    }
    CP_COMMIT();

    // stage 0 prefetch
    {
        uint32_t base = sb + 2 * QT_B;
        #pragma unroll
        for (int u = 0; u < 4; u++) {
            int lin = tid + u * 128; int row = lin >> 3, seg = lin & 7;
            size_t koff = (size_t)row * DH + seg * 8;
            CP_ASYNC16(base + 0 * QT_B + row * FRB + seg * 16, khp + koff);
            CP_ASYNC16(base + 1 * QT_B + row * FRB + seg * 16, klp + koff);
            size_t voff = (size_t)row * SEQ + seg * 8;
            CP_ASYNC16(base + 2 * QT_B + row * FRB + seg * 16, vhp + voff);
            CP_ASYNC16(base + 3 * QT_B + row * FRB + seg * 16, vlp + voff);
        }
        CP_COMMIT();
    }
    CP_WAIT(0);
    __syncthreads();

    const int qrow0 = wid * 16;
    uint32_t qah[4][4], qal[4][4];
    #pragma unroll
    for (int ks = 0; ks < 4; ks++) {
        uint32_t ah = qhS + (uint32_t)(qrow0 + (lane & 15)) * FRB + ks * 32 + (lane >> 4) * 16;
        uint32_t al = qlS + (uint32_t)(qrow0 + (lane & 15)) * FRB + ks * 32 + (lane >> 4) * 16;
        ldsm_x4(ah, qah[ks][0], qah[ks][1], qah[ks][2], qah[ks][3]);
        ldsm_x4(al, qal[ks][0], qal[ks][1], qal[ks][2], qal[ks][3]);
    }

    float Oa[8][4];
    #pragma unroll
    for (int nt = 0; nt < 8; nt++)
        #pragma unroll
        for (int f = 0; f < 4; f++) Oa[nt][f] = 0.0f;
    float mrow[2] = {0.0f, 0.0f};   // sink: score 0
    float lrow[2] = {1.0f, 1.0f};   // sink: exp(0-0)

    for (int jt = 0; jt <= qb; jt++) {
        const int s = jt & 1;
        if (jt < qb) {
            uint32_t base = sb + 2 * QT_B + (s ^ 1) * STG_B;
            const int j1 = (jt + 1) * 64;
            #pragma unroll
            for (int u = 0; u < 4; u++) {
                int lin = tid + u * 128; int row = lin >> 3, seg = lin & 7;
                size_t koff = (size_t)(j1 + row) * DH + seg * 8;
                CP_ASYNC16(base + 0 * QT_B + row * FRB + seg * 16, khp + koff);
                CP_ASYNC16(base + 1 * QT_B + row * FRB + seg * 16, klp + koff);
                size_t voff = (size_t)row * SEQ + j1 + seg * 8;
                CP_ASYNC16(base + 2 * QT_B + row * FRB + seg * 16, vhp + voff);
                CP_ASYNC16(base + 3 * QT_B + row * FRB + seg * 16, vlp + voff);
            }
            CP_COMMIT();
            CP_WAIT(1);
        } else {
            CP_WAIT(0);
        }
        __syncthreads();

        const uint32_t st = sb + 2 * QT_B + s * STG_B;
        const uint32_t khT = st, klT = st + QT_B, vhT = st + 2 * QT_B, vlT = st + 3 * QT_B;

        // ---- S = Q K^T (3-pass) ----
        float S[8][4];
        #pragma unroll
        for (int nt = 0; nt < 8; nt++)
            #pragma unroll
            for (int f = 0; f < 4; f++) S[nt][f] = 0.0f;

        #pragma unroll
        for (int ks = 0; ks < 4; ks++) {
            uint32_t kh4[16], kl4[16];
            #pragma unroll
            for (int p = 0; p < 4; p++) {
                ldsm_b(khT, p * 16, ks * 32, lane, kh4 + p * 4);
                ldsm_b(klT, p * 16, ks * 32, lane, kl4 + p * 4);
            }
            #pragma unroll
            for (int nt = 0; nt < 8; nt++) {
                mma16816(S[nt], qah[ks][0], qah[ks][1], qah[ks][2], qah[ks][3],
                         kh4[2 * nt], kh4[2 * nt + 1]);
                mma16816(S[nt], qah[ks][0], qah[ks][1], qah[ks][2], qah[ks][3],
                         kl4[2 * nt], kl4[2 * nt + 1]);
                mma16816(S[nt], qal[ks][0], qal[ks][1], qal[ks][2], qal[ks][3],
                         kh4[2 * nt], kh4[2 * nt + 1]);
            }
        }

        if (jt == qb) {
            const int j0 = jt * 64;
            #pragma unroll
            for (int nt = 0; nt < 8; nt++) {
                #pragma unroll
                for (int e = 0; e < 4; e++) {
                    int grow = q0 + qrow0 + (lane >> 2) + ((e >= 2) ? 8 : 0);
                    int gcol = j0 + nt * 8 + (lane & 3) * 2 + (e & 1);
                    if (gcol > grow) S[nt][e] = -1e30f;
                }
            }
        }

        // ---- online softmax ----
        #pragma unroll
        for (int i = 0; i < 2; i++) {
            float rm = -1e30f;
            #pragma unroll
            for (int nt = 0; nt < 8; nt++)
                rm = fmaxf(rm, fmaxf(S[nt][2 * i], S[nt][2 * i + 1]));
            rm = fmaxf(rm, __shfl_xor_sync(0xffffffffu, rm, 1));
            rm = fmaxf(rm, __shfl_xor_sync(0xffffffffu, rm, 2));
            float mn = fmaxf(mrow[i], rm);
            float alpha = __expf(mrow[i] - mn);
            float rs = 0.0f;
            #pragma unroll
            for (int nt = 0; nt < 8; nt++) {
                float p0 = __expf(S[nt][2 * i]     - mn);
                float p1 = __expf(S[nt][2 * i + 1] - mn);
                S[nt][2 * i] = p0; S[nt][2 * i + 1] = p1;
                rs += p0 + p1;
            }
            rs += __shfl_xor_sync(0xffffffffu, rs, 1);
            rs += __shfl_xor_sync(0xffffffffu, rs, 2);
            lrow[i] = lrow[i] * alpha + rs;
            mrow[i] = mn;
            #pragma unroll
            for (int nt = 0; nt < 8; nt++) {
                Oa[nt][2 * i]     *= alpha;
                Oa[nt][2 * i + 1] *= alpha;
            }
        }

        // ---- O += P V (3-pass) ----
        #pragma unroll
        for (int ks = 0; ks < 4; ks++) {
            uint32_t ah0 = packbf(S[2 * ks][0],     S[2 * ks][1]);
            uint32_t ah1 = packbf(S[2 * ks][2],     S[2 * ks][3]);
            uint32_t ah2 = packbf(S[2 * ks + 1][0], S[2 * ks + 1][1]);
            uint32_t ah3 = packbf(S[2 * ks + 1][2], S[2 * ks + 1][3]);
            uint32_t al0 = packbf(lof(S[2 * ks][0]),     lof(S[2 * ks][1]));
            uint32_t al1 = packbf(lof(S[2 * ks][2]),     lof(S[2 * ks][3]));
            uint32_t al2 = packbf(lof(S[2 * ks + 1][0]), lof(S[2 * ks + 1][1]));
            uint32_t al3 = packbf(lof(S[2 * ks + 1][2]), lof(S[2 * ks + 1][3]));
            uint32_t vh4[16], vl4[16];
            #pragma unroll
            for (int p = 0; p < 4; p++) {
                ldsm_b(vhT, p * 16, ks * 32, lane, vh4 + p * 4);
                ldsm_b(vlT, p * 16, ks * 32, lane, vl4 + p * 4);
            }
            #pragma unroll
            for (int nt = 0; nt < 8; nt++) {
                mma16816(Oa[nt], ah0, ah1, ah2, ah3, vh4[2 * nt], vh4[2 * nt + 1]);
                mma16816(Oa[nt], ah0, ah1, ah2, ah3, vl4[2 * nt], vl4[2 * nt + 1]);
                mma16816(Oa[nt], al0, al1, al2, al3, vh4[2 * nt], vh4[2 * nt + 1]);
            }
        }
        __syncthreads();
    }

    // ---- epilogue ----
    const float inv0 = 1.0f / lrow[0];
    const float inv1 = 1.0f / lrow[1];
    const int r = lane >> 2, c2 = (lane & 3) * 2;
    const int srow0 = q0 + qrow0 + r;
    #pragma unroll
    for (int nt = 0; nt < 8; nt++) {
        int col = h * 64 + nt * 8 + c2;
        float o00 = Oa[nt][0] * inv0, o01 = Oa[nt][1] * inv0;
        float o10 = Oa[nt][2] * inv1, o11 = Oa[nt][3] * inv1;
        size_t off0 = ((size_t)srow0 * BB + b) * DD + col;
        size_t off1 = ((size_t)(srow0 + 8) * BB + b) * DD + col;
        *(uint32_t*)(ahi + off0) = packbf(o00, o01);
        *(uint32_t*)(ahi + off1) = packbf(o10, o11);
        *(uint32_t*)(alo + off0) = packbf(lof(o00), lof(o01));
        *(uint32_t*)(alo + off1) = packbf(lof(o10), lof(o11));
    }
}

// ---------------------------------------------------------------------------
extern "C" void kernel_launch(void* const* d_in, const int* in_sizes, int n_in,
                              void* d_out, int out_size)
{
    const float* x    = (const float*)d_in[0];
    const float* beta = (const float*)d_in[2];
    const float* Wq   = (const float*)d_in[3];
    const float* bq   = (const float*)d_in[4];
    const float* Wk   = (const float*)d_in[5];
    const float* bk   = (const float*)d_in[6];
    const float* Wv   = (const float*)d_in[7];
    const float* bv   = (const float*)d_in[8];
    const float* Wo   = (const float*)d_in[9];
    const float* bo   = (const float*)d_in[10];
    float* out = (float*)d_out;

    __nv_bfloat16 *xhi, *xlo, *wqh, *wql, *wkh, *wkl, *wvh, *wvl, *woh, *wol;
    __nv_bfloat16 *qh, *ql, *kh, *kl, *vh, *vl, *ahi, *alo;
    cudaGetSymbolAddress((void**)&xhi, g_xhi);
    cudaGetSymbolAddress((void**)&xlo, g_xlo);
    cudaGetSymbolAddress((void**)&wqh, g_wqh);
    cudaGetSymbolAddress((void**)&wql, g_wql);
    cudaGetSymbolAddress((void**)&wkh, g_wkh);
    cudaGetSymbolAddress((void**)&wkl, g_wkl);
    cudaGetSymbolAddress((void**)&wvh, g_wvh);
    cudaGetSymbolAddress((void**)&wvl, g_wvl);
    cudaGetSymbolAddress((void**)&woh, g_woh);
    cudaGetSymbolAddress((void**)&wol, g_wol);
    cudaGetSymbolAddress((void**)&qh, g_qh);
    cudaGetSymbolAddress((void**)&ql, g_ql);
    cudaGetSymbolAddress((void**)&kh, g_kh);
    cudaGetSymbolAddress((void**)&kl, g_kl);
    cudaGetSymbolAddress((void**)&vh, g_vh);
    cudaGetSymbolAddress((void**)&vl, g_vl);
    cudaGetSymbolAddress((void**)&ahi, g_ahi);
    cudaGetSymbolAddress((void**)&alo, g_alo);

    cudaFuncSetAttribute(gemm_mma_kernel,
                         cudaFuncAttributeMaxDynamicSharedMemorySize, GEMM_SMEM);
    cudaFuncSetAttribute(flash_mma_kernel,
                         cudaFuncAttributeMaxDynamicSharedMemorySize, FLASH_SMEM);

    const int nx4 = MM * DD / 4;
    const int nw4 = DD * DD / 4;

    split_kernel<<<(nx4 + 255) / 256, 256>>>(x, xhi, xlo, nx4);
    {
        dim3 sg((nw4 + 255) / 256, 4);
        split4_kernel<<<sg, 256>>>(Wq, Wk, Wv, Wo,
                                   wqh, wql, wkh, wkl, wvh, wvl, woh, wol, nw4);
    }

    dim3 ggrid(DD / 128, MM / 128);   // (8, 64)
    gemm_mma_kernel<<<ggrid, 256, GEMM_SMEM>>>(xhi, xlo, wqh, wql, bq,
                                               1, beta, nullptr, qh, ql);
    gemm_mma_kernel<<<ggrid, 256, GEMM_SMEM>>>(xhi, xlo, wkh, wkl, bk,
                                               1, nullptr, nullptr, kh, kl);
    gemm_mma_kernel<<<ggrid, 256, GEMM_SMEM>>>(xhi, xlo, wvh, wvl, bv,
                                               2, nullptr, nullptr, vh, vl);

    dim3 fgrid(SEQ / 64, HH, BB);   // (32, 16, 4)
    flash_mma_kernel<<<fgrid, 128, FLASH_SMEM>>>(qh, ql, kh, kl, vh, vl, ahi, alo);

    gemm_mma_kernel<<<ggrid, 256, GEMM_SMEM>>>(ahi, alo, woh, wol, bo,
                                               0, nullptr, out, nullptr, nullptr);
}

// round 7
// speedup vs baseline: 2.6413x; 1.0335x over previous
#include <cuda_runtime.h>
#include <cuda_bf16.h>
#include <stdint.h>
#include <math.h>

// Problem constants
#define SEQ 2048
#define BB  4
#define DD  1024
#define HH  16
#define DH  64
#define MM  (SEQ*BB)   // 8192 rows for GEMMs

// ---------------- scratch (device globals; allocation-free) ----------------
__device__ __nv_bfloat16 g_xhi[MM*DD], g_xlo[MM*DD];
__device__ __nv_bfloat16 g_wqh[DD*DD], g_wql[DD*DD];
__device__ __nv_bfloat16 g_wkh[DD*DD], g_wkl[DD*DD];
__device__ __nv_bfloat16 g_wvh[DD*DD], g_wvl[DD*DD];
__device__ __nv_bfloat16 g_woh[DD*DD], g_wol[DD*DD];
// q,k in [b,h,s,dh]; v transposed [b,h,dh,s]; att in [s,b,D] (hi/lo)
__device__ __nv_bfloat16 g_qh[MM*DD], g_ql[MM*DD];
__device__ __nv_bfloat16 g_kh[MM*DD], g_kl[MM*DD];
__device__ __nv_bfloat16 g_vh[MM*DD], g_vl[MM*DD];
__device__ __nv_bfloat16 g_ahi[MM*DD], g_alo[MM*DD];

// ---------------- PTX helpers (baseline ISA only) ----------------
static __device__ __forceinline__ uint32_t s2u(const void* p) {
    return (uint32_t)__cvta_generic_to_shared(p);
}

#define CP_ASYNC16(saddr, gptr) \
    asm volatile("cp.async.cg.shared.global [%0], [%1], 16;" :: "r"(saddr), "l"(gptr))
#define CP_COMMIT() asm volatile("cp.async.commit_group;" ::: "memory")
#define CP_WAIT(n)  asm volatile("cp.async.wait_group %0;" :: "n"(n) : "memory")

static __device__ __forceinline__ void ldsm_x4(uint32_t addr,
    uint32_t &r0, uint32_t &r1, uint32_t &r2, uint32_t &r3)
{
    asm volatile("ldmatrix.sync.aligned.m8n8.x4.shared.b16 {%0,%1,%2,%3}, [%4];"
        : "=r"(r0), "=r"(r1), "=r"(r2), "=r"(r3) : "r"(addr));
}

static __device__ __forceinline__ void mma16816(float* d,
    uint32_t a0, uint32_t a1, uint32_t a2, uint32_t a3, uint32_t b0, uint32_t b1)
{
    asm volatile("mma.sync.aligned.m16n8k16.row.col.f32.bf16.bf16.f32 "
        "{%0,%1,%2,%3}, {%4,%5,%6,%7}, {%8,%9}, {%0,%1,%2,%3};"
        : "+f"(d[0]), "+f"(d[1]), "+f"(d[2]), "+f"(d[3])
        : "r"(a0), "r"(a1), "r"(a2), "r"(a3), "r"(b0), "r"(b1));
}

static __device__ __forceinline__ uint32_t packbf(float x, float y) {
    __nv_bfloat162 t = __floats2bfloat162_rn(x, y);
    return *(uint32_t*)&t;
}
static __device__ __forceinline__ float lof(float x) {
    return x - __bfloat162float(__float2bfloat16_rn(x));
}

// ---------------- splits: fp32 -> bf16 hi + bf16 lo ----------------
__global__ void split_kernel(const float* __restrict__ src,
                             __nv_bfloat16* __restrict__ hi,
                             __nv_bfloat16* __restrict__ lo, int n4)
{
    int i = blockIdx.x * blockDim.x + threadIdx.x;
    if (i >= n4) return;
    float4 v = ((const float4*)src)[i];
    __nv_bfloat162* hp = (__nv_bfloat162*)hi;
    __nv_bfloat162* lp = (__nv_bfloat162*)lo;
    hp[i*2+0] = __floats2bfloat162_rn(v.x, v.y);
    hp[i*2+1] = __floats2bfloat162_rn(v.z, v.w);
    lp[i*2+0] = __floats2bfloat162_rn(lof(v.x), lof(v.y));
    lp[i*2+1] = __floats2bfloat162_rn(lof(v.z), lof(v.w));
}

__global__ void split4_kernel(const float* __restrict__ s0, const float* __restrict__ s1,
                              const float* __restrict__ s2, const float* __restrict__ s3,
                              __nv_bfloat16* __restrict__ h0, __nv_bfloat16* __restrict__ l0,
                              __nv_bfloat16* __restrict__ h1, __nv_bfloat16* __restrict__ l1,
                              __nv_bfloat16* __restrict__ h2, __nv_bfloat16* __restrict__ l2,
                              __nv_bfloat16* __restrict__ h3, __nv_bfloat16* __restrict__ l3,
                              int n4)
{
    int i = blockIdx.x * blockDim.x + threadIdx.x;
    if (i >= n4) return;
    const float* src; __nv_bfloat16 *hi, *lo;
    switch (blockIdx.y) {
        case 0:  src = s0; hi = h0; lo = l0; break;
        case 1:  src = s1; hi = h1; lo = l1; break;
        case 2:  src = s2; hi = h2; lo = l2; break;
        default: src = s3; hi = h3; lo = l3; break;
    }
    float4 v = ((const float4*)src)[i];
    __nv_bfloat162* hp = (__nv_bfloat162*)hi;
    __nv_bfloat162* lp = (__nv_bfloat162*)lo;
    hp[i*2+0] = __floats2bfloat162_rn(v.x, v.y);
    hp[i*2+1] = __floats2bfloat162_rn(v.z, v.w);
    lp[i*2+0] = __floats2bfloat162_rn(lof(v.x), lof(v.y));
    lp[i*2+1] = __floats2bfloat162_rn(lof(v.z), lof(v.w));
}

// ---------------------------------------------------------------------------
// HMMA GEMM (3-pass, pass-outer mma order for ILP).
// mode 0: fp32 out [s,b,D]
// mode 1: bf16 hi/lo out [b,h,s,dh]  (+ 1/(exp(beta_h)*8) scaling if beta)
// mode 2: bf16 hi/lo out transposed [b,h,dh,s]
// ---------------------------------------------------------------------------
#define GBK 32
#define NCG (DD / GBK)
#define RSMEM 80
#define TILE_B (128 * RSMEM)
#define BUF_B  (4 * TILE_B)
#define GEMM_SMEM (2 * BUF_B)

__global__ __launch_bounds__(256, 2)
void gemm_mma_kernel(const __nv_bfloat16* __restrict__ Ahi,
                     const __nv_bfloat16* __restrict__ Alo,
                     const __nv_bfloat16* __restrict__ Bhi,
                     const __nv_bfloat16* __restrict__ Blo,
                     const float* __restrict__ bias,
                     int mode, const float* __restrict__ beta,
                     float* __restrict__ C,
                     __nv_bfloat16* __restrict__ Oh,
                     __nv_bfloat16* __restrict__ Ol)
{
    extern __shared__ char smc[];
    const int tid  = threadIdx.x;
    const int wid  = tid >> 5;
    const int lane = tid & 31;
    const int bn = blockIdx.x * 128;
    const int bm = blockIdx.y * 128;
    const uint32_t sb = s2u(smc);

    const int warpM = wid >> 2;
    const int warpN = wid & 3;
    const int m0 = warpM * 64;
    const int n0 = warpN * 32;

    const int lrow0 = tid >> 2;
    const int lseg  = tid & 3;

    const __nv_bfloat16* gsrc[4] = {Ahi, Alo, Bhi, Blo};
    const int rowbase[4] = {bm, bm, bn, bn};

    #pragma unroll
    for (int t = 0; t < 4; t++) {
        const __nv_bfloat16* g = gsrc[t] + (size_t)(rowbase[t]) * DD + lseg * 8;
        uint32_t sb_t = sb + t * TILE_B + lseg * 16;
        CP_ASYNC16(sb_t + lrow0 * RSMEM,        g + (size_t)lrow0 * DD);
        CP_ASYNC16(sb_t + (lrow0 + 64) * RSMEM, g + (size_t)(lrow0 + 64) * DD);
    }
    CP_COMMIT();

    float acc[4][4][4];
    #pragma unroll
    for (int mi = 0; mi < 4; mi++)
        #pragma unroll
        for (int ni = 0; ni < 4; ni++)
            #pragma unroll
            for (int f = 0; f < 4; f++) acc[mi][ni][f] = 0.0f;

    for (int c = 0; c < NCG; c++) {
        if (c + 1 < NCG) {
            const int k0 = (c + 1) * GBK;
            const uint32_t bufo = ((c + 1) & 1) * BUF_B;
            #pragma unroll
            for (int t = 0; t < 4; t++) {
                const __nv_bfloat16* g = gsrc[t] + (size_t)(rowbase[t]) * DD + k0 + lseg * 8;
                uint32_t sb_t = sb + bufo + t * TILE_B + lseg * 16;
                CP_ASYNC16(sb_t + lrow0 * RSMEM,        g + (size_t)lrow0 * DD);
                CP_ASYNC16(sb_t + (lrow0 + 64) * RSMEM, g + (size_t)(lrow0 + 64) * DD);
            }
            CP_COMMIT();
            CP_WAIT(1);
        } else {
            CP_WAIT(0);
        }
        __syncthreads();

        const uint32_t bufo = (c & 1) * BUF_B;
        const uint32_t AhT = sb + bufo + 0 * TILE_B;
        const uint32_t AlT = sb + bufo + 1 * TILE_B;
        const uint32_t BhT = sb + bufo + 2 * TILE_B;
        const uint32_t BlT = sb + bufo + 3 * TILE_B;

        #pragma unroll
        for (int s = 0; s < 2; s++) {
            const uint32_t kb = s * 32;
            uint32_t bh[4][2], bl[4][2], ah[4][4], al[4][4];
            {
                int g = lane >> 3;
                int ntl = g >> 1, half = g & 1;
                uint32_t boff = (uint32_t)(n0 + ntl * 8 + (lane & 7)) * RSMEM
                              + kb + half * 16;
                ldsm_x4(BhT + boff,              bh[0][0], bh[0][1], bh[1][0], bh[1][1]);
                ldsm_x4(BhT + boff + 16 * RSMEM, bh[2][0], bh[2][1], bh[3][0], bh[3][1]);
                ldsm_x4(BlT + boff,              bl[0][0], bl[0][1], bl[1][0], bl[1][1]);
                ldsm_x4(BlT + boff + 16 * RSMEM, bl[2][0], bl[2][1], bl[3][0], bl[3][1]);
            }
            #pragma unroll
            for (int mi = 0; mi < 4; mi++) {
                uint32_t aoff = (uint32_t)(m0 + mi * 16 + (lane & 15)) * RSMEM
                              + kb + (lane >> 4) * 16;
                ldsm_x4(AhT + aoff, ah[mi][0], ah[mi][1], ah[mi][2], ah[mi][3]);
                ldsm_x4(AlT + aoff, al[mi][0], al[mi][1], al[mi][2], al[mi][3]);
            }
            // pass-outer: 16 independent mmas between touches of the same acc
            #pragma unroll
            for (int mi = 0; mi < 4; mi++)
                #pragma unroll
                for (int ni = 0; ni < 4; ni++)
                    mma16816(acc[mi][ni], ah[mi][0], ah[mi][1], ah[mi][2], ah[mi][3],
                             bh[ni][0], bh[ni][1]);
            #pragma unroll
            for (int mi = 0; mi < 4; mi++)
                #pragma unroll
                for (int ni = 0; ni < 4; ni++)
                    mma16816(acc[mi][ni], ah[mi][0], ah[mi][1], ah[mi][2], ah[mi][3],
                             bl[ni][0], bl[ni][1]);
            #pragma unroll
            for (int mi = 0; mi < 4; mi++)
                #pragma unroll
                for (int ni = 0; ni < 4; ni++)
                    mma16816(acc[mi][ni], al[mi][0], al[mi][1], al[mi][2], al[mi][3],
                             bh[ni][0], bh[ni][1]);
        }
        __syncthreads();
    }

    const int erow = lane >> 2;
    const int ecol = (lane & 3) * 2;
    #pragma unroll
    for (int mi = 0; mi < 4; mi++) {
        #pragma unroll
        for (int ni = 0; ni < 4; ni++) {
            int gr = bm + m0 + mi * 16 + erow;
            int gc = bn + n0 + ni * 8 + ecol;
            float v0x = acc[mi][ni][0] + bias[gc];
            float v0y = acc[mi][ni][1] + bias[gc + 1];
            float v1x = acc[mi][ni][2] + bias[gc];
            float v1y = acc[mi][ni][3] + bias[gc + 1];
            if (mode == 0) {
                float2 a = {v0x, v0y}, bb2 = {v1x, v1y};
                *(float2*)(C + (size_t)gr * DD + gc)       = a;
                *(float2*)(C + (size_t)(gr + 8) * DD + gc) = bb2;
            } else {
                int hh = gc >> 6, dh = gc & 63;
                if (beta) {
                    float sc = 1.0f / (__expf(beta[hh]) * 8.0f);
                    v0x *= sc; v0y *= sc; v1x *= sc; v1y *= sc;
                }
                int s0 = gr >> 2, bbi = gr & 3;
                if (mode == 1) {
                    size_t off0 = (((size_t)bbi * HH + hh) * SEQ + s0) * DH + dh;
                    size_t off1 = off0 + 2 * DH;
                    *(uint32_t*)(Oh + off0) = packbf(v0x, v0y);
                    *(uint32_t*)(Oh + off1) = packbf(v1x, v1y);
                    *(uint32_t*)(Ol + off0) = packbf(lof(v0x), lof(v0y));
                    *(uint32_t*)(Ol + off1) = packbf(lof(v1x), lof(v1y));
                } else {
                    size_t off = (((size_t)bbi * HH + hh) * DH + dh) * SEQ + s0;
                    Oh[off]           = __float2bfloat16_rn(v0x);
                    Oh[off + SEQ]     = __float2bfloat16_rn(v0y);
                    Oh[off + 2]       = __float2bfloat16_rn(v1x);
                    Oh[off + SEQ + 2] = __float2bfloat16_rn(v1y);
                    Ol[off]           = __float2bfloat16_rn(lof(v0x));
                    Ol[off + SEQ]     = __float2bfloat16_rn(lof(v0y));
                    Ol[off + 2]       = __float2bfloat16_rn(lof(v1x));
                    Ol[off + SEQ + 2] = __float2bfloat16_rn(lof(v1y));
                }
            }
        }
    }
}

// ---------------------------------------------------------------------------
// Flash attention on mma.sync bf16, 3-pass split, pass-outer mma order.
// ---------------------------------------------------------------------------
#define FRB 144
#define QT_B (64 * FRB)
#define STG_B (4 * QT_B)
#define FLASH_SMEM (2 * QT_B + 2 * STG_B)   // 92160

static __device__ __forceinline__ void ldsm_b(uint32_t tile, int nbase, int ksb,
                                              int lane, uint32_t* r4)
{
    int g = lane >> 3, ntl = g >> 1, half = g & 1;
    uint32_t addr = tile + (uint32_t)(nbase + ntl * 8 + (lane & 7)) * FRB
                  + ksb + half * 16;
    ldsm_x4(addr, r4[0], r4[1], r4[2], r4[3]);
}

__global__ __launch_bounds__(128)
void flash_mma_kernel(const __nv_bfloat16* __restrict__ qh_g,
                      const __nv_bfloat16* __restrict__ ql_g,
                      const __nv_bfloat16* __restrict__ kh_g,
                      const __nv_bfloat16* __restrict__ kl_g,
                      const __nv_bfloat16* __restrict__ vh_g,
                      const __nv_bfloat16* __restrict__ vl_g,
                      __nv_bfloat16* __restrict__ ahi,
                      __nv_bfloat16* __restrict__ alo)
{
    extern __shared__ char smf[];
    const int tid = threadIdx.x, lane = tid & 31, wid = tid >> 5;
    const int qb = (int)gridDim.x - 1 - (int)blockIdx.x;   // LPT order
    const int h = blockIdx.y, b = blockIdx.z;
    const int q0 = qb * 64;
    const uint32_t sb = s2u(smf);
    const uint32_t qhS = sb, qlS = sb + QT_B;

    const size_t bh = (size_t)b * HH + h;
    const char* qhp = (const char*)(qh_g + (bh * SEQ + q0) * DH);
    const char* qlp = (const char*)(ql_g + (bh * SEQ + q0) * DH);
    const __nv_bfloat16* khp = kh_g + bh * SEQ * DH;
    const __nv_bfloat16* klp = kl_g + bh * SEQ * DH;
    const __nv_bfloat16* vhp = vh_g + bh * (size_t)DH * SEQ;
    const __nv_bfloat16* vlp = vl_g + bh * (size_t)DH * SEQ;

    #pragma unroll
    for (int u = 0; u < 4; u++) {
        int lin = tid + u * 128; int row = lin >> 3, seg = lin & 7;
        CP_ASYNC16(qhS + row * FRB + seg * 16, qhp + row * 128 + seg * 16);
        CP_ASYNC16(qlS + row * FRB + seg * 16, qlp + row * 128 + seg * 16);
    }
    CP_COMMIT();

    {
        uint32_t base = sb + 2 * QT_B;
        #pragma unroll
        for (int u = 0; u < 4; u++) {
            int lin = tid + u * 128; int row = lin >> 3, seg = lin & 7;
            size_t koff = (size_t)row * DH + seg * 8;
            CP_ASYNC16(base + 0 * QT_B + row * FRB + seg * 16, khp + koff);
            CP_ASYNC16(base + 1 * QT_B + row * FRB + seg * 16, klp + koff);
            size_t voff = (size_t)row * SEQ + seg * 8;
            CP_ASYNC16(base + 2 * QT_B + row * FRB + seg * 16, vhp + voff);
            CP_ASYNC16(base + 3 * QT_B + row * FRB + seg * 16, vlp + voff);
        }
        CP_COMMIT();
    }
    CP_WAIT(0);
    __syncthreads();

    const int qrow0 = wid * 16;
    uint32_t qah[4][4], qal[4][4];
    #pragma unroll
    for (int ks = 0; ks < 4; ks++) {
        uint32_t ah = qhS + (uint32_t)(qrow0 + (lane & 15)) * FRB + ks * 32 + (lane >> 4) * 16;
        uint32_t al = qlS + (uint32_t)(qrow0 + (lane & 15)) * FRB + ks * 32 + (lane >> 4) * 16;
        ldsm_x4(ah, qah[ks][0], qah[ks][1], qah[ks][2], qah[ks][3]);
        ldsm_x4(al, qal[ks][0], qal[ks][1], qal[ks][2], qal[ks][3]);
    }

    float Oa[8][4];
    #pragma unroll
    for (int nt = 0; nt < 8; nt++)
        #pragma unroll
        for (int f = 0; f < 4; f++) Oa[nt][f] = 0.0f;
    float mrow[2] = {0.0f, 0.0f};
    float lrow[2] = {1.0f, 1.0f};

    for (int jt = 0; jt <= qb; jt++) {
        const int s = jt & 1;
        if (jt < qb) {
            uint32_t base = sb + 2 * QT_B + (s ^ 1) * STG_B;
            const int j1 = (jt + 1) * 64;
            #pragma unroll
            for (int u = 0; u < 4; u++) {
                int lin = tid + u * 128; int row = lin >> 3, seg = lin & 7;
                size_t koff = (size_t)(j1 + row) * DH + seg * 8;
                CP_ASYNC16(base + 0 * QT_B + row * FRB + seg * 16, khp + koff);
                CP_ASYNC16(base + 1 * QT_B + row * FRB + seg * 16, klp + koff);
                size_t voff = (size_t)row * SEQ + j1 + seg * 8;
                CP_ASYNC16(base + 2 * QT_B + row * FRB + seg * 16, vhp + voff);
                CP_ASYNC16(base + 3 * QT_B + row * FRB + seg * 16, vlp + voff);
            }
            CP_COMMIT();
            CP_WAIT(1);
        } else {
            CP_WAIT(0);
        }
        __syncthreads();

        const uint32_t st = sb + 2 * QT_B + s * STG_B;
        const uint32_t khT = st, klT = st + QT_B, vhT = st + 2 * QT_B, vlT = st + 3 * QT_B;

        // ---- S = Q K^T (3-pass, pass-outer) ----
        float S[8][4];
        #pragma unroll
        for (int nt = 0; nt < 8; nt++)
            #pragma unroll
            for (int f = 0; f < 4; f++) S[nt][f] = 0.0f;

        #pragma unroll
        for (int ks = 0; ks < 4; ks++) {
            uint32_t kh4[16], kl4[16];
            #pragma unroll
            for (int p = 0; p < 4; p++) {
                ldsm_b(khT, p * 16, ks * 32, lane, kh4 + p * 4);
                ldsm_b(klT, p * 16, ks * 32, lane, kl4 + p * 4);
            }
            #pragma unroll
            for (int nt = 0; nt < 8; nt++)
                mma16816(S[nt], qah[ks][0], qah[ks][1], qah[ks][2], qah[ks][3],
                         kh4[2 * nt], kh4[2 * nt + 1]);
            #pragma unroll
            for (int nt = 0; nt < 8; nt++)
                mma16816(S[nt], qah[ks][0], qah[ks][1], qah[ks][2], qah[ks][3],
                         kl4[2 * nt], kl4[2 * nt + 1]);
            #pragma unroll
            for (int nt = 0; nt < 8; nt++)
                mma16816(S[nt], qal[ks][0], qal[ks][1], qal[ks][2], qal[ks][3],
                         kh4[2 * nt], kh4[2 * nt + 1]);
        }

        if (jt == qb) {
            const int j0 = jt * 64;
            #pragma unroll
            for (int nt = 0; nt < 8; nt++) {
                #pragma unroll
                for (int e = 0; e < 4; e++) {
                    int grow = q0 + qrow0 + (lane >> 2) + ((e >= 2) ? 8 : 0);
                    int gcol = j0 + nt * 8 + (lane & 3) * 2 + (e & 1);
                    if (gcol > grow) S[nt][e] = -1e30f;
                }
            }
        }

        // ---- online softmax ----
        #pragma unroll
        for (int i = 0; i < 2; i++) {
            float rm = -1e30f;
            #pragma unroll
            for (int nt = 0; nt < 8; nt++)
                rm = fmaxf(rm, fmaxf(S[nt][2 * i], S[nt][2 * i + 1]));
            rm = fmaxf(rm, __shfl_xor_sync(0xffffffffu, rm, 1));
            rm = fmaxf(rm, __shfl_xor_sync(0xffffffffu, rm, 2));
            float mn = fmaxf(mrow[i], rm);
            float alpha = __expf(mrow[i] - mn);
            float rs = 0.0f;
            #pragma unroll
            for (int nt = 0; nt < 8; nt++) {
                float p0 = __expf(S[nt][2 * i]     - mn);
                float p1 = __expf(S[nt][2 * i + 1] - mn);
                S[nt][2 * i] = p0; S[nt][2 * i + 1] = p1;
                rs += p0 + p1;
            }
            rs += __shfl_xor_sync(0xffffffffu, rs, 1);
            rs += __shfl_xor_sync(0xffffffffu, rs, 2);
            lrow[i] = lrow[i] * alpha + rs;
            mrow[i] = mn;
            #pragma unroll
            for (int nt = 0; nt < 8; nt++) {
                Oa[nt][2 * i]     *= alpha;
                Oa[nt][2 * i + 1] *= alpha;
            }
        }

        // ---- O += P V (3-pass, pass-outer) ----
        #pragma unroll
        for (int ks = 0; ks < 4; ks++) {
            uint32_t ah0 = packbf(S[2 * ks][0],     S[2 * ks][1]);
            uint32_t ah1 = packbf(S[2 * ks][2],     S[2 * ks][3]);
            uint32_t ah2 = packbf(S[2 * ks + 1][0], S[2 * ks + 1][1]);
            uint32_t ah3 = packbf(S[2 * ks + 1][2], S[2 * ks + 1][3]);
            uint32_t al0 = packbf(lof(S[2 * ks][0]),     lof(S[2 * ks][1]));
            uint32_t al1 = packbf(lof(S[2 * ks][2]),     lof(S[2 * ks][3]));
            uint32_t al2 = packbf(lof(S[2 * ks + 1][0]), lof(S[2 * ks + 1][1]));
            uint32_t al3 = packbf(lof(S[2 * ks + 1][2]), lof(S[2 * ks + 1][3]));
            uint32_t vh4[16], vl4[16];
            #pragma unroll
            for (int p = 0; p < 4; p++) {
                ldsm_b(vhT, p * 16, ks * 32, lane, vh4 + p * 4);
                ldsm_b(vlT, p * 16, ks * 32, lane, vl4 + p * 4);
            }
            #pragma unroll
            for (int nt = 0; nt < 8; nt++)
                mma16816(Oa[nt], ah0, ah1, ah2, ah3, vh4[2 * nt], vh4[2 * nt + 1]);
            #pragma unroll
            for (int nt = 0; nt < 8; nt++)
                mma16816(Oa[nt], ah0, ah1, ah2, ah3, vl4[2 * nt], vl4[2 * nt + 1]);
            #pragma unroll
            for (int nt = 0; nt < 8; nt++)
                mma16816(Oa[nt], al0, al1, al2, al3, vh4[2 * nt], vh4[2 * nt + 1]);
        }
        __syncthreads();
    }

    // ---- epilogue ----
    const float inv0 = 1.0f / lrow[0];
    const float inv1 = 1.0f / lrow[1];
    const int r = lane >> 2, c2 = (lane & 3) * 2;
    const int srow0 = q0 + qrow0 + r;
    #pragma unroll
    for (int nt = 0; nt < 8; nt++) {
        int col = h * 64 + nt * 8 + c2;
        float o00 = Oa[nt][0] * inv0, o01 = Oa[nt][1] * inv0;
        float o10 = Oa[nt][2] * inv1, o11 = Oa[nt][3] * inv1;
        size_t off0 = ((size_t)srow0 * BB + b) * DD + col;
        size_t off1 = ((size_t)(srow0 + 8) * BB + b) * DD + col;
        *(uint32_t*)(ahi + off0) = packbf(o00, o01);
        *(uint32_t*)(ahi + off1) = packbf(o10, o11);
        *(uint32_t*)(alo + off0) = packbf(lof(o00), lof(o01));
        *(uint32_t*)(alo + off1) = packbf(lof(o10), lof(o11));
    }
}

// ---------------------------------------------------------------------------
extern "C" void kernel_launch(void* const* d_in, const int* in_sizes, int n_in,
                              void* d_out, int out_size)
{
    const float* x    = (const float*)d_in[0];
    const float* beta = (const float*)d_in[2];
    const float* Wq   = (const float*)d_in[3];
    const float* bq   = (const float*)d_in[4];
    const float* Wk   = (const float*)d_in[5];
    const float* bk   = (const float*)d_in[6];
    const float* Wv   = (const float*)d_in[7];
    const float* bv   = (const float*)d_in[8];
    const float* Wo   = (const float*)d_in[9];
    const float* bo   = (const float*)d_in[10];
    float* out = (float*)d_out;

    __nv_bfloat16 *xhi, *xlo, *wqh, *wql, *wkh, *wkl, *wvh, *wvl, *woh, *wol;
    __nv_bfloat16 *qh, *ql, *kh, *kl, *vh, *vl, *ahi, *alo;
    cudaGetSymbolAddress((void**)&xhi, g_xhi);
    cudaGetSymbolAddress((void**)&xlo, g_xlo);
    cudaGetSymbolAddress((void**)&wqh, g_wqh);
    cudaGetSymbolAddress((void**)&wql, g_wql);
    cudaGetSymbolAddress((void**)&wkh, g_wkh);
    cudaGetSymbolAddress((void**)&wkl, g_wkl);
    cudaGetSymbolAddress((void**)&wvh, g_wvh);
    cudaGetSymbolAddress((void**)&wvl, g_wvl);
    cudaGetSymbolAddress((void**)&woh, g_woh);
    cudaGetSymbolAddress((void**)&wol, g_wol);
    cudaGetSymbolAddress((void**)&qh, g_qh);
    cudaGetSymbolAddress((void**)&ql, g_ql);
    cudaGetSymbolAddress((void**)&kh, g_kh);
    cudaGetSymbolAddress((void**)&kl, g_kl);
    cudaGetSymbolAddress((void**)&vh, g_vh);
    cudaGetSymbolAddress((void**)&vl, g_vl);
    cudaGetSymbolAddress((void**)&ahi, g_ahi);
    cudaGetSymbolAddress((void**)&alo, g_alo);

    cudaFuncSetAttribute(gemm_mma_kernel,
                         cudaFuncAttributeMaxDynamicSharedMemorySize, GEMM_SMEM);
    cudaFuncSetAttribute(flash_mma_kernel,
                         cudaFuncAttributeMaxDynamicSharedMemorySize, FLASH_SMEM);

    const int nx4 = MM * DD / 4;
    const int nw4 = DD * DD / 4;

    split_kernel<<<(nx4 + 255) / 256, 256>>>(x, xhi, xlo, nx4);
    {
        dim3 sg((nw4 + 255) / 256, 4);
        split4_kernel<<<sg, 256>>>(Wq, Wk, Wv, Wo,
                                   wqh, wql, wkh, wkl, wvh, wvl, woh, wol, nw4);
    }

    dim3 ggrid(DD / 128, MM / 128);   // (8, 64)
    gemm_mma_kernel<<<ggrid, 256, GEMM_SMEM>>>(xhi, xlo, wqh, wql, bq,
                                               1, beta, nullptr, qh, ql);
    gemm_mma_kernel<<<ggrid, 256, GEMM_SMEM>>>(xhi, xlo, wkh, wkl, bk,
                                               1, nullptr, nullptr, kh, kl);
    gemm_mma_kernel<<<ggrid, 256, GEMM_SMEM>>>(xhi, xlo, wvh, wvl, bv,
                                               2, nullptr, nullptr, vh, vl);

    dim3 fgrid(SEQ / 64, HH, BB);   // (32, 16, 4)
    flash_mma_kernel<<<fgrid, 128, FLASH_SMEM>>>(qh, ql, kh, kl, vh, vl, ahi, alo);

    gemm_mma_kernel<<<ggrid, 256, GEMM_SMEM>>>(ahi, alo, woh, wol, bo,
                                               0, nullptr, out, nullptr, nullptr);
}

// round 8
// speedup vs baseline: 2.8009x; 1.0604x over previous
#include <cuda_runtime.h>
#include <cuda_bf16.h>
#include <stdint.h>
#include <math.h>

// Problem constants
#define SEQ 2048
#define BB  4
#define DD  1024
#define HH  16
#define DH  64
#define MM  (SEQ*BB)

// ---------------- scratch (device globals; allocation-free) ----------------
__device__ __nv_bfloat16 g_xhi[MM*DD], g_xlo[MM*DD];
__device__ __nv_bfloat16 g_wqh[DD*DD], g_wql[DD*DD];
__device__ __nv_bfloat16 g_wkh[DD*DD], g_wkl[DD*DD];
__device__ __nv_bfloat16 g_wvh[DD*DD], g_wvl[DD*DD];
__device__ __nv_bfloat16 g_woh[DD*DD], g_wol[DD*DD];
__device__ __nv_bfloat16 g_qh[MM*DD], g_ql[MM*DD];
__device__ __nv_bfloat16 g_kh[MM*DD], g_kl[MM*DD];
__device__ __nv_bfloat16 g_vh[MM*DD], g_vl[MM*DD];
__device__ __nv_bfloat16 g_ahi[MM*DD], g_alo[MM*DD];

// ---------------- PTX helpers (baseline ISA only) ----------------
static __device__ __forceinline__ uint32_t s2u(const void* p) {
    return (uint32_t)__cvta_generic_to_shared(p);
}

#define CP_ASYNC16(saddr, gptr) \
    asm volatile("cp.async.cg.shared.global [%0], [%1], 16;" :: "r"(saddr), "l"(gptr))
#define CP_COMMIT() asm volatile("cp.async.commit_group;" ::: "memory")
#define CP_WAIT(n)  asm volatile("cp.async.wait_group %0;" :: "n"(n) : "memory")

static __device__ __forceinline__ void ldsm_x4(uint32_t addr,
    uint32_t &r0, uint32_t &r1, uint32_t &r2, uint32_t &r3)
{
    asm volatile("ldmatrix.sync.aligned.m8n8.x4.shared.b16 {%0,%1,%2,%3}, [%4];"
        : "=r"(r0), "=r"(r1), "=r"(r2), "=r"(r3) : "r"(addr));
}

static __device__ __forceinline__ void mma16816(float* d,
    uint32_t a0, uint32_t a1, uint32_t a2, uint32_t a3, uint32_t b0, uint32_t b1)
{
    asm volatile("mma.sync.aligned.m16n8k16.row.col.f32.bf16.bf16.f32 "
        "{%0,%1,%2,%3}, {%4,%5,%6,%7}, {%8,%9}, {%0,%1,%2,%3};"
        : "+f"(d[0]), "+f"(d[1]), "+f"(d[2]), "+f"(d[3])
        : "r"(a0), "r"(a1), "r"(a2), "r"(a3), "r"(b0), "r"(b1));
}

static __device__ __forceinline__ uint32_t packbf(float x, float y) {
    __nv_bfloat162 t = __floats2bfloat162_rn(x, y);
    return *(uint32_t*)&t;
}
static __device__ __forceinline__ float lof(float x) {
    return x - __bfloat162float(__float2bfloat16_rn(x));
}

// ---------------- splits ----------------
__global__ void split_kernel(const float* __restrict__ src,
                             __nv_bfloat16* __restrict__ hi,
                             __nv_bfloat16* __restrict__ lo, int n4)
{
    int i = blockIdx.x * blockDim.x + threadIdx.x;
    if (i >= n4) return;
    float4 v = ((const float4*)src)[i];
    __nv_bfloat162* hp = (__nv_bfloat162*)hi;
    __nv_bfloat162* lp = (__nv_bfloat162*)lo;
    hp[i*2+0] = __floats2bfloat162_rn(v.x, v.y);
    hp[i*2+1] = __floats2bfloat162_rn(v.z, v.w);
    lp[i*2+0] = __floats2bfloat162_rn(lof(v.x), lof(v.y));
    lp[i*2+1] = __floats2bfloat162_rn(lof(v.z), lof(v.w));
}

__global__ void split4_kernel(const float* __restrict__ s0, const float* __restrict__ s1,
                              const float* __restrict__ s2, const float* __restrict__ s3,
                              int n4)
{
    int i = blockIdx.x * blockDim.x + threadIdx.x;
    if (i >= n4) return;
    const float* src; __nv_bfloat16 *hi, *lo;
    switch (blockIdx.y) {
        case 0:  src = s0; hi = g_wqh; lo = g_wql; break;
        case 1:  src = s1; hi = g_wkh; lo = g_wkl; break;
        case 2:  src = s2; hi = g_wvh; lo = g_wvl; break;
        default: src = s3; hi = g_woh; lo = g_wol; break;
    }
    float4 v = ((const float4*)src)[i];
    __nv_bfloat162* hp = (__nv_bfloat162*)hi;
    __nv_bfloat162* lp = (__nv_bfloat162*)lo;
    hp[i*2+0] = __floats2bfloat162_rn(v.x, v.y);
    hp[i*2+1] = __floats2bfloat162_rn(v.z, v.w);
    lp[i*2+0] = __floats2bfloat162_rn(lof(v.x), lof(v.y));
    lp[i*2+1] = __floats2bfloat162_rn(lof(v.z), lof(v.w));
}

// ---------------------------------------------------------------------------
// HMMA GEMM body (3-pass), CTA tile 128(M)x64(N), 8 warps of 32x32.
// smem/buffer: Ah 10240 | Al 10240 | Bh 5120 | Bl 5120 = 30720; x2 buffers.
// ---------------------------------------------------------------------------
#define GBK 32
#define NCG (DD / GBK)
#define RSMEM 80
#define A_T 10240
#define B_T 5120
#define BUF_B 30720
#define GEMM_SMEM (2 * BUF_B)   // 61440

static __device__ __forceinline__ void gemm_body(
    const __nv_bfloat16* __restrict__ Ahi, const __nv_bfloat16* __restrict__ Alo,
    const __nv_bfloat16* __restrict__ Bhi, const __nv_bfloat16* __restrict__ Blo,
    const float* __restrict__ bias, int mode, const float* __restrict__ beta,
    float* __restrict__ C, __nv_bfloat16* __restrict__ Oh, __nv_bfloat16* __restrict__ Ol,
    int bn, int bm, char* smc)
{
    const int tid  = threadIdx.x;
    const int wid  = tid >> 5;
    const int lane = tid & 31;
    const uint32_t sb = s2u(smc);

    const int m0 = (wid >> 1) * 32;   // warpM 0..3
    const int n0 = (wid & 1) * 32;    // warpN 0..1

    const int lrow0 = tid >> 2;       // 0..63
    const int lseg  = tid & 3;

    // prologue chunk 0 -> buffer 0
    {
        const __nv_bfloat16* ga0 = Ahi + (size_t)(bm + lrow0) * DD + lseg * 8;
        const __nv_bfloat16* ga1 = Alo + (size_t)(bm + lrow0) * DD + lseg * 8;
        const __nv_bfloat16* gb0 = Bhi + (size_t)(bn + lrow0) * DD + lseg * 8;
        const __nv_bfloat16* gb1 = Blo + (size_t)(bn + lrow0) * DD + lseg * 8;
        uint32_t sa = sb + lrow0 * RSMEM + lseg * 16;
        CP_ASYNC16(sa,                     ga0);
        CP_ASYNC16(sa + 64 * RSMEM,        ga0 + (size_t)64 * DD);
        CP_ASYNC16(sa + A_T,               ga1);
        CP_ASYNC16(sa + A_T + 64 * RSMEM,  ga1 + (size_t)64 * DD);
        CP_ASYNC16(sa + 2 * A_T,           gb0);
        CP_ASYNC16(sa + 2 * A_T + B_T,     gb1);
    }
    CP_COMMIT();

    float acc[2][4][4];
    #pragma unroll
    for (int mi = 0; mi < 2; mi++)
        #pragma unroll
        for (int ni = 0; ni < 4; ni++)
            #pragma unroll
            for (int f = 0; f < 4; f++) acc[mi][ni][f] = 0.0f;

    for (int c = 0; c < NCG; c++) {
        if (c + 1 < NCG) {
            const int k0 = (c + 1) * GBK;
            const uint32_t bufo = ((c + 1) & 1) * BUF_B;
            const __nv_bfloat16* ga0 = Ahi + (size_t)(bm + lrow0) * DD + k0 + lseg * 8;
            const __nv_bfloat16* ga1 = Alo + (size_t)(bm + lrow0) * DD + k0 + lseg * 8;
            const __nv_bfloat16* gb0 = Bhi + (size_t)(bn + lrow0) * DD + k0 + lseg * 8;
            const __nv_bfloat16* gb1 = Blo + (size_t)(bn + lrow0) * DD + k0 + lseg * 8;
            uint32_t sa = sb + bufo + lrow0 * RSMEM + lseg * 16;
            CP_ASYNC16(sa,                     ga0);
            CP_ASYNC16(sa + 64 * RSMEM,        ga0 + (size_t)64 * DD);
            CP_ASYNC16(sa + A_T,               ga1);
            CP_ASYNC16(sa + A_T + 64 * RSMEM,  ga1 + (size_t)64 * DD);
            CP_ASYNC16(sa + 2 * A_T,           gb0);
            CP_ASYNC16(sa + 2 * A_T + B_T,     gb1);
            CP_COMMIT();
            CP_WAIT(1);
        } else {
            CP_WAIT(0);
        }
        __syncthreads();

        const uint32_t bufo = (c & 1) * BUF_B;
        const uint32_t AhT = sb + bufo;
        const uint32_t AlT = AhT + A_T;
        const uint32_t BhT = AhT + 2 * A_T;
        const uint32_t BlT = BhT + B_T;

        #pragma unroll
        for (int s = 0; s < 2; s++) {
            const uint32_t kb = s * 32;
            uint32_t bh[4][2], bl[4][2], ah[2][4], al[2][4];
            {
                int g = lane >> 3;
                int ntl = g >> 1, half = g & 1;
                uint32_t boff = (uint32_t)(n0 + ntl * 8 + (lane & 7)) * RSMEM
                              + kb + half * 16;
                ldsm_x4(BhT + boff,              bh[0][0], bh[0][1], bh[1][0], bh[1][1]);
                ldsm_x4(BhT + boff + 16 * RSMEM, bh[2][0], bh[2][1], bh[3][0], bh[3][1]);
                ldsm_x4(BlT + boff,              bl[0][0], bl[0][1], bl[1][0], bl[1][1]);
                ldsm_x4(BlT + boff + 16 * RSMEM, bl[2][0], bl[2][1], bl[3][0], bl[3][1]);
            }
            #pragma unroll
            for (int mi = 0; mi < 2; mi++) {
                uint32_t aoff = (uint32_t)(m0 + mi * 16 + (lane & 15)) * RSMEM
                              + kb + (lane >> 4) * 16;
                ldsm_x4(AhT + aoff, ah[mi][0], ah[mi][1], ah[mi][2], ah[mi][3]);
                ldsm_x4(AlT + aoff, al[mi][0], al[mi][1], al[mi][2], al[mi][3]);
            }
            #pragma unroll
            for (int mi = 0; mi < 2; mi++)
                #pragma unroll
                for (int ni = 0; ni < 4; ni++)
                    mma16816(acc[mi][ni], ah[mi][0], ah[mi][1], ah[mi][2], ah[mi][3],
                             bh[ni][0], bh[ni][1]);
            #pragma unroll
            for (int mi = 0; mi < 2; mi++)
                #pragma unroll
                for (int ni = 0; ni < 4; ni++)
                    mma16816(acc[mi][ni], ah[mi][0], ah[mi][1], ah[mi][2], ah[mi][3],
                             bl[ni][0], bl[ni][1]);
            #pragma unroll
            for (int mi = 0; mi < 2; mi++)
                #pragma unroll
                for (int ni = 0; ni < 4; ni++)
                    mma16816(acc[mi][ni], al[mi][0], al[mi][1], al[mi][2], al[mi][3],
                             bh[ni][0], bh[ni][1]);
        }
        __syncthreads();
    }

    const int erow = lane >> 2;
    const int ecol = (lane & 3) * 2;
    #pragma unroll
    for (int mi = 0; mi < 2; mi++) {
        #pragma unroll
        for (int ni = 0; ni < 4; ni++) {
            int gr = bm + m0 + mi * 16 + erow;
            int gc = bn + n0 + ni * 8 + ecol;
            float v0x = acc[mi][ni][0] + bias[gc];
            float v0y = acc[mi][ni][1] + bias[gc + 1];
            float v1x = acc[mi][ni][2] + bias[gc];
            float v1y = acc[mi][ni][3] + bias[gc + 1];
            if (mode == 0) {
                float2 a = {v0x, v0y}, bb2 = {v1x, v1y};
                *(float2*)(C + (size_t)gr * DD + gc)       = a;
                *(float2*)(C + (size_t)(gr + 8) * DD + gc) = bb2;
            } else {
                int hh = gc >> 6, dh = gc & 63;
                if (beta) {
                    float sc = 1.0f / (__expf(beta[hh]) * 8.0f);
                    v0x *= sc; v0y *= sc; v1x *= sc; v1y *= sc;
                }
                int s0 = gr >> 2, bbi = gr & 3;
                if (mode == 1) {
                    size_t off0 = (((size_t)bbi * HH + hh) * SEQ + s0) * DH + dh;
                    size_t off1 = off0 + 2 * DH;
                    *(uint32_t*)(Oh + off0) = packbf(v0x, v0y);
                    *(uint32_t*)(Oh + off1) = packbf(v1x, v1y);
                    *(uint32_t*)(Ol + off0) = packbf(lof(v0x), lof(v0y));
                    *(uint32_t*)(Ol + off1) = packbf(lof(v1x), lof(v1y));
                } else {
                    size_t off = (((size_t)bbi * HH + hh) * DH + dh) * SEQ + s0;
                    Oh[off]           = __float2bfloat16_rn(v0x);
                    Oh[off + SEQ]     = __float2bfloat16_rn(v0y);
                    Oh[off + 2]       = __float2bfloat16_rn(v1x);
                    Oh[off + SEQ + 2] = __float2bfloat16_rn(v1y);
                    Ol[off]           = __float2bfloat16_rn(lof(v0x));
                    Ol[off + SEQ]     = __float2bfloat16_rn(lof(v0y));
                    Ol[off + 2]       = __float2bfloat16_rn(lof(v1x));
                    Ol[off + SEQ + 2] = __float2bfloat16_rn(lof(v1y));
                }
            }
        }
    }
}

// Fused Q/K/V projection: blockIdx.z selects weight/output/mode.
__global__ __launch_bounds__(256, 3)
void gemm_qkv_kernel(const float* __restrict__ beta,
                     const float* __restrict__ bq,
                     const float* __restrict__ bk,
                     const float* __restrict__ bv)
{
    extern __shared__ char smc[];
    const int bn = blockIdx.x * 64;
    const int bm = blockIdx.y * 128;
    if (blockIdx.z == 0)
        gemm_body(g_xhi, g_xlo, g_wqh, g_wql, bq, 1, beta, nullptr, g_qh, g_ql, bn, bm, smc);
    else if (blockIdx.z == 1)
        gemm_body(g_xhi, g_xlo, g_wkh, g_wkl, bk, 1, nullptr, nullptr, g_kh, g_kl, bn, bm, smc);
    else
        gemm_body(g_xhi, g_xlo, g_wvh, g_wvl, bv, 2, nullptr, nullptr, g_vh, g_vl, bn, bm, smc);
}

// Output projection: fp32 out.
__global__ __launch_bounds__(256, 3)
void gemm_out_kernel(const float* __restrict__ bo, float* __restrict__ out)
{
    extern __shared__ char smc[];
    const int bn = blockIdx.x * 64;
    const int bm = blockIdx.y * 128;
    gemm_body(g_ahi, g_alo, g_woh, g_wol, bo, 0, nullptr, out, nullptr, nullptr, bn, bm, smc);
}

// ---------------------------------------------------------------------------
// Flash attention (unchanged from R7: mma.sync bf16, 3-pass, pass-outer, LPT)
// ---------------------------------------------------------------------------
#define FRB 144
#define QT_B (64 * FRB)
#define STG_B (4 * QT_B)
#define FLASH_SMEM (2 * QT_B + 2 * STG_B)   // 92160

static __device__ __forceinline__ void ldsm_b(uint32_t tile, int nbase, int ksb,
                                              int lane, uint32_t* r4)
{
    int g = lane >> 3, ntl = g >> 1, half = g & 1;
    uint32_t addr = tile + (uint32_t)(nbase + ntl * 8 + (lane & 7)) * FRB
                  + ksb + half * 16;
    ldsm_x4(addr, r4[0], r4[1], r4[2], r4[3]);
}

__global__ __launch_bounds__(128)
void flash_mma_kernel(const __nv_bfloat16* __restrict__ qh_g,
                      const __nv_bfloat16* __restrict__ ql_g,
                      const __nv_bfloat16* __restrict__ kh_g,
                      const __nv_bfloat16* __restrict__ kl_g,
                      const __nv_bfloat16* __restrict__ vh_g,
                      const __nv_bfloat16* __restrict__ vl_g,
                      __nv_bfloat16* __restrict__ ahi,
                      __nv_bfloat16* __restrict__ alo)
{
    extern __shared__ char smf[];
    const int tid = threadIdx.x, lane = tid & 31, wid = tid >> 5;
    const int qb = (int)gridDim.x - 1 - (int)blockIdx.x;
    const int h = blockIdx.y, b = blockIdx.z;
    const int q0 = qb * 64;
    const uint32_t sb = s2u(smf);
    const uint32_t qhS = sb, qlS = sb + QT_B;

    const size_t bh = (size_t)b * HH + h;
    const char* qhp = (const char*)(qh_g + (bh * SEQ + q0) * DH);
    const char* qlp = (const char*)(ql_g + (bh * SEQ + q0) * DH);
    const __nv_bfloat16* khp = kh_g + bh * SEQ * DH;
    const __nv_bfloat16* klp = kl_g + bh * SEQ * DH;
    const __nv_bfloat16* vhp = vh_g + bh * (size_t)DH * SEQ;
    const __nv_bfloat16* vlp = vl_g + bh * (size_t)DH * SEQ;

    #pragma unroll
    for (int u = 0; u < 4; u++) {
        int lin = tid + u * 128; int row = lin >> 3, seg = lin & 7;
        CP_ASYNC16(qhS + row * FRB + seg * 16, qhp + row * 128 + seg * 16);
        CP_ASYNC16(qlS + row * FRB + seg * 16, qlp + row * 128 + seg * 16);
    }
    CP_COMMIT();

    {
        uint32_t base = sb + 2 * QT_B;
        #pragma unroll
        for (int u = 0; u < 4; u++) {
            int lin = tid + u * 128; int row = lin >> 3, seg = lin & 7;
            size_t koff = (size_t)row * DH + seg * 8;
            CP_ASYNC16(base + 0 * QT_B + row * FRB + seg * 16, khp + koff);
            CP_ASYNC16(base + 1 * QT_B + row * FRB + seg * 16, klp + koff);
            size_t voff = (size_t)row * SEQ + seg * 8;
            CP_ASYNC16(base + 2 * QT_B + row * FRB + seg * 16, vhp + voff);
            CP_ASYNC16(base + 3 * QT_B + row * FRB + seg * 16, vlp + voff);
        }
        CP_COMMIT();
    }
    CP_WAIT(0);
    __syncthreads();

    const int qrow0 = wid * 16;
    uint32_t qah[4][4], qal[4][4];
    #pragma unroll
    for (int ks = 0; ks < 4; ks++) {
        uint32_t ah = qhS + (uint32_t)(qrow0 + (lane & 15)) * FRB + ks * 32 + (lane >> 4) * 16;
        uint32_t al = qlS + (uint32_t)(qrow0 + (lane & 15)) * FRB + ks * 32 + (lane >> 4) * 16;
        ldsm_x4(ah, qah[ks][0], qah[ks][1], qah[ks][2], qah[ks][3]);
        ldsm_x4(al, qal[ks][0], qal[ks][1], qal[ks][2], qal[ks][3]);
    }

    float Oa[8][4];
    #pragma unroll
    for (int nt = 0; nt < 8; nt++)
        #pragma unroll
        for (int f = 0; f < 4; f++) Oa[nt][f] = 0.0f;
    float mrow[2] = {0.0f, 0.0f};
    float lrow[2] = {1.0f, 1.0f};

    for (int jt = 0; jt <= qb; jt++) {
        const int s = jt & 1;
        if (jt < qb) {
            uint32_t base = sb + 2 * QT_B + (s ^ 1) * STG_B;
            const int j1 = (jt + 1) * 64;
            #pragma unroll
            for (int u = 0; u < 4; u++) {
                int lin = tid + u * 128; int row = lin >> 3, seg = lin & 7;
                size_t koff = (size_t)(j1 + row) * DH + seg * 8;
                CP_ASYNC16(base + 0 * QT_B + row * FRB + seg * 16, khp + koff);
                CP_ASYNC16(base + 1 * QT_B + row * FRB + seg * 16, klp + koff);
                size_t voff = (size_t)row * SEQ + j1 + seg * 8;
                CP_ASYNC16(base + 2 * QT_B + row * FRB + seg * 16, vhp + voff);
                CP_ASYNC16(base + 3 * QT_B + row * FRB + seg * 16, vlp + voff);
            }
            CP_COMMIT();
            CP_WAIT(1);
        } else {
            CP_WAIT(0);
        }
        __syncthreads();

        const uint32_t st = sb + 2 * QT_B + s * STG_B;
        const uint32_t khT = st, klT = st + QT_B, vhT = st + 2 * QT_B, vlT = st + 3 * QT_B;

        float S[8][4];
        #pragma unroll
        for (int nt = 0; nt < 8; nt++)
            #pragma unroll
            for (int f = 0; f < 4; f++) S[nt][f] = 0.0f;

        #pragma unroll
        for (int ks = 0; ks < 4; ks++) {
            uint32_t kh4[16], kl4[16];
            #pragma unroll
            for (int p = 0; p < 4; p++) {
                ldsm_b(khT, p * 16, ks * 32, lane, kh4 + p * 4);
                ldsm_b(klT, p * 16, ks * 32, lane, kl4 + p * 4);
            }
            #pragma unroll
            for (int nt = 0; nt < 8; nt++)
                mma16816(S[nt], qah[ks][0], qah[ks][1], qah[ks][2], qah[ks][3],
                         kh4[2 * nt], kh4[2 * nt + 1]);
            #pragma unroll
            for (int nt = 0; nt < 8; nt++)
                mma16816(S[nt], qah[ks][0], qah[ks][1], qah[ks][2], qah[ks][3],
                         kl4[2 * nt], kl4[2 * nt + 1]);
            #pragma unroll
            for (int nt = 0; nt < 8; nt++)
                mma16816(S[nt], qal[ks][0], qal[ks][1], qal[ks][2], qal[ks][3],
                         kh4[2 * nt], kh4[2 * nt + 1]);
        }

        if (jt == qb) {
            const int j0 = jt * 64;
            #pragma unroll
            for (int nt = 0; nt < 8; nt++) {
                #pragma unroll
                for (int e = 0; e < 4; e++) {
                    int grow = q0 + qrow0 + (lane >> 2) + ((e >= 2) ? 8 : 0);
                    int gcol = j0 + nt * 8 + (lane & 3) * 2 + (e & 1);
                    if (gcol > grow) S[nt][e] = -1e30f;
                }
            }
        }

        #pragma unroll
        for (int i = 0; i < 2; i++) {
            float rm = -1e30f;
            #pragma unroll
            for (int nt = 0; nt < 8; nt++)
                rm = fmaxf(rm, fmaxf(S[nt][2 * i], S[nt][2 * i + 1]));
            rm = fmaxf(rm, __shfl_xor_sync(0xffffffffu, rm, 1));
            rm = fmaxf(rm, __shfl_xor_sync(0xffffffffu, rm, 2));
            float mn = fmaxf(mrow[i], rm);
            float alpha = __expf(mrow[i] - mn);
            float rs = 0.0f;
            #pragma unroll
            for (int nt = 0; nt < 8; nt++) {
                float p0 = __expf(S[nt][2 * i]     - mn);
                float p1 = __expf(S[nt][2 * i + 1] - mn);
                S[nt][2 * i] = p0; S[nt][2 * i + 1] = p1;
                rs += p0 + p1;
            }
            rs += __shfl_xor_sync(0xffffffffu, rs, 1);
            rs += __shfl_xor_sync(0xffffffffu, rs, 2);
            lrow[i] = lrow[i] * alpha + rs;
            mrow[i] = mn;
            #pragma unroll
            for (int nt = 0; nt < 8; nt++) {
                Oa[nt][2 * i]     *= alpha;
                Oa[nt][2 * i + 1] *= alpha;
            }
        }

        #pragma unroll
        for (int ks = 0; ks < 4; ks++) {
            uint32_t ah0 = packbf(S[2 * ks][0],     S[2 * ks][1]);
            uint32_t ah1 = packbf(S[2 * ks][2],     S[2 * ks][3]);
            uint32_t ah2 = packbf(S[2 * ks + 1][0], S[2 * ks + 1][1]);
            uint32_t ah3 = packbf(S[2 * ks + 1][2], S[2 * ks + 1][3]);
            uint32_t al0 = packbf(lof(S[2 * ks][0]),     lof(S[2 * ks][1]));
            uint32_t al1 = packbf(lof(S[2 * ks][2]),     lof(S[2 * ks][3]));
            uint32_t al2 = packbf(lof(S[2 * ks + 1][0]), lof(S[2 * ks + 1][1]));
            uint32_t al3 = packbf(lof(S[2 * ks + 1][2]), lof(S[2 * ks + 1][3]));
            uint32_t vh4[16], vl4[16];
            #pragma unroll
            for (int p = 0; p < 4; p++) {
                ldsm_b(vhT, p * 16, ks * 32, lane, vh4 + p * 4);
                ldsm_b(vlT, p * 16, ks * 32, lane, vl4 + p * 4);
            }
            #pragma unroll
            for (int nt = 0; nt < 8; nt++)
                mma16816(Oa[nt], ah0, ah1, ah2, ah3, vh4[2 * nt], vh4[2 * nt + 1]);
            #pragma unroll
            for (int nt = 0; nt < 8; nt++)
                mma16816(Oa[nt], ah0, ah1, ah2, ah3, vl4[2 * nt], vl4[2 * nt + 1]);
            #pragma unroll
            for (int nt = 0; nt < 8; nt++)
                mma16816(Oa[nt], al0, al1, al2, al3, vh4[2 * nt], vh4[2 * nt + 1]);
        }
        __syncthreads();
    }

    const float inv0 = 1.0f / lrow[0];
    const float inv1 = 1.0f / lrow[1];
    const int r = lane >> 2, c2 = (lane & 3) * 2;
    const int srow0 = q0 + qrow0 + r;
    #pragma unroll
    for (int nt = 0; nt < 8; nt++) {
        int col = h * 64 + nt * 8 + c2;
        float o00 = Oa[nt][0] * inv0, o01 = Oa[nt][1] * inv0;
        float o10 = Oa[nt][2] * inv1, o11 = Oa[nt][3] * inv1;
        size_t off0 = ((size_t)srow0 * BB + b) * DD + col;
        size_t off1 = ((size_t)(srow0 + 8) * BB + b) * DD + col;
        *(uint32_t*)(ahi + off0) = packbf(o00, o01);
        *(uint32_t*)(ahi + off1) = packbf(o10, o11);
        *(uint32_t*)(alo + off0) = packbf(lof(o00), lof(o01));
        *(uint32_t*)(alo + off1) = packbf(lof(o10), lof(o11));
    }
}

// ---------------------------------------------------------------------------
extern "C" void kernel_launch(void* const* d_in, const int* in_sizes, int n_in,
                              void* d_out, int out_size)
{
    const float* x    = (const float*)d_in[0];
    const float* beta = (const float*)d_in[2];
    const float* Wq   = (const float*)d_in[3];
    const float* bq   = (const float*)d_in[4];
    const float* Wk   = (const float*)d_in[5];
    const float* bk   = (const float*)d_in[6];
    const float* Wv   = (const float*)d_in[7];
    const float* bv   = (const float*)d_in[8];
    const float* Wo   = (const float*)d_in[9];
    const float* bo   = (const float*)d_in[10];
    float* out = (float*)d_out;

    __nv_bfloat16 *xhi, *xlo, *qh, *ql, *kh, *kl, *vh, *vl, *ahi, *alo;
    cudaGetSymbolAddress((void**)&xhi, g_xhi);
    cudaGetSymbolAddress((void**)&xlo, g_xlo);
    cudaGetSymbolAddress((void**)&qh, g_qh);
    cudaGetSymbolAddress((void**)&ql, g_ql);
    cudaGetSymbolAddress((void**)&kh, g_kh);
    cudaGetSymbolAddress((void**)&kl, g_kl);
    cudaGetSymbolAddress((void**)&vh, g_vh);
    cudaGetSymbolAddress((void**)&vl, g_vl);
    cudaGetSymbolAddress((void**)&ahi, g_ahi);
    cudaGetSymbolAddress((void**)&alo, g_alo);

    cudaFuncSetAttribute(gemm_qkv_kernel,
                         cudaFuncAttributeMaxDynamicSharedMemorySize, GEMM_SMEM);
    cudaFuncSetAttribute(gemm_out_kernel,
                         cudaFuncAttributeMaxDynamicSharedMemorySize, GEMM_SMEM);
    cudaFuncSetAttribute(flash_mma_kernel,
                         cudaFuncAttributeMaxDynamicSharedMemorySize, FLASH_SMEM);

    const int nx4 = MM * DD / 4;
    const int nw4 = DD * DD / 4;

    split_kernel<<<(nx4 + 255) / 256, 256>>>(x, xhi, xlo, nx4);
    {
        dim3 sg((nw4 + 255) / 256, 4);
        split4_kernel<<<sg, 256>>>(Wq, Wk, Wv, Wo, nw4);
    }

    dim3 qkvgrid(DD / 64, MM / 128, 3);   // (16, 64, 3) fused Q/K/V
    gemm_qkv_kernel<<<qkvgrid, 256, GEMM_SMEM>>>(beta, bq, bk, bv);

    dim3 fgrid(SEQ / 64, HH, BB);   // (32, 16, 4)
    flash_mma_kernel<<<fgrid, 128, FLASH_SMEM>>>(qh, ql, kh, kl, vh, vl, ahi, alo);

    dim3 ogrid(DD / 64, MM / 128);   // (16, 64)
    gemm_out_kernel<<<ogrid, 256, GEMM_SMEM>>>(bo, out);
}

// round 9
// speedup vs baseline: 4.2185x; 1.5061x over previous
#include <cuda_runtime.h>
#include <cuda_fp16.h>
#include <stdint.h>
#include <math.h>

// Problem constants
#define SEQ 2048
#define BB  4
#define DD  1024
#define HH  16
#define DH  64
#define MM  (SEQ*BB)

// ---------------- scratch (device globals; allocation-free) ----------------
// x hi-only fp16; W split (scaled x64); q split (scaled x16 incl beta);
// k,v hi-only; att hi-only.
__device__ __half g_xh[MM*DD];
__device__ __half g_wqh[DD*DD], g_wql[DD*DD];
__device__ __half g_wkh[DD*DD], g_wkl[DD*DD];
__device__ __half g_wvh[DD*DD], g_wvl[DD*DD];
__device__ __half g_woh[DD*DD], g_wol[DD*DD];
__device__ __half g_qh[MM*DD], g_ql[MM*DD];
__device__ __half g_kh[MM*DD];
__device__ __half g_vh[MM*DD];   // transposed [b,h,dh,s]
__device__ __half g_ah[MM*DD];   // att output [s,b,D]

// ---------------- PTX helpers (baseline ISA only) ----------------
static __device__ __forceinline__ uint32_t s2u(const void* p) {
    return (uint32_t)__cvta_generic_to_shared(p);
}

#define CP_ASYNC16(saddr, gptr) \
    asm volatile("cp.async.cg.shared.global [%0], [%1], 16;" :: "r"(saddr), "l"(gptr))
#define CP_COMMIT() asm volatile("cp.async.commit_group;" ::: "memory")
#define CP_WAIT(n)  asm volatile("cp.async.wait_group %0;" :: "n"(n) : "memory")

static __device__ __forceinline__ void ldsm_x4(uint32_t addr,
    uint32_t &r0, uint32_t &r1, uint32_t &r2, uint32_t &r3)
{
    asm volatile("ldmatrix.sync.aligned.m8n8.x4.shared.b16 {%0,%1,%2,%3}, [%4];"
        : "=r"(r0), "=r"(r1), "=r"(r2), "=r"(r3) : "r"(addr));
}

static __device__ __forceinline__ void mma16816(float* d,
    uint32_t a0, uint32_t a1, uint32_t a2, uint32_t a3, uint32_t b0, uint32_t b1)
{
    asm volatile("mma.sync.aligned.m16n8k16.row.col.f32.f16.f16.f32 "
        "{%0,%1,%2,%3}, {%4,%5,%6,%7}, {%8,%9}, {%0,%1,%2,%3};"
        : "+f"(d[0]), "+f"(d[1]), "+f"(d[2]), "+f"(d[3])
        : "r"(a0), "r"(a1), "r"(a2), "r"(a3), "r"(b0), "r"(b1));
}

static __device__ __forceinline__ uint32_t packh(float x, float y) {
    __half2 t = __floats2half2_rn(x, y);
    return *(uint32_t*)&t;
}
static __device__ __forceinline__ float hof(float x) {
    return x - __half2float(__float2half_rn(x));
}

// ---------------- conversion kernels ----------------
// x -> fp16 hi only
__global__ void convx_kernel(const float* __restrict__ src,
                             __half* __restrict__ hi, int n4)
{
    int i = blockIdx.x * blockDim.x + threadIdx.x;
    if (i >= n4) return;
    float4 v = ((const float4*)src)[i];
    uint2 o;
    o.x = packh(v.x, v.y);
    o.y = packh(v.z, v.w);
    ((uint2*)hi)[i] = o;
}

// W*64 -> fp16 hi + lo  (4 weight tensors via blockIdx.y)
__global__ void split4_kernel(const float* __restrict__ s0, const float* __restrict__ s1,
                              const float* __restrict__ s2, const float* __restrict__ s3,
                              int n4)
{
    int i = blockIdx.x * blockDim.x + threadIdx.x;
    if (i >= n4) return;
    const float* src; __half *hi, *lo;
    switch (blockIdx.y) {
        case 0:  src = s0; hi = g_wqh; lo = g_wql; break;
        case 1:  src = s1; hi = g_wkh; lo = g_wkl; break;
        case 2:  src = s2; hi = g_wvh; lo = g_wvl; break;
        default: src = s3; hi = g_woh; lo = g_wol; break;
    }
    float4 v = ((const float4*)src)[i];
    float a = v.x * 64.0f, b = v.y * 64.0f, c = v.z * 64.0f, d = v.w * 64.0f;
    uint2 oh, ol;
    oh.x = packh(a, b); oh.y = packh(c, d);
    ol.x = packh(hof(a), hof(b)); ol.y = packh(hof(c), hof(d));
    ((uint2*)hi)[i] = oh;
    ((uint2*)lo)[i] = ol;
}

// ---------------------------------------------------------------------------
// HMMA GEMM body (2-pass fp16): C = A[M,K] @ (Bh+Bl)[N,K]^T (B pre-scaled x64)
// CTA tile 128(M)x64(N), 8 warps of 32x32. Result descaled by 1/64 + bias.
// mode 0: fp32 out [s,b,D]
// mode 1: q split hi/lo [b,h,s,dh], scaled by 2*exp(-beta)
// mode 2: hi-only transposed [b,h,dh,s]
// mode 3: hi-only [b,h,s,dh]
// ---------------------------------------------------------------------------
#define GBK 32
#define NCG (DD / GBK)
#define RSMEM 80
#define A_T 10240
#define B_T 5120
#define BUF_B (A_T + 2 * B_T)     // 20480
#define GEMM_SMEM (2 * BUF_B)     // 40960

static __device__ __forceinline__ void gemm_body(
    const __half* __restrict__ A,
    const __half* __restrict__ Bhi, const __half* __restrict__ Blo,
    const float* __restrict__ bias, int mode, const float* __restrict__ beta,
    float* __restrict__ C, __half* __restrict__ Oh, __half* __restrict__ Ol,
    int bn, int bm, char* smc)
{
    const int tid  = threadIdx.x;
    const int wid  = tid >> 5;
    const int lane = tid & 31;
    const uint32_t sb = s2u(smc);

    const int m0 = (wid >> 1) * 32;
    const int n0 = (wid & 1) * 32;

    const int lrow0 = tid >> 2;       // 0..63
    const int lseg  = tid & 3;

    {
        const __half* ga  = A   + (size_t)(bm + lrow0) * DD + lseg * 8;
        const __half* gb0 = Bhi + (size_t)(bn + lrow0) * DD + lseg * 8;
        const __half* gb1 = Blo + (size_t)(bn + lrow0) * DD + lseg * 8;
        uint32_t sa = sb + lrow0 * RSMEM + lseg * 16;
        CP_ASYNC16(sa,                 ga);
        CP_ASYNC16(sa + 64 * RSMEM,    ga + (size_t)64 * DD);
        CP_ASYNC16(sa + A_T,           gb0);
        CP_ASYNC16(sa + A_T + B_T,     gb1);
    }
    CP_COMMIT();

    float acc[2][4][4];
    #pragma unroll
    for (int mi = 0; mi < 2; mi++)
        #pragma unroll
        for (int ni = 0; ni < 4; ni++)
            #pragma unroll
            for (int f = 0; f < 4; f++) acc[mi][ni][f] = 0.0f;

    for (int c = 0; c < NCG; c++) {
        if (c + 1 < NCG) {
            const int k0 = (c + 1) * GBK;
            const uint32_t bufo = ((c + 1) & 1) * BUF_B;
            const __half* ga  = A   + (size_t)(bm + lrow0) * DD + k0 + lseg * 8;
            const __half* gb0 = Bhi + (size_t)(bn + lrow0) * DD + k0 + lseg * 8;
            const __half* gb1 = Blo + (size_t)(bn + lrow0) * DD + k0 + lseg * 8;
            uint32_t sa = sb + bufo + lrow0 * RSMEM + lseg * 16;
            CP_ASYNC16(sa,                 ga);
            CP_ASYNC16(sa + 64 * RSMEM,    ga + (size_t)64 * DD);
            CP_ASYNC16(sa + A_T,           gb0);
            CP_ASYNC16(sa + A_T + B_T,     gb1);
            CP_COMMIT();
            CP_WAIT(1);
        } else {
            CP_WAIT(0);
        }
        __syncthreads();

        const uint32_t bufo = (c & 1) * BUF_B;
        const uint32_t AT  = sb + bufo;
        const uint32_t BhT = AT + A_T;
        const uint32_t BlT = BhT + B_T;

        #pragma unroll
        for (int s = 0; s < 2; s++) {
            const uint32_t kb = s * 32;
            uint32_t bh[4][2], bl[4][2], ah[2][4];
            {
                int g = lane >> 3;
                int ntl = g >> 1, half = g & 1;
                uint32_t boff = (uint32_t)(n0 + ntl * 8 + (lane & 7)) * RSMEM
                              + kb + half * 16;
                ldsm_x4(BhT + boff,              bh[0][0], bh[0][1], bh[1][0], bh[1][1]);
                ldsm_x4(BhT + boff + 16 * RSMEM, bh[2][0], bh[2][1], bh[3][0], bh[3][1]);
                ldsm_x4(BlT + boff,              bl[0][0], bl[0][1], bl[1][0], bl[1][1]);
                ldsm_x4(BlT + boff + 16 * RSMEM, bl[2][0], bl[2][1], bl[3][0], bl[3][1]);
            }
            #pragma unroll
            for (int mi = 0; mi < 2; mi++) {
                uint32_t aoff = (uint32_t)(m0 + mi * 16 + (lane & 15)) * RSMEM
                              + kb + (lane >> 4) * 16;
                ldsm_x4(AT + aoff, ah[mi][0], ah[mi][1], ah[mi][2], ah[mi][3]);
            }
            #pragma unroll
            for (int mi = 0; mi < 2; mi++)
                #pragma unroll
                for (int ni = 0; ni < 4; ni++)
                    mma16816(acc[mi][ni], ah[mi][0], ah[mi][1], ah[mi][2], ah[mi][3],
                             bh[ni][0], bh[ni][1]);
            #pragma unroll
            for (int mi = 0; mi < 2; mi++)
                #pragma unroll
                for (int ni = 0; ni < 4; ni++)
                    mma16816(acc[mi][ni], ah[mi][0], ah[mi][1], ah[mi][2], ah[mi][3],
                             bl[ni][0], bl[ni][1]);
        }
        __syncthreads();
    }

    const float DS = 1.0f / 64.0f;   // undo W x64 scaling
    const int erow = lane >> 2;
    const int ecol = (lane & 3) * 2;
    #pragma unroll
    for (int mi = 0; mi < 2; mi++) {
        #pragma unroll
        for (int ni = 0; ni < 4; ni++) {
            int gr = bm + m0 + mi * 16 + erow;
            int gc = bn + n0 + ni * 8 + ecol;
            float v0x = acc[mi][ni][0] * DS + bias[gc];
            float v0y = acc[mi][ni][1] * DS + bias[gc + 1];
            float v1x = acc[mi][ni][2] * DS + bias[gc];
            float v1y = acc[mi][ni][3] * DS + bias[gc + 1];
            if (mode == 0) {
                float2 a = {v0x, v0y}, bb2 = {v1x, v1y};
                *(float2*)(C + (size_t)gr * DD + gc)       = a;
                *(float2*)(C + (size_t)(gr + 8) * DD + gc) = bb2;
            } else {
                int hh = gc >> 6, dh = gc & 63;
                int s0 = gr >> 2, bbi = gr & 3;   // rows gr, gr+8 -> s0, s0+2
                if (mode == 1) {
                    // q: scale by 2*exp(-beta) (= 16 / (8 e^beta)), split hi/lo
                    float f = 2.0f * __expf(-beta[hh]);
                    v0x *= f; v0y *= f; v1x *= f; v1y *= f;
                    size_t off0 = (((size_t)bbi * HH + hh) * SEQ + s0) * DH + dh;
                    size_t off1 = off0 + 2 * DH;
                    *(uint32_t*)(Oh + off0) = packh(v0x, v0y);
                    *(uint32_t*)(Oh + off1) = packh(v1x, v1y);
                    *(uint32_t*)(Ol + off0) = packh(hof(v0x), hof(v0y));
                    *(uint32_t*)(Ol + off1) = packh(hof(v1x), hof(v1y));
                } else if (mode == 3) {
                    size_t off0 = (((size_t)bbi * HH + hh) * SEQ + s0) * DH + dh;
                    size_t off1 = off0 + 2 * DH;
                    *(uint32_t*)(Oh + off0) = packh(v0x, v0y);
                    *(uint32_t*)(Oh + off1) = packh(v1x, v1y);
                } else {
                    size_t off = (((size_t)bbi * HH + hh) * DH + dh) * SEQ + s0;
                    Oh[off]           = __float2half_rn(v0x);
                    Oh[off + SEQ]     = __float2half_rn(v0y);
                    Oh[off + 2]       = __float2half_rn(v1x);
                    Oh[off + SEQ + 2] = __float2half_rn(v1y);
                }
            }
        }
    }
}

__global__ __launch_bounds__(256, 3)
void gemm_qkv_kernel(const float* __restrict__ beta,
                     const float* __restrict__ bq,
                     const float* __restrict__ bk,
                     const float* __restrict__ bv)
{
    extern __shared__ char smc[];
    const int bn = blockIdx.x * 64;
    const int bm = blockIdx.y * 128;
    if (blockIdx.z == 0)
        gemm_body(g_xh, g_wqh, g_wql, bq, 1, beta, nullptr, g_qh, g_ql, bn, bm, smc);
    else if (blockIdx.z == 1)
        gemm_body(g_xh, g_wkh, g_wkl, bk, 3, nullptr, nullptr, g_kh, nullptr, bn, bm, smc);
    else
        gemm_body(g_xh, g_wvh, g_wvl, bv, 2, nullptr, nullptr, g_vh, nullptr, bn, bm, smc);
}

__global__ __launch_bounds__(256, 3)
void gemm_out_kernel(const float* __restrict__ bo, float* __restrict__ out)
{
    extern __shared__ char smc[];
    const int bn = blockIdx.x * 64;
    const int bm = blockIdx.y * 128;
    gemm_body(g_ah, g_woh, g_wol, bo, 0, nullptr, out, nullptr, nullptr, bn, bm, smc);
}

// ---------------------------------------------------------------------------
// Flash attention, fp16 2-pass: S = (Qh+Ql)Kh^T (x16 scaled), O = (Ph+Pl)Vh
// (P x256 scaled). Block 128 thr / 4 warps, 64 Q rows, LPT order.
// smem: Qh,Ql + 2 stages x (Kh,Vh) = 54 KB -> 3 CTAs/SM.
// ---------------------------------------------------------------------------
#define FRB 144
#define QT_B (64 * FRB)            // 9216
#define STG_B (2 * QT_B)           // 18432
#define FLASH_SMEM (2 * QT_B + 2 * STG_B)   // 55296

static __device__ __forceinline__ void ldsm_b(uint32_t tile, int nbase, int ksb,
                                              int lane, uint32_t* r4)
{
    int g = lane >> 3, ntl = g >> 1, half = g & 1;
    uint32_t addr = tile + (uint32_t)(nbase + ntl * 8 + (lane & 7)) * FRB
                  + ksb + half * 16;
    ldsm_x4(addr, r4[0], r4[1], r4[2], r4[3]);
}

__global__ __launch_bounds__(128, 3)
void flash_mma_kernel(const __half* __restrict__ qh_g,
                      const __half* __restrict__ ql_g,
                      const __half* __restrict__ kh_g,
                      const __half* __restrict__ vh_g,
                      __half* __restrict__ ah_g)
{
    extern __shared__ char smf[];
    const int tid = threadIdx.x, lane = tid & 31, wid = tid >> 5;
    const int qb = (int)gridDim.x - 1 - (int)blockIdx.x;
    const int h = blockIdx.y, b = blockIdx.z;
    const int q0 = qb * 64;
    const uint32_t sb = s2u(smf);
    const uint32_t qhS = sb, qlS = sb + QT_B;

    const size_t bh = (size_t)b * HH + h;
    const char* qhp = (const char*)(qh_g + (bh * SEQ + q0) * DH);
    const char* qlp = (const char*)(ql_g + (bh * SEQ + q0) * DH);
    const __half* khp = kh_g + bh * SEQ * DH;
    const __half* vhp = vh_g + bh * (size_t)DH * SEQ;

    // Q tiles (8 asyncs/thread)
    #pragma unroll
    for (int u = 0; u < 4; u++) {
        int lin = tid + u * 128; int row = lin >> 3, seg = lin & 7;
        CP_ASYNC16(qhS + row * FRB + seg * 16, qhp + row * 128 + seg * 16);
        CP_ASYNC16(qlS + row * FRB + seg * 16, qlp + row * 128 + seg * 16);
    }
    CP_COMMIT();

    // stage 0 prefetch (Kh, Vh)
    {
        uint32_t base = sb + 2 * QT_B;
        #pragma unroll
        for (int u = 0; u < 4; u++) {
            int lin = tid + u * 128; int row = lin >> 3, seg = lin & 7;
            CP_ASYNC16(base + row * FRB + seg * 16, khp + (size_t)row * DH + seg * 8);
            CP_ASYNC16(base + QT_B + row * FRB + seg * 16, vhp + (size_t)row * SEQ + seg * 8);
        }
        CP_COMMIT();
    }
    CP_WAIT(0);
    __syncthreads();

    const int qrow0 = wid * 16;
    uint32_t qah[4][4], qal[4][4];
    #pragma unroll
    for (int ks = 0; ks < 4; ks++) {
        uint32_t ah = qhS + (uint32_t)(qrow0 + (lane & 15)) * FRB + ks * 32 + (lane >> 4) * 16;
        uint32_t al = qlS + (uint32_t)(qrow0 + (lane & 15)) * FRB + ks * 32 + (lane >> 4) * 16;
        ldsm_x4(ah, qah[ks][0], qah[ks][1], qah[ks][2], qah[ks][3]);
        ldsm_x4(al, qal[ks][0], qal[ks][1], qal[ks][2], qal[ks][3]);
    }

    float Oa[8][4];
    #pragma unroll
    for (int nt = 0; nt < 8; nt++)
        #pragma unroll
        for (int f = 0; f < 4; f++) Oa[nt][f] = 0.0f;
    float mrow[2] = {0.0f, 0.0f};   // sink score 0
    float lrow[2] = {1.0f, 1.0f};   // sink exp(0-0)

    for (int jt = 0; jt <= qb; jt++) {
        const int s = jt & 1;
        if (jt < qb) {
            uint32_t base = sb + 2 * QT_B + (s ^ 1) * STG_B;
            const int j1 = (jt + 1) * 64;
            #pragma unroll
            for (int u = 0; u < 4; u++) {
                int lin = tid + u * 128; int row = lin >> 3, seg = lin & 7;
                CP_ASYNC16(base + row * FRB + seg * 16,
                           khp + (size_t)(j1 + row) * DH + seg * 8);
                CP_ASYNC16(base + QT_B + row * FRB + seg * 16,
                           vhp + (size_t)row * SEQ + j1 + seg * 8);
            }
            CP_COMMIT();
            CP_WAIT(1);
        } else {
            CP_WAIT(0);
        }
        __syncthreads();

        const uint32_t st = sb + 2 * QT_B + s * STG_B;
        const uint32_t khT = st, vhT = st + QT_B;

        // ---- S = Q Kh^T (2-pass: Qh, Ql) ----
        float S[8][4];
        #pragma unroll
        for (int nt = 0; nt < 8; nt++)
            #pragma unroll
            for (int f = 0; f < 4; f++) S[nt][f] = 0.0f;

        #pragma unroll
        for (int ks = 0; ks < 4; ks++) {
            uint32_t kh4[16];
            #pragma unroll
            for (int p = 0; p < 4; p++)
                ldsm_b(khT, p * 16, ks * 32, lane, kh4 + p * 4);
            #pragma unroll
            for (int nt = 0; nt < 8; nt++)
                mma16816(S[nt], qah[ks][0], qah[ks][1], qah[ks][2], qah[ks][3],
                         kh4[2 * nt], kh4[2 * nt + 1]);
            #pragma unroll
            for (int nt = 0; nt < 8; nt++)
                mma16816(S[nt], qal[ks][0], qal[ks][1], qal[ks][2], qal[ks][3],
                         kh4[2 * nt], kh4[2 * nt + 1]);
        }

        // descale x16 and causal mask
        #pragma unroll
        for (int nt = 0; nt < 8; nt++)
            #pragma unroll
            for (int e = 0; e < 4; e++) S[nt][e] *= 0.0625f;
        if (jt == qb) {
            const int j0 = jt * 64;
            #pragma unroll
            for (int nt = 0; nt < 8; nt++) {
                #pragma unroll
                for (int e = 0; e < 4; e++) {
                    int grow = q0 + qrow0 + (lane >> 2) + ((e >= 2) ? 8 : 0);
                    int gcol = j0 + nt * 8 + (lane & 3) * 2 + (e & 1);
                    if (gcol > grow) S[nt][e] = -1e30f;
                }
            }
        }

        // ---- online softmax ----
        #pragma unroll
        for (int i = 0; i < 2; i++) {
            float rm = -1e30f;
            #pragma unroll
            for (int nt = 0; nt < 8; nt++)
                rm = fmaxf(rm, fmaxf(S[nt][2 * i], S[nt][2 * i + 1]));
            rm = fmaxf(rm, __shfl_xor_sync(0xffffffffu, rm, 1));
            rm = fmaxf(rm, __shfl_xor_sync(0xffffffffu, rm, 2));
            float mn = fmaxf(mrow[i], rm);
            float alpha = __expf(mrow[i] - mn);
            float rs = 0.0f;
            #pragma unroll
            for (int nt = 0; nt < 8; nt++) {
                float p0 = __expf(S[nt][2 * i]     - mn);
                float p1 = __expf(S[nt][2 * i + 1] - mn);
                S[nt][2 * i] = p0; S[nt][2 * i + 1] = p1;
                rs += p0 + p1;
            }
            rs += __shfl_xor_sync(0xffffffffu, rs, 1);
            rs += __shfl_xor_sync(0xffffffffu, rs, 2);
            lrow[i] = lrow[i] * alpha + rs;
            mrow[i] = mn;
            #pragma unroll
            for (int nt = 0; nt < 8; nt++) {
                Oa[nt][2 * i]     *= alpha;
                Oa[nt][2 * i + 1] *= alpha;
            }
        }

        // ---- O += P Vh (2-pass: Ph, Pl; P scaled x256) ----
        #pragma unroll
        for (int ks = 0; ks < 4; ks++) {
            float p00 = S[2 * ks][0] * 256.0f,     p01 = S[2 * ks][1] * 256.0f;
            float p02 = S[2 * ks][2] * 256.0f,     p03 = S[2 * ks][3] * 256.0f;
            float p10 = S[2 * ks + 1][0] * 256.0f, p11 = S[2 * ks + 1][1] * 256.0f;
            float p12 = S[2 * ks + 1][2] * 256.0f, p13 = S[2 * ks + 1][3] * 256.0f;
            uint32_t ah0 = packh(p00, p01), ah1 = packh(p02, p03);
            uint32_t ah2 = packh(p10, p11), ah3 = packh(p12, p13);
            uint32_t al0 = packh(hof(p00), hof(p01)), al1 = packh(hof(p02), hof(p03));
            uint32_t al2 = packh(hof(p10), hof(p11)), al3 = packh(hof(p12), hof(p13));
            uint32_t vh4[16];
            #pragma unroll
            for (int p = 0; p < 4; p++)
                ldsm_b(vhT, p * 16, ks * 32, lane, vh4 + p * 4);
            #pragma unroll
            for (int nt = 0; nt < 8; nt++)
                mma16816(Oa[nt], ah0, ah1, ah2, ah3, vh4[2 * nt], vh4[2 * nt + 1]);
            #pragma unroll
            for (int nt = 0; nt < 8; nt++)
                mma16816(Oa[nt], al0, al1, al2, al3, vh4[2 * nt], vh4[2 * nt + 1]);
        }
        __syncthreads();
    }

    // ---- epilogue: normalize (incl 1/256), store att hi fp16 [s,b,D] ----
    const float inv0 = 1.0f / (256.0f * lrow[0]);
    const float inv1 = 1.0f / (256.0f * lrow[1]);
    const int r = lane >> 2, c2 = (lane & 3) * 2;
    const int srow0 = q0 + qrow0 + r;
    #pragma unroll
    for (int nt = 0; nt < 8; nt++) {
        int col = h * 64 + nt * 8 + c2;
        float o00 = Oa[nt][0] * inv0, o01 = Oa[nt][1] * inv0;
        float o10 = Oa[nt][2] * inv1, o11 = Oa[nt][3] * inv1;
        size_t off0 = ((size_t)srow0 * BB + b) * DD + col;
        size_t off1 = ((size_t)(srow0 + 8) * BB + b) * DD + col;
        *(uint32_t*)(ah_g + off0) = packh(o00, o01);
        *(uint32_t*)(ah_g + off1) = packh(o10, o11);
    }
}

// ---------------------------------------------------------------------------
extern "C" void kernel_launch(void* const* d_in, const int* in_sizes, int n_in,
                              void* d_out, int out_size)
{
    const float* x    = (const float*)d_in[0];
    const float* beta = (const float*)d_in[2];
    const float* Wq   = (const float*)d_in[3];
    const float* bq   = (const float*)d_in[4];
    const float* Wk   = (const float*)d_in[5];
    const float* bk   = (const float*)d_in[6];
    const float* Wv   = (const float*)d_in[7];
    const float* bv   = (const float*)d_in[8];
    const float* Wo   = (const float*)d_in[9];
    const float* bo   = (const float*)d_in[10];
    float* out = (float*)d_out;

    __half *xh, *qh, *ql, *kh, *vh, *ah;
    cudaGetSymbolAddress((void**)&xh, g_xh);
    cudaGetSymbolAddress((void**)&qh, g_qh);
    cudaGetSymbolAddress((void**)&ql, g_ql);
    cudaGetSymbolAddress((void**)&kh, g_kh);
    cudaGetSymbolAddress((void**)&vh, g_vh);
    cudaGetSymbolAddress((void**)&ah, g_ah);

    cudaFuncSetAttribute(gemm_qkv_kernel,
                         cudaFuncAttributeMaxDynamicSharedMemorySize, GEMM_SMEM);
    cudaFuncSetAttribute(gemm_out_kernel,
                         cudaFuncAttributeMaxDynamicSharedMemorySize, GEMM_SMEM);
    cudaFuncSetAttribute(flash_mma_kernel,
                         cudaFuncAttributeMaxDynamicSharedMemorySize, FLASH_SMEM);

    const int nx4 = MM * DD / 4;
    const int nw4 = DD * DD / 4;

    convx_kernel<<<(nx4 + 255) / 256, 256>>>(x, xh, nx4);
    {
        dim3 sg((nw4 + 255) / 256, 4);
        split4_kernel<<<sg, 256>>>(Wq, Wk, Wv, Wo, nw4);
    }

    dim3 qkvgrid(DD / 64, MM / 128, 3);   // (16, 64, 3)
    gemm_qkv_kernel<<<qkvgrid, 256, GEMM_SMEM>>>(beta, bq, bk, bv);

    dim3 fgrid(SEQ / 64, HH, BB);   // (32, 16, 4)
    flash_mma_kernel<<<fgrid, 128, FLASH_SMEM>>>(qh, ql, kh, vh, ah);

    dim3 ogrid(DD / 64, MM / 128);   // (16, 64)
    gemm_out_kernel<<<ogrid, 256, GEMM_SMEM>>>(bo, out);
}

// round 10
// speedup vs baseline: 5.0199x; 1.1900x over previous
#include <cuda_runtime.h>
#include <cuda_fp16.h>
#include <stdint.h>
#include <math.h>

// Problem constants
#define SEQ 2048
#define BB  4
#define DD  1024
#define HH  16
#define DH  64
#define MM  (SEQ*BB)

// ---------------- scratch (device globals; allocation-free) ----------------
__device__ __half g_xh[MM*DD];
__device__ __half g_wqh[DD*DD], g_wql[DD*DD];
__device__ __half g_wkh[DD*DD], g_wkl[DD*DD];
__device__ __half g_wvh[DD*DD];
__device__ __half g_woh[DD*DD], g_wol[DD*DD];
__device__ __half g_qh[MM*DD];   // scaled x16 incl beta, [b,h,s,dh]
__device__ __half g_kh[MM*DD];   // [b,h,s,dh]
__device__ __half g_vh[MM*DD];   // transposed [b,h,dh,s]
__device__ __half g_ah[MM*DD];   // att output [s,b,D]

// ---------------- PTX helpers (baseline ISA only) ----------------
static __device__ __forceinline__ uint32_t s2u(const void* p) {
    return (uint32_t)__cvta_generic_to_shared(p);
}

#define CP_ASYNC16(saddr, gptr) \
    asm volatile("cp.async.cg.shared.global [%0], [%1], 16;" :: "r"(saddr), "l"(gptr))
#define CP_COMMIT() asm volatile("cp.async.commit_group;" ::: "memory")
#define CP_WAIT(n)  asm volatile("cp.async.wait_group %0;" :: "n"(n) : "memory")

static __device__ __forceinline__ void ldsm_x4(uint32_t addr,
    uint32_t &r0, uint32_t &r1, uint32_t &r2, uint32_t &r3)
{
    asm volatile("ldmatrix.sync.aligned.m8n8.x4.shared.b16 {%0,%1,%2,%3}, [%4];"
        : "=r"(r0), "=r"(r1), "=r"(r2), "=r"(r3) : "r"(addr));
}

static __device__ __forceinline__ void mma16816(float* d,
    uint32_t a0, uint32_t a1, uint32_t a2, uint32_t a3, uint32_t b0, uint32_t b1)
{
    asm volatile("mma.sync.aligned.m16n8k16.row.col.f32.f16.f16.f32 "
        "{%0,%1,%2,%3}, {%4,%5,%6,%7}, {%8,%9}, {%0,%1,%2,%3};"
        : "+f"(d[0]), "+f"(d[1]), "+f"(d[2]), "+f"(d[3])
        : "r"(a0), "r"(a1), "r"(a2), "r"(a3), "r"(b0), "r"(b1));
}

static __device__ __forceinline__ uint32_t packh(float x, float y) {
    __half2 t = __floats2half2_rn(x, y);
    return *(uint32_t*)&t;
}
static __device__ __forceinline__ float hof(float x) {
    return x - __half2float(__float2half_rn(x));
}

// ---------------- conversion kernels ----------------
__global__ void convx_kernel(const float* __restrict__ src,
                             __half* __restrict__ hi, int n4)
{
    int i = blockIdx.x * blockDim.x + threadIdx.x;
    if (i >= n4) return;
    float4 v = ((const float4*)src)[i];
    uint2 o;
    o.x = packh(v.x, v.y);
    o.y = packh(v.z, v.w);
    ((uint2*)hi)[i] = o;
}

// W*64 -> fp16 hi (+ lo for Q,K,O; V is hi-only)
__global__ void split4_kernel(const float* __restrict__ s0, const float* __restrict__ s1,
                              const float* __restrict__ s2, const float* __restrict__ s3,
                              int n4)
{
    int i = blockIdx.x * blockDim.x + threadIdx.x;
    if (i >= n4) return;
    const float* src; __half *hi, *lo;
    switch (blockIdx.y) {
        case 0:  src = s0; hi = g_wqh; lo = g_wql; break;
        case 1:  src = s1; hi = g_wkh; lo = g_wkl; break;
        case 2:  src = s2; hi = g_wvh; lo = nullptr; break;
        default: src = s3; hi = g_woh; lo = g_wol; break;
    }
    float4 v = ((const float4*)src)[i];
    float a = v.x * 64.0f, b = v.y * 64.0f, c = v.z * 64.0f, d = v.w * 64.0f;
    uint2 oh;
    oh.x = packh(a, b); oh.y = packh(c, d);
    ((uint2*)hi)[i] = oh;
    if (lo) {
        uint2 ol;
        ol.x = packh(hof(a), hof(b)); ol.y = packh(hof(c), hof(d));
        ((uint2*)lo)[i] = ol;
    }
}

// ---------------------------------------------------------------------------
// HMMA GEMM body: C = A[M,K] @ (Bh[+Bl])[N,K]^T (B pre-scaled x64), npass 1|2.
// CTA tile 128(M)x64(N), 8 warps of 32x32. Descale 1/64 + bias in epilogue.
// mode 0: fp32 out [s,b,D]
// mode 1: fp16 hi out [b,h,s,dh], scaled by 2*exp(-beta_h)
// mode 2: fp16 hi out transposed [b,h,dh,s]
// mode 3: fp16 hi out [b,h,s,dh]
// ---------------------------------------------------------------------------
#define GBK 32
#define NCG (DD / GBK)
#define RSMEM 80
#define A_T 10240
#define B_T 5120
#define BUF_B (A_T + 2 * B_T)     // 20480
#define GEMM_SMEM (2 * BUF_B)     // 40960

static __device__ __forceinline__ void gemm_body(
    const __half* __restrict__ A,
    const __half* __restrict__ Bhi, const __half* __restrict__ Blo,
    const float* __restrict__ bias, int mode, int npass,
    const float* __restrict__ beta,
    float* __restrict__ C, __half* __restrict__ Oh,
    int bn, int bm, char* smc)
{
    const int tid  = threadIdx.x;
    const int wid  = tid >> 5;
    const int lane = tid & 31;
    const uint32_t sb = s2u(smc);

    const int m0 = (wid >> 1) * 32;
    const int n0 = (wid & 1) * 32;

    const int lrow0 = tid >> 2;
    const int lseg  = tid & 3;

    {
        const __half* ga  = A   + (size_t)(bm + lrow0) * DD + lseg * 8;
        const __half* gb0 = Bhi + (size_t)(bn + lrow0) * DD + lseg * 8;
        uint32_t sa = sb + lrow0 * RSMEM + lseg * 16;
        CP_ASYNC16(sa,                 ga);
        CP_ASYNC16(sa + 64 * RSMEM,    ga + (size_t)64 * DD);
        CP_ASYNC16(sa + A_T,           gb0);
        if (npass == 2) {
            const __half* gb1 = Blo + (size_t)(bn + lrow0) * DD + lseg * 8;
            CP_ASYNC16(sa + A_T + B_T, gb1);
        }
    }
    CP_COMMIT();

    float acc[2][4][4];
    #pragma unroll
    for (int mi = 0; mi < 2; mi++)
        #pragma unroll
        for (int ni = 0; ni < 4; ni++)
            #pragma unroll
            for (int f = 0; f < 4; f++) acc[mi][ni][f] = 0.0f;

    for (int c = 0; c < NCG; c++) {
        if (c + 1 < NCG) {
            const int k0 = (c + 1) * GBK;
            const uint32_t bufo = ((c + 1) & 1) * BUF_B;
            const __half* ga  = A   + (size_t)(bm + lrow0) * DD + k0 + lseg * 8;
            const __half* gb0 = Bhi + (size_t)(bn + lrow0) * DD + k0 + lseg * 8;
            uint32_t sa = sb + bufo + lrow0 * RSMEM + lseg * 16;
            CP_ASYNC16(sa,                 ga);
            CP_ASYNC16(sa + 64 * RSMEM,    ga + (size_t)64 * DD);
            CP_ASYNC16(sa + A_T,           gb0);
            if (npass == 2) {
                const __half* gb1 = Blo + (size_t)(bn + lrow0) * DD + k0 + lseg * 8;
                CP_ASYNC16(sa + A_T + B_T, gb1);
            }
            CP_COMMIT();
            CP_WAIT(1);
        } else {
            CP_WAIT(0);
        }
        __syncthreads();

        const uint32_t bufo = (c & 1) * BUF_B;
        const uint32_t AT  = sb + bufo;
        const uint32_t BhT = AT + A_T;
        const uint32_t BlT = BhT + B_T;

        #pragma unroll
        for (int s = 0; s < 2; s++) {
            const uint32_t kb = s * 32;
            uint32_t bh[4][2], bl[4][2], ah[2][4];
            {
                int g = lane >> 3;
                int ntl = g >> 1, half = g & 1;
                uint32_t boff = (uint32_t)(n0 + ntl * 8 + (lane & 7)) * RSMEM
                              + kb + half * 16;
                ldsm_x4(BhT + boff,              bh[0][0], bh[0][1], bh[1][0], bh[1][1]);
                ldsm_x4(BhT + boff + 16 * RSMEM, bh[2][0], bh[2][1], bh[3][0], bh[3][1]);
                if (npass == 2) {
                    ldsm_x4(BlT + boff,              bl[0][0], bl[0][1], bl[1][0], bl[1][1]);
                    ldsm_x4(BlT + boff + 16 * RSMEM, bl[2][0], bl[2][1], bl[3][0], bl[3][1]);
                }
            }
            #pragma unroll
            for (int mi = 0; mi < 2; mi++) {
                uint32_t aoff = (uint32_t)(m0 + mi * 16 + (lane & 15)) * RSMEM
                              + kb + (lane >> 4) * 16;
                ldsm_x4(AT + aoff, ah[mi][0], ah[mi][1], ah[mi][2], ah[mi][3]);
            }
            #pragma unroll
            for (int mi = 0; mi < 2; mi++)
                #pragma unroll
                for (int ni = 0; ni < 4; ni++)
                    mma16816(acc[mi][ni], ah[mi][0], ah[mi][1], ah[mi][2], ah[mi][3],
                             bh[ni][0], bh[ni][1]);
            if (npass == 2) {
                #pragma unroll
                for (int mi = 0; mi < 2; mi++)
                    #pragma unroll
                    for (int ni = 0; ni < 4; ni++)
                        mma16816(acc[mi][ni], ah[mi][0], ah[mi][1], ah[mi][2], ah[mi][3],
                                 bl[ni][0], bl[ni][1]);
            }
        }
        __syncthreads();
    }

    const float DS = 1.0f / 64.0f;
    const int erow = lane >> 2;
    const int ecol = (lane & 3) * 2;
    #pragma unroll
    for (int mi = 0; mi < 2; mi++) {
        #pragma unroll
        for (int ni = 0; ni < 4; ni++) {
            int gr = bm + m0 + mi * 16 + erow;
            int gc = bn + n0 + ni * 8 + ecol;
            float v0x = acc[mi][ni][0] * DS + bias[gc];
            float v0y = acc[mi][ni][1] * DS + bias[gc + 1];
            float v1x = acc[mi][ni][2] * DS + bias[gc];
            float v1y = acc[mi][ni][3] * DS + bias[gc + 1];
            if (mode == 0) {
                float2 a = {v0x, v0y}, bb2 = {v1x, v1y};
                *(float2*)(C + (size_t)gr * DD + gc)       = a;
                *(float2*)(C + (size_t)(gr + 8) * DD + gc) = bb2;
            } else {
                int hh = gc >> 6, dh = gc & 63;
                int s0 = gr >> 2, bbi = gr & 3;
                if (mode == 1 || mode == 3) {
                    if (mode == 1) {
                        float f = 2.0f * __expf(-beta[hh]);
                        v0x *= f; v0y *= f; v1x *= f; v1y *= f;
                    }
                    size_t off0 = (((size_t)bbi * HH + hh) * SEQ + s0) * DH + dh;
                    size_t off1 = off0 + 2 * DH;
                    *(uint32_t*)(Oh + off0) = packh(v0x, v0y);
                    *(uint32_t*)(Oh + off1) = packh(v1x, v1y);
                } else {
                    size_t off = (((size_t)bbi * HH + hh) * DH + dh) * SEQ + s0;
                    Oh[off]           = __float2half_rn(v0x);
                    Oh[off + SEQ]     = __float2half_rn(v0y);
                    Oh[off + 2]       = __float2half_rn(v1x);
                    Oh[off + SEQ + 2] = __float2half_rn(v1y);
                }
            }
        }
    }
}

__global__ __launch_bounds__(256, 3)
void gemm_qkv_kernel(const float* __restrict__ beta,
                     const float* __restrict__ bq,
                     const float* __restrict__ bk,
                     const float* __restrict__ bv)
{
    extern __shared__ char smc[];
    const int bn = blockIdx.x * 64;
    const int bm = blockIdx.y * 128;
    if (blockIdx.z == 0)
        gemm_body(g_xh, g_wqh, g_wql, bq, 1, 2, beta, nullptr, g_qh, bn, bm, smc);
    else if (blockIdx.z == 1)
        gemm_body(g_xh, g_wkh, g_wkl, bk, 3, 2, nullptr, nullptr, g_kh, bn, bm, smc);
    else
        gemm_body(g_xh, g_wvh, nullptr, bv, 2, 1, nullptr, nullptr, g_vh, bn, bm, smc);
}

__global__ __launch_bounds__(256, 3)
void gemm_out_kernel(const float* __restrict__ bo, float* __restrict__ out)
{
    extern __shared__ char smc[];
    const int bn = blockIdx.x * 64;
    const int bm = blockIdx.y * 128;
    gemm_body(g_ah, g_woh, g_wol, bo, 0, 2, nullptr, out, nullptr, bn, bm, smc);
}

// ---------------------------------------------------------------------------
// Flash attention, fp16 1-pass each GEMM: S = Qh Kh^T (x16), O = Ph Vh (x256).
// Block 128 thr / 4 warps, 64 Q rows, LPT order.
// smem: Qh + 2 stages x (Kh,Vh) = 45 KB.
// ---------------------------------------------------------------------------
#define FRB 144
#define QT_B (64 * FRB)            // 9216
#define STG_B (2 * QT_B)           // 18432
#define FLASH_SMEM (QT_B + 2 * STG_B)   // 46080

static __device__ __forceinline__ void ldsm_b(uint32_t tile, int nbase, int ksb,
                                              int lane, uint32_t* r4)
{
    int g = lane >> 3, ntl = g >> 1, half = g & 1;
    uint32_t addr = tile + (uint32_t)(nbase + ntl * 8 + (lane & 7)) * FRB
                  + ksb + half * 16;
    ldsm_x4(addr, r4[0], r4[1], r4[2], r4[3]);
}

__global__ __launch_bounds__(128, 3)
void flash_mma_kernel(const __half* __restrict__ qh_g,
                      const __half* __restrict__ kh_g,
                      const __half* __restrict__ vh_g,
                      __half* __restrict__ ah_g)
{
    extern __shared__ char smf[];
    const int tid = threadIdx.x, lane = tid & 31, wid = tid >> 5;
    const int qb = (int)gridDim.x - 1 - (int)blockIdx.x;
    const int h = blockIdx.y, b = blockIdx.z;
    const int q0 = qb * 64;
    const uint32_t sb = s2u(smf);
    const uint32_t qhS = sb;

    const size_t bh = (size_t)b * HH + h;
    const char* qhp = (const char*)(qh_g + (bh * SEQ + q0) * DH);
    const __half* khp = kh_g + bh * SEQ * DH;
    const __half* vhp = vh_g + bh * (size_t)DH * SEQ;

    #pragma unroll
    for (int u = 0; u < 4; u++) {
        int lin = tid + u * 128; int row = lin >> 3, seg = lin & 7;
        CP_ASYNC16(qhS + row * FRB + seg * 16, qhp + row * 128 + seg * 16);
    }
    CP_COMMIT();

    {
        uint32_t base = sb + QT_B;
        #pragma unroll
        for (int u = 0; u < 4; u++) {
            int lin = tid + u * 128; int row = lin >> 3, seg = lin & 7;
            CP_ASYNC16(base + row * FRB + seg * 16, khp + (size_t)row * DH + seg * 8);
            CP_ASYNC16(base + QT_B + row * FRB + seg * 16, vhp + (size_t)row * SEQ + seg * 8);
        }
        CP_COMMIT();
    }
    CP_WAIT(0);
    __syncthreads();

    const int qrow0 = wid * 16;
    uint32_t qah[4][4];
    #pragma unroll
    for (int ks = 0; ks < 4; ks++) {
        uint32_t ah = qhS + (uint32_t)(qrow0 + (lane & 15)) * FRB + ks * 32 + (lane >> 4) * 16;
        ldsm_x4(ah, qah[ks][0], qah[ks][1], qah[ks][2], qah[ks][3]);
    }

    float Oa[8][4];
    #pragma unroll
    for (int nt = 0; nt < 8; nt++)
        #pragma unroll
        for (int f = 0; f < 4; f++) Oa[nt][f] = 0.0f;
    float mrow[2] = {0.0f, 0.0f};   // sink score 0
    float lrow[2] = {1.0f, 1.0f};   // sink exp(0-0)

    for (int jt = 0; jt <= qb; jt++) {
        const int s = jt & 1;
        if (jt < qb) {
            uint32_t base = sb + QT_B + (s ^ 1) * STG_B;
            const int j1 = (jt + 1) * 64;
            #pragma unroll
            for (int u = 0; u < 4; u++) {
                int lin = tid + u * 128; int row = lin >> 3, seg = lin & 7;
                CP_ASYNC16(base + row * FRB + seg * 16,
                           khp + (size_t)(j1 + row) * DH + seg * 8);
                CP_ASYNC16(base + QT_B + row * FRB + seg * 16,
                           vhp + (size_t)row * SEQ + j1 + seg * 8);
            }
            CP_COMMIT();
            CP_WAIT(1);
        } else {
            CP_WAIT(0);
        }
        __syncthreads();

        const uint32_t st = sb + QT_B + s * STG_B;
        const uint32_t khT = st, vhT = st + QT_B;

        // ---- S = Qh Kh^T (1 pass) ----
        float S[8][4];
        #pragma unroll
        for (int nt = 0; nt < 8; nt++)
            #pragma unroll
            for (int f = 0; f < 4; f++) S[nt][f] = 0.0f;

        #pragma unroll
        for (int ks = 0; ks < 4; ks++) {
            uint32_t kh4[16];
            #pragma unroll
            for (int p = 0; p < 4; p++)
                ldsm_b(khT, p * 16, ks * 32, lane, kh4 + p * 4);
            #pragma unroll
            for (int nt = 0; nt < 8; nt++)
                mma16816(S[nt], qah[ks][0], qah[ks][1], qah[ks][2], qah[ks][3],
                         kh4[2 * nt], kh4[2 * nt + 1]);
        }

        // descale x16 + causal mask
        #pragma unroll
        for (int nt = 0; nt < 8; nt++)
            #pragma unroll
            for (int e = 0; e < 4; e++) S[nt][e] *= 0.0625f;
        if (jt == qb) {
            const int j0 = jt * 64;
            #pragma unroll
            for (int nt = 0; nt < 8; nt++) {
                #pragma unroll
                for (int e = 0; e < 4; e++) {
                    int grow = q0 + qrow0 + (lane >> 2) + ((e >= 2) ? 8 : 0);
                    int gcol = j0 + nt * 8 + (lane & 3) * 2 + (e & 1);
                    if (gcol > grow) S[nt][e] = -1e30f;
                }
            }
        }

        // ---- online softmax ----
        #pragma unroll
        for (int i = 0; i < 2; i++) {
            float rm = -1e30f;
            #pragma unroll
            for (int nt = 0; nt < 8; nt++)
                rm = fmaxf(rm, fmaxf(S[nt][2 * i], S[nt][2 * i + 1]));
            rm = fmaxf(rm, __shfl_xor_sync(0xffffffffu, rm, 1));
            rm = fmaxf(rm, __shfl_xor_sync(0xffffffffu, rm, 2));
            float mn = fmaxf(mrow[i], rm);
            float alpha = __expf(mrow[i] - mn);
            float rs = 0.0f;
            #pragma unroll
            for (int nt = 0; nt < 8; nt++) {
                float p0 = __expf(S[nt][2 * i]     - mn);
                float p1 = __expf(S[nt][2 * i + 1] - mn);
                S[nt][2 * i] = p0; S[nt][2 * i + 1] = p1;
                rs += p0 + p1;
            }
            rs += __shfl_xor_sync(0xffffffffu, rs, 1);
            rs += __shfl_xor_sync(0xffffffffu, rs, 2);
            lrow[i] = lrow[i] * alpha + rs;
            mrow[i] = mn;
            #pragma unroll
            for (int nt = 0; nt < 8; nt++) {
                Oa[nt][2 * i]     *= alpha;
                Oa[nt][2 * i + 1] *= alpha;
            }
        }

        // ---- O += Ph Vh (1 pass; P scaled x256 vs denormals) ----
        #pragma unroll
        for (int ks = 0; ks < 4; ks++) {
            uint32_t ah0 = packh(S[2 * ks][0] * 256.0f,     S[2 * ks][1] * 256.0f);
            uint32_t ah1 = packh(S[2 * ks][2] * 256.0f,     S[2 * ks][3] * 256.0f);
            uint32_t ah2 = packh(S[2 * ks + 1][0] * 256.0f, S[2 * ks + 1][1] * 256.0f);
            uint32_t ah3 = packh(S[2 * ks + 1][2] * 256.0f, S[2 * ks + 1][3] * 256.0f);
            uint32_t vh4[16];
            #pragma unroll
            for (int p = 0; p < 4; p++)
                ldsm_b(vhT, p * 16, ks * 32, lane, vh4 + p * 4);
            #pragma unroll
            for (int nt = 0; nt < 8; nt++)
                mma16816(Oa[nt], ah0, ah1, ah2, ah3, vh4[2 * nt], vh4[2 * nt + 1]);
        }
        __syncthreads();
    }

    // ---- epilogue: normalize (incl 1/256), store att hi fp16 [s,b,D] ----
    const float inv0 = 1.0f / (256.0f * lrow[0]);
    const float inv1 = 1.0f / (256.0f * lrow[1]);
    const int r = lane >> 2, c2 = (lane & 3) * 2;
    const int srow0 = q0 + qrow0 + r;
    #pragma unroll
    for (int nt = 0; nt < 8; nt++) {
        int col = h * 64 + nt * 8 + c2;
        float o00 = Oa[nt][0] * inv0, o01 = Oa[nt][1] * inv0;
        float o10 = Oa[nt][2] * inv1, o11 = Oa[nt][3] * inv1;
        size_t off0 = ((size_t)srow0 * BB + b) * DD + col;
        size_t off1 = ((size_t)(srow0 + 8) * BB + b) * DD + col;
        *(uint32_t*)(ah_g + off0) = packh(o00, o01);
        *(uint32_t*)(ah_g + off1) = packh(o10, o11);
    }
}

// ---------------------------------------------------------------------------
extern "C" void kernel_launch(void* const* d_in, const int* in_sizes, int n_in,
                              void* d_out, int out_size)
{
    const float* x    = (const float*)d_in[0];
    const float* beta = (const float*)d_in[2];
    const float* Wq   = (const float*)d_in[3];
    const float* bq   = (const float*)d_in[4];
    const float* Wk   = (const float*)d_in[5];
    const float* bk   = (const float*)d_in[6];
    const float* Wv   = (const float*)d_in[7];
    const float* bv   = (const float*)d_in[8];
    const float* Wo   = (const float*)d_in[9];
    const float* bo   = (const float*)d_in[10];
    float* out = (float*)d_out;

    __half *xh, *qh, *kh, *vh, *ah;
    cudaGetSymbolAddress((void**)&xh, g_xh);
    cudaGetSymbolAddress((void**)&qh, g_qh);
    cudaGetSymbolAddress((void**)&kh, g_kh);
    cudaGetSymbolAddress((void**)&vh, g_vh);
    cudaGetSymbolAddress((void**)&ah, g_ah);

    cudaFuncSetAttribute(gemm_qkv_kernel,
                         cudaFuncAttributeMaxDynamicSharedMemorySize, GEMM_SMEM);
    cudaFuncSetAttribute(gemm_out_kernel,
                         cudaFuncAttributeMaxDynamicSharedMemorySize, GEMM_SMEM);
    cudaFuncSetAttribute(flash_mma_kernel,
                         cudaFuncAttributeMaxDynamicSharedMemorySize, FLASH_SMEM);

    const int nx4 = MM * DD / 4;
    const int nw4 = DD * DD / 4;

    convx_kernel<<<(nx4 + 255) / 256, 256>>>(x, xh, nx4);
    {
        dim3 sg((nw4 + 255) / 256, 4);
        split4_kernel<<<sg, 256>>>(Wq, Wk, Wv, Wo, nw4);
    }

    dim3 qkvgrid(DD / 64, MM / 128, 3);   // (16, 64, 3)
    gemm_qkv_kernel<<<qkvgrid, 256, GEMM_SMEM>>>(beta, bq, bk, bv);

    dim3 fgrid(SEQ / 64, HH, BB);   // (32, 16, 4)
    flash_mma_kernel<<<fgrid, 128, FLASH_SMEM>>>(qh, kh, vh, ah);

    dim3 ogrid(DD / 64, MM / 128);   // (16, 64)
    gemm_out_kernel<<<ogrid, 256, GEMM_SMEM>>>(bo, out);
}

// round 11
// speedup vs baseline: 6.1024x; 1.2156x over previous
#include <cuda_runtime.h>
#include <cuda_fp16.h>
#include <stdint.h>
#include <math.h>

// Problem constants
#define SEQ 2048
#define BB  4
#define DD  1024
#define HH  16
#define DH  64
#define MM  (SEQ*BB)

// ---------------- scratch (device globals; allocation-free) ----------------
__device__ __half g_xh[MM*DD];
__device__ __half g_wqh[DD*DD], g_wkh[DD*DD], g_wvh[DD*DD], g_woh[DD*DD];
__device__ __half g_qh[MM*DD];   // scaled x16 incl beta, [b,h,s,dh]
__device__ __half g_kh[MM*DD];   // [b,h,s,dh]
__device__ __half g_vh[MM*DD];   // transposed [b,h,dh,s]
__device__ __half g_ah[MM*DD];   // att output [s,b,D]

// ---------------- PTX helpers (baseline ISA only) ----------------
static __device__ __forceinline__ uint32_t s2u(const void* p) {
    return (uint32_t)__cvta_generic_to_shared(p);
}

#define CP_ASYNC16(saddr, gptr) \
    asm volatile("cp.async.cg.shared.global [%0], [%1], 16;" :: "r"(saddr), "l"(gptr))
#define CP_COMMIT() asm volatile("cp.async.commit_group;" ::: "memory")
#define CP_WAIT(n)  asm volatile("cp.async.wait_group %0;" :: "n"(n) : "memory")

static __device__ __forceinline__ void ldsm_x4(uint32_t addr,
    uint32_t &r0, uint32_t &r1, uint32_t &r2, uint32_t &r3)
{
    asm volatile("ldmatrix.sync.aligned.m8n8.x4.shared.b16 {%0,%1,%2,%3}, [%4];"
        : "=r"(r0), "=r"(r1), "=r"(r2), "=r"(r3) : "r"(addr));
}

static __device__ __forceinline__ void mma16816(float* d,
    uint32_t a0, uint32_t a1, uint32_t a2, uint32_t a3, uint32_t b0, uint32_t b1)
{
    asm volatile("mma.sync.aligned.m16n8k16.row.col.f32.f16.f16.f32 "
        "{%0,%1,%2,%3}, {%4,%5,%6,%7}, {%8,%9}, {%0,%1,%2,%3};"
        : "+f"(d[0]), "+f"(d[1]), "+f"(d[2]), "+f"(d[3])
        : "r"(a0), "r"(a1), "r"(a2), "r"(a3), "r"(b0), "r"(b1));
}

static __device__ __forceinline__ uint32_t packh(float x, float y) {
    __half2 t = __floats2half2_rn(x, y);
    return *(uint32_t*)&t;
}

// ---------------- conversion kernels ----------------
__global__ void convx_kernel(const float* __restrict__ src,
                             __half* __restrict__ hi, int n4)
{
    int i = blockIdx.x * blockDim.x + threadIdx.x;
    if (i >= n4) return;
    float4 v = ((const float4*)src)[i];
    uint2 o;
    o.x = packh(v.x, v.y);
    o.y = packh(v.z, v.w);
    ((uint2*)hi)[i] = o;
}

// W*64 -> fp16 hi only (4 weight tensors via blockIdx.y)
__global__ void split4_kernel(const float* __restrict__ s0, const float* __restrict__ s1,
                              const float* __restrict__ s2, const float* __restrict__ s3,
                              int n4)
{
    int i = blockIdx.x * blockDim.x + threadIdx.x;
    if (i >= n4) return;
    const float* src; __half* hi;
    switch (blockIdx.y) {
        case 0:  src = s0; hi = g_wqh; break;
        case 1:  src = s1; hi = g_wkh; break;
        case 2:  src = s2; hi = g_wvh; break;
        default: src = s3; hi = g_woh; break;
    }
    float4 v = ((const float4*)src)[i];
    uint2 oh;
    oh.x = packh(v.x * 64.0f, v.y * 64.0f);
    oh.y = packh(v.z * 64.0f, v.w * 64.0f);
    ((uint2*)hi)[i] = oh;
}

// ---------------------------------------------------------------------------
// HMMA GEMM body (1-pass fp16): C = A[M,K] @ Bh[N,K]^T  (B pre-scaled x64).
// CTA tile 128(M)x64(N), 8 warps of 32x32. Descale 1/64 + bias in epilogue.
// mode 0: fp32 out [s,b,D]
// mode 1: fp16 out [b,h,s,dh], scaled by 2*exp(-beta_h)
// mode 2: fp16 out transposed [b,h,dh,s]
// mode 3: fp16 out [b,h,s,dh]
// ---------------------------------------------------------------------------
#define GBK 32
#define NCG (DD / GBK)
#define RSMEM 80
#define A_T 10240
#define B_T 5120
#define BUF_B (A_T + B_T)         // 15360
#define GEMM_SMEM (2 * BUF_B)     // 30720

static __device__ __forceinline__ void gemm_body(
    const __half* __restrict__ A, const __half* __restrict__ Bhi,
    const float* __restrict__ bias, int mode,
    const float* __restrict__ beta,
    float* __restrict__ C, __half* __restrict__ Oh,
    int bn, int bm, char* smc)
{
    const int tid  = threadIdx.x;
    const int wid  = tid >> 5;
    const int lane = tid & 31;
    const uint32_t sb = s2u(smc);

    const int m0 = (wid >> 1) * 32;
    const int n0 = (wid & 1) * 32;

    const int lrow0 = tid >> 2;
    const int lseg  = tid & 3;

    {
        const __half* ga  = A   + (size_t)(bm + lrow0) * DD + lseg * 8;
        const __half* gb0 = Bhi + (size_t)(bn + lrow0) * DD + lseg * 8;
        uint32_t sa = sb + lrow0 * RSMEM + lseg * 16;
        CP_ASYNC16(sa,              ga);
        CP_ASYNC16(sa + 64 * RSMEM, ga + (size_t)64 * DD);
        CP_ASYNC16(sa + A_T,        gb0);
    }
    CP_COMMIT();

    float acc[2][4][4];
    #pragma unroll
    for (int mi = 0; mi < 2; mi++)
        #pragma unroll
        for (int ni = 0; ni < 4; ni++)
            #pragma unroll
            for (int f = 0; f < 4; f++) acc[mi][ni][f] = 0.0f;

    for (int c = 0; c < NCG; c++) {
        if (c + 1 < NCG) {
            const int k0 = (c + 1) * GBK;
            const uint32_t bufo = ((c + 1) & 1) * BUF_B;
            const __half* ga  = A   + (size_t)(bm + lrow0) * DD + k0 + lseg * 8;
            const __half* gb0 = Bhi + (size_t)(bn + lrow0) * DD + k0 + lseg * 8;
            uint32_t sa = sb + bufo + lrow0 * RSMEM + lseg * 16;
            CP_ASYNC16(sa,              ga);
            CP_ASYNC16(sa + 64 * RSMEM, ga + (size_t)64 * DD);
            CP_ASYNC16(sa + A_T,        gb0);
            CP_COMMIT();
            CP_WAIT(1);
        } else {
            CP_WAIT(0);
        }
        __syncthreads();

        const uint32_t bufo = (c & 1) * BUF_B;
        const uint32_t AT  = sb + bufo;
        const uint32_t BhT = AT + A_T;

        #pragma unroll
        for (int s = 0; s < 2; s++) {
            const uint32_t kb = s * 32;
            uint32_t bh[4][2], ah[2][4];
            {
                int g = lane >> 3;
                int ntl = g >> 1, half = g & 1;
                uint32_t boff = (uint32_t)(n0 + ntl * 8 + (lane & 7)) * RSMEM
                              + kb + half * 16;
                ldsm_x4(BhT + boff,              bh[0][0], bh[0][1], bh[1][0], bh[1][1]);
                ldsm_x4(BhT + boff + 16 * RSMEM, bh[2][0], bh[2][1], bh[3][0], bh[3][1]);
            }
            #pragma unroll
            for (int mi = 0; mi < 2; mi++) {
                uint32_t aoff = (uint32_t)(m0 + mi * 16 + (lane & 15)) * RSMEM
                              + kb + (lane >> 4) * 16;
                ldsm_x4(AT + aoff, ah[mi][0], ah[mi][1], ah[mi][2], ah[mi][3]);
            }
            #pragma unroll
            for (int mi = 0; mi < 2; mi++)
                #pragma unroll
                for (int ni = 0; ni < 4; ni++)
                    mma16816(acc[mi][ni], ah[mi][0], ah[mi][1], ah[mi][2], ah[mi][3],
                             bh[ni][0], bh[ni][1]);
        }
        __syncthreads();
    }

    const float DS = 1.0f / 64.0f;
    const int erow = lane >> 2;
    const int ecol = (lane & 3) * 2;
    #pragma unroll
    for (int mi = 0; mi < 2; mi++) {
        #pragma unroll
        for (int ni = 0; ni < 4; ni++) {
            int gr = bm + m0 + mi * 16 + erow;
            int gc = bn + n0 + ni * 8 + ecol;
            float v0x = acc[mi][ni][0] * DS + bias[gc];
            float v0y = acc[mi][ni][1] * DS + bias[gc + 1];
            float v1x = acc[mi][ni][2] * DS + bias[gc];
            float v1y = acc[mi][ni][3] * DS + bias[gc + 1];
            if (mode == 0) {
                float2 a = {v0x, v0y}, bb2 = {v1x, v1y};
                *(float2*)(C + (size_t)gr * DD + gc)       = a;
                *(float2*)(C + (size_t)(gr + 8) * DD + gc) = bb2;
            } else {
                int hh = gc >> 6, dh = gc & 63;
                int s0 = gr >> 2, bbi = gr & 3;
                if (mode == 1 || mode == 3) {
                    if (mode == 1) {
                        float f = 2.0f * __expf(-beta[hh]);
                        v0x *= f; v0y *= f; v1x *= f; v1y *= f;
                    }
                    size_t off0 = (((size_t)bbi * HH + hh) * SEQ + s0) * DH + dh;
                    size_t off1 = off0 + 2 * DH;
                    *(uint32_t*)(Oh + off0) = packh(v0x, v0y);
                    *(uint32_t*)(Oh + off1) = packh(v1x, v1y);
                } else {
                    size_t off = (((size_t)bbi * HH + hh) * DH + dh) * SEQ + s0;
                    Oh[off]           = __float2half_rn(v0x);
                    Oh[off + SEQ]     = __float2half_rn(v0y);
                    Oh[off + 2]       = __float2half_rn(v1x);
                    Oh[off + SEQ + 2] = __float2half_rn(v1y);
                }
            }
        }
    }
}

__global__ __launch_bounds__(256, 3)
void gemm_qkv_kernel(const float* __restrict__ beta,
                     const float* __restrict__ bq,
                     const float* __restrict__ bk,
                     const float* __restrict__ bv)
{
    extern __shared__ char smc[];
    const int bn = blockIdx.x * 64;
    const int bm = blockIdx.y * 128;
    if (blockIdx.z == 0)
        gemm_body(g_xh, g_wqh, bq, 1, beta, nullptr, g_qh, bn, bm, smc);
    else if (blockIdx.z == 1)
        gemm_body(g_xh, g_wkh, bk, 3, nullptr, nullptr, g_kh, bn, bm, smc);
    else
        gemm_body(g_xh, g_wvh, bv, 2, nullptr, nullptr, g_vh, bn, bm, smc);
}

__global__ __launch_bounds__(256, 3)
void gemm_out_kernel(const float* __restrict__ bo, float* __restrict__ out)
{
    extern __shared__ char smc[];
    const int bn = blockIdx.x * 64;
    const int bm = blockIdx.y * 128;
    gemm_body(g_ah, g_woh, bo, 0, nullptr, out, nullptr, bn, bm, smc);
}

// ---------------------------------------------------------------------------
// Flash attention, fp16: S = Qh Kh^T (x16 scaled), O = Ph Vh (P x256 scaled).
// Block 128 thr / 4 warps, 64 Q rows, LPT order. smem 45 KB.
// ---------------------------------------------------------------------------
#define FRB 144
#define QT_B (64 * FRB)            // 9216
#define STG_B (2 * QT_B)           // 18432
#define FLASH_SMEM (QT_B + 2 * STG_B)   // 46080

static __device__ __forceinline__ void ldsm_b(uint32_t tile, int nbase, int ksb,
                                              int lane, uint32_t* r4)
{
    int g = lane >> 3, ntl = g >> 1, half = g & 1;
    uint32_t addr = tile + (uint32_t)(nbase + ntl * 8 + (lane & 7)) * FRB
                  + ksb + half * 16;
    ldsm_x4(addr, r4[0], r4[1], r4[2], r4[3]);
}

__global__ __launch_bounds__(128, 3)
void flash_mma_kernel(const __half* __restrict__ qh_g,
                      const __half* __restrict__ kh_g,
                      const __half* __restrict__ vh_g,
                      __half* __restrict__ ah_g)
{
    extern __shared__ char smf[];
    const int tid = threadIdx.x, lane = tid & 31, wid = tid >> 5;
    const int qb = (int)gridDim.x - 1 - (int)blockIdx.x;
    const int h = blockIdx.y, b = blockIdx.z;
    const int q0 = qb * 64;
    const uint32_t sb = s2u(smf);
    const uint32_t qhS = sb;

    const size_t bh = (size_t)b * HH + h;
    const char* qhp = (const char*)(qh_g + (bh * SEQ + q0) * DH);
    const __half* khp = kh_g + bh * SEQ * DH;
    const __half* vhp = vh_g + bh * (size_t)DH * SEQ;

    #pragma unroll
    for (int u = 0; u < 4; u++) {
        int lin = tid + u * 128; int row = lin >> 3, seg = lin & 7;
        CP_ASYNC16(qhS + row * FRB + seg * 16, qhp + row * 128 + seg * 16);
    }
    CP_COMMIT();

    {
        uint32_t base = sb + QT_B;
        #pragma unroll
        for (int u = 0; u < 4; u++) {
            int lin = tid + u * 128; int row = lin >> 3, seg = lin & 7;
            CP_ASYNC16(base + row * FRB + seg * 16, khp + (size_t)row * DH + seg * 8);
            CP_ASYNC16(base + QT_B + row * FRB + seg * 16, vhp + (size_t)row * SEQ + seg * 8);
        }
        CP_COMMIT();
    }
    CP_WAIT(0);
    __syncthreads();

    const int qrow0 = wid * 16;
    uint32_t qah[4][4];
    #pragma unroll
    for (int ks = 0; ks < 4; ks++) {
        uint32_t ah = qhS + (uint32_t)(qrow0 + (lane & 15)) * FRB + ks * 32 + (lane >> 4) * 16;
        ldsm_x4(ah, qah[ks][0], qah[ks][1], qah[ks][2], qah[ks][3]);
    }

    float Oa[8][4];
    #pragma unroll
    for (int nt = 0; nt < 8; nt++)
        #pragma unroll
        for (int f = 0; f < 4; f++) Oa[nt][f] = 0.0f;
    float mrow[2] = {0.0f, 0.0f};   // sink score 0
    float lrow[2] = {1.0f, 1.0f};   // sink exp(0-0)

    for (int jt = 0; jt <= qb; jt++) {
        const int s = jt & 1;
        if (jt < qb) {
            uint32_t base = sb + QT_B + (s ^ 1) * STG_B;
            const int j1 = (jt + 1) * 64;
            #pragma unroll
            for (int u = 0; u < 4; u++) {
                int lin = tid + u * 128; int row = lin >> 3, seg = lin & 7;
                CP_ASYNC16(base + row * FRB + seg * 16,
                           khp + (size_t)(j1 + row) * DH + seg * 8);
                CP_ASYNC16(base + QT_B + row * FRB + seg * 16,
                           vhp + (size_t)row * SEQ + j1 + seg * 8);
            }
            CP_COMMIT();
            CP_WAIT(1);
        } else {
            CP_WAIT(0);
        }
        __syncthreads();

        const uint32_t st = sb + QT_B + s * STG_B;
        const uint32_t khT = st, vhT = st + QT_B;

        // ---- S = Qh Kh^T ----
        float S[8][4];
        #pragma unroll
        for (int nt = 0; nt < 8; nt++)
            #pragma unroll
            for (int f = 0; f < 4; f++) S[nt][f] = 0.0f;

        #pragma unroll
        for (int ks = 0; ks < 4; ks++) {
            uint32_t kh4[16];
            #pragma unroll
            for (int p = 0; p < 4; p++)
                ldsm_b(khT, p * 16, ks * 32, lane, kh4 + p * 4);
            #pragma unroll
            for (int nt = 0; nt < 8; nt++)
                mma16816(S[nt], qah[ks][0], qah[ks][1], qah[ks][2], qah[ks][3],
                         kh4[2 * nt], kh4[2 * nt + 1]);
        }

        // descale x16 + causal mask
        #pragma unroll
        for (int nt = 0; nt < 8; nt++)
            #pragma unroll
            for (int e = 0; e < 4; e++) S[nt][e] *= 0.0625f;
        if (jt == qb) {
            const int j0 = jt * 64;
            #pragma unroll
            for (int nt = 0; nt < 8; nt++) {
                #pragma unroll
                for (int e = 0; e < 4; e++) {
                    int grow = q0 + qrow0 + (lane >> 2) + ((e >= 2) ? 8 : 0);
                    int gcol = j0 + nt * 8 + (lane & 3) * 2 + (e & 1);
                    if (gcol > grow) S[nt][e] = -1e30f;
                }
            }
        }

        // ---- online softmax ----
        #pragma unroll
        for (int i = 0; i < 2; i++) {
            float rm = -1e30f;
            #pragma unroll
            for (int nt = 0; nt < 8; nt++)
                rm = fmaxf(rm, fmaxf(S[nt][2 * i], S[nt][2 * i + 1]));
            rm = fmaxf(rm, __shfl_xor_sync(0xffffffffu, rm, 1));
            rm = fmaxf(rm, __shfl_xor_sync(0xffffffffu, rm, 2));
            float mn = fmaxf(mrow[i], rm);
            float alpha = __expf(mrow[i] - mn);
            float rs = 0.0f;
            #pragma unroll
            for (int nt = 0; nt < 8; nt++) {
                float p0 = __expf(S[nt][2 * i]     - mn);
                float p1 = __expf(S[nt][2 * i + 1] - mn);
                S[nt][2 * i] = p0; S[nt][2 * i + 1] = p1;
                rs += p0 + p1;
            }
            rs += __shfl_xor_sync(0xffffffffu, rs, 1);
            rs += __shfl_xor_sync(0xffffffffu, rs, 2);
            lrow[i] = lrow[i] * alpha + rs;
            mrow[i] = mn;
            #pragma unroll
            for (int nt = 0; nt < 8; nt++) {
                Oa[nt][2 * i]     *= alpha;
                Oa[nt][2 * i + 1] *= alpha;
            }
        }

        // ---- O += Ph Vh (P scaled x256 vs denormals) ----
        #pragma unroll
        for (int ks = 0; ks < 4; ks++) {
            uint32_t ah0 = packh(S[2 * ks][0] * 256.0f,     S[2 * ks][1] * 256.0f);
            uint32_t ah1 = packh(S[2 * ks][2] * 256.0f,     S[2 * ks][3] * 256.0f);
            uint32_t ah2 = packh(S[2 * ks + 1][0] * 256.0f, S[2 * ks + 1][1] * 256.0f);
            uint32_t ah3 = packh(S[2 * ks + 1][2] * 256.0f, S[2 * ks + 1][3] * 256.0f);
            uint32_t vh4[16];
            #pragma unroll
            for (int p = 0; p < 4; p++)
                ldsm_b(vhT, p * 16, ks * 32, lane, vh4 + p * 4);
            #pragma unroll
            for (int nt = 0; nt < 8; nt++)
                mma16816(Oa[nt], ah0, ah1, ah2, ah3, vh4[2 * nt], vh4[2 * nt + 1]);
        }
        __syncthreads();
    }

    // ---- epilogue: normalize (incl 1/256), store att fp16 [s,b,D] ----
    const float inv0 = 1.0f / (256.0f * lrow[0]);
    const float inv1 = 1.0f / (256.0f * lrow[1]);
    const int r = lane >> 2, c2 = (lane & 3) * 2;
    const int srow0 = q0 + qrow0 + r;
    #pragma unroll
    for (int nt = 0; nt < 8; nt++) {
        int col = h * 64 + nt * 8 + c2;
        float o00 = Oa[nt][0] * inv0, o01 = Oa[nt][1] * inv0;
        float o10 = Oa[nt][2] * inv1, o11 = Oa[nt][3] * inv1;
        size_t off0 = ((size_t)srow0 * BB + b) * DD + col;
        size_t off1 = ((size_t)(srow0 + 8) * BB + b) * DD + col;
        *(uint32_t*)(ah_g + off0) = packh(o00, o01);
        *(uint32_t*)(ah_g + off1) = packh(o10, o11);
    }
}

// ---------------------------------------------------------------------------
extern "C" void kernel_launch(void* const* d_in, const int* in_sizes, int n_in,
                              void* d_out, int out_size)
{
    const float* x    = (const float*)d_in[0];
    const float* beta = (const float*)d_in[2];
    const float* Wq   = (const float*)d_in[3];
    const float* bq   = (const float*)d_in[4];
    const float* Wk   = (const float*)d_in[5];
    const float* bk   = (const float*)d_in[6];
    const float* Wv   = (const float*)d_in[7];
    const float* bv   = (const float*)d_in[8];
    const float* Wo   = (const float*)d_in[9];
    const float* bo   = (const float*)d_in[10];
    float* out = (float*)d_out;

    __half *xh, *qh, *kh, *vh, *ah;
    cudaGetSymbolAddress((void**)&xh, g_xh);
    cudaGetSymbolAddress((void**)&qh, g_qh);
    cudaGetSymbolAddress((void**)&kh, g_kh);
    cudaGetSymbolAddress((void**)&vh, g_vh);
    cudaGetSymbolAddress((void**)&ah, g_ah);

    cudaFuncSetAttribute(gemm_qkv_kernel,
                         cudaFuncAttributeMaxDynamicSharedMemorySize, GEMM_SMEM);
    cudaFuncSetAttribute(gemm_out_kernel,
                         cudaFuncAttributeMaxDynamicSharedMemorySize, GEMM_SMEM);
    cudaFuncSetAttribute(flash_mma_kernel,
                         cudaFuncAttributeMaxDynamicSharedMemorySize, FLASH_SMEM);

    const int nx4 = MM * DD / 4;
    const int nw4 = DD * DD / 4;

    convx_kernel<<<(nx4 + 255) / 256, 256>>>(x, xh, nx4);
    {
        dim3 sg((nw4 + 255) / 256, 4);
        split4_kernel<<<sg, 256>>>(Wq, Wk, Wv, Wo, nw4);
    }

    dim3 qkvgrid(DD / 64, MM / 128, 3);   // (16, 64, 3)
    gemm_qkv_kernel<<<qkvgrid, 256, GEMM_SMEM>>>(beta, bq, bk, bv);

    dim3 fgrid(SEQ / 64, HH, BB);   // (32, 16, 4)
    flash_mma_kernel<<<fgrid, 128, FLASH_SMEM>>>(qh, kh, vh, ah);

    dim3 ogrid(DD / 64, MM / 128);   // (16, 64)
    gemm_out_kernel<<<ogrid, 256, GEMM_SMEM>>>(bo, out);
}

// round 12
// speedup vs baseline: 6.1484x; 1.0075x over previous
#include <cuda_runtime.h>
#include <cuda_fp16.h>
#include <stdint.h>
#include <math.h>

// Problem constants
#define SEQ 2048
#define BB  4
#define DD  1024
#define HH  16
#define DH  64
#define MM  (SEQ*BB)

// ---------------- scratch (device globals; allocation-free) ----------------
__device__ __half g_xh[MM*DD];
__device__ __half g_wqh[DD*DD], g_wkh[DD*DD], g_wvh[DD*DD], g_woh[DD*DD];
__device__ __half g_qh[MM*DD];   // scaled x16 incl beta, [b,h,s,dh]
__device__ __half g_kh[MM*DD];   // [b,h,s,dh]
__device__ __half g_vh[MM*DD];   // transposed [b,h,dh,s]
__device__ __half g_ah[MM*DD];   // att output [s,b,D]

// ---------------- PTX helpers (baseline ISA only) ----------------
static __device__ __forceinline__ uint32_t s2u(const void* p) {
    return (uint32_t)__cvta_generic_to_shared(p);
}

#define CP_ASYNC16(saddr, gptr) \
    asm volatile("cp.async.cg.shared.global [%0], [%1], 16;" :: "r"(saddr), "l"(gptr))
#define CP_COMMIT() asm volatile("cp.async.commit_group;" ::: "memory")
#define CP_WAIT(n)  asm volatile("cp.async.wait_group %0;" :: "n"(n) : "memory")

static __device__ __forceinline__ void ldsm_x4(uint32_t addr,
    uint32_t &r0, uint32_t &r1, uint32_t &r2, uint32_t &r3)
{
    asm volatile("ldmatrix.sync.aligned.m8n8.x4.shared.b16 {%0,%1,%2,%3}, [%4];"
        : "=r"(r0), "=r"(r1), "=r"(r2), "=r"(r3) : "r"(addr));
}

static __device__ __forceinline__ void mma16816(float* d,
    uint32_t a0, uint32_t a1, uint32_t a2, uint32_t a3, uint32_t b0, uint32_t b1)
{
    asm volatile("mma.sync.aligned.m16n8k16.row.col.f32.f16.f16.f32 "
        "{%0,%1,%2,%3}, {%4,%5,%6,%7}, {%8,%9}, {%0,%1,%2,%3};"
        : "+f"(d[0]), "+f"(d[1]), "+f"(d[2]), "+f"(d[3])
        : "r"(a0), "r"(a1), "r"(a2), "r"(a3), "r"(b0), "r"(b1));
}

static __device__ __forceinline__ uint32_t packh(float x, float y) {
    __half2 t = __floats2half2_rn(x, y);
    return *(uint32_t*)&t;
}

// ---------------- conversion kernels ----------------
__global__ void convx_kernel(const float* __restrict__ src,
                             __half* __restrict__ hi, int n4)
{
    int i = blockIdx.x * blockDim.x + threadIdx.x;
    if (i >= n4) return;
    float4 v = ((const float4*)src)[i];
    uint2 o;
    o.x = packh(v.x, v.y);
    o.y = packh(v.z, v.w);
    ((uint2*)hi)[i] = o;
}

__global__ void split4_kernel(const float* __restrict__ s0, const float* __restrict__ s1,
                              const float* __restrict__ s2, const float* __restrict__ s3,
                              int n4)
{
    int i = blockIdx.x * blockDim.x + threadIdx.x;
    if (i >= n4) return;
    const float* src; __half* hi;
    switch (blockIdx.y) {
        case 0:  src = s0; hi = g_wqh; break;
        case 1:  src = s1; hi = g_wkh; break;
        case 2:  src = s2; hi = g_wvh; break;
        default: src = s3; hi = g_woh; break;
    }
    float4 v = ((const float4*)src)[i];
    uint2 oh;
    oh.x = packh(v.x * 64.0f, v.y * 64.0f);
    oh.y = packh(v.z * 64.0f, v.w * 64.0f);
    ((uint2*)hi)[i] = oh;
}

// ---------------------------------------------------------------------------
// HMMA GEMM body (1-pass fp16): C = A[M,K] @ Bh[N,K]^T  (B pre-scaled x64).
// CTA tile 128(M)x64(N), 8 warps of 32x32. Descale 1/64 + bias in epilogue.
// mode 0: fp32 out [s,b,D]
// mode 1: fp16 out [b,h,s,dh], scaled by 2*exp(-beta_h)
// mode 2: fp16 out transposed [b,h,dh,s]
// mode 3: fp16 out [b,h,s,dh]
// ---------------------------------------------------------------------------
#define GBK 32
#define NCG (DD / GBK)
#define RSMEM 80
#define A_T 10240
#define B_T 5120
#define BUF_B (A_T + B_T)         // 15360
#define GEMM_SMEM (2 * BUF_B)     // 30720

static __device__ __forceinline__ void gemm_body(
    const __half* __restrict__ A, const __half* __restrict__ Bhi,
    const float* __restrict__ bias, int mode,
    const float* __restrict__ beta,
    float* __restrict__ C, __half* __restrict__ Oh,
    int bn, int bm, char* smc)
{
    const int tid  = threadIdx.x;
    const int wid  = tid >> 5;
    const int lane = tid & 31;
    const uint32_t sb = s2u(smc);

    const int m0 = (wid >> 1) * 32;
    const int n0 = (wid & 1) * 32;

    const int lrow0 = tid >> 2;
    const int lseg  = tid & 3;

    {
        const __half* ga  = A   + (size_t)(bm + lrow0) * DD + lseg * 8;
        const __half* gb0 = Bhi + (size_t)(bn + lrow0) * DD + lseg * 8;
        uint32_t sa = sb + lrow0 * RSMEM + lseg * 16;
        CP_ASYNC16(sa,              ga);
        CP_ASYNC16(sa + 64 * RSMEM, ga + (size_t)64 * DD);
        CP_ASYNC16(sa + A_T,        gb0);
    }
    CP_COMMIT();

    float acc[2][4][4];
    #pragma unroll
    for (int mi = 0; mi < 2; mi++)
        #pragma unroll
        for (int ni = 0; ni < 4; ni++)
            #pragma unroll
            for (int f = 0; f < 4; f++) acc[mi][ni][f] = 0.0f;

    for (int c = 0; c < NCG; c++) {
        if (c + 1 < NCG) {
            const int k0 = (c + 1) * GBK;
            const uint32_t bufo = ((c + 1) & 1) * BUF_B;
            const __half* ga  = A   + (size_t)(bm + lrow0) * DD + k0 + lseg * 8;
            const __half* gb0 = Bhi + (size_t)(bn + lrow0) * DD + k0 + lseg * 8;
            uint32_t sa = sb + bufo + lrow0 * RSMEM + lseg * 16;
            CP_ASYNC16(sa,              ga);
            CP_ASYNC16(sa + 64 * RSMEM, ga + (size_t)64 * DD);
            CP_ASYNC16(sa + A_T,        gb0);
            CP_COMMIT();
            CP_WAIT(1);
        } else {
            CP_WAIT(0);
        }
        __syncthreads();

        const uint32_t bufo = (c & 1) * BUF_B;
        const uint32_t AT  = sb + bufo;
        const uint32_t BhT = AT + A_T;

        #pragma unroll
        for (int s = 0; s < 2; s++) {
            const uint32_t kb = s * 32;
            uint32_t bh[4][2], ah[2][4];
            {
                int g = lane >> 3;
                int ntl = g >> 1, half = g & 1;
                uint32_t boff = (uint32_t)(n0 + ntl * 8 + (lane & 7)) * RSMEM
                              + kb + half * 16;
                ldsm_x4(BhT + boff,              bh[0][0], bh[0][1], bh[1][0], bh[1][1]);
                ldsm_x4(BhT + boff + 16 * RSMEM, bh[2][0], bh[2][1], bh[3][0], bh[3][1]);
            }
            #pragma unroll
            for (int mi = 0; mi < 2; mi++) {
                uint32_t aoff = (uint32_t)(m0 + mi * 16 + (lane & 15)) * RSMEM
                              + kb + (lane >> 4) * 16;
                ldsm_x4(AT + aoff, ah[mi][0], ah[mi][1], ah[mi][2], ah[mi][3]);
            }
            #pragma unroll
            for (int mi = 0; mi < 2; mi++)
                #pragma unroll
                for (int ni = 0; ni < 4; ni++)
                    mma16816(acc[mi][ni], ah[mi][0], ah[mi][1], ah[mi][2], ah[mi][3],
                             bh[ni][0], bh[ni][1]);
        }
        __syncthreads();
    }

    const float DS = 1.0f / 64.0f;
    const int erow = lane >> 2;
    const int ecol = (lane & 3) * 2;
    #pragma unroll
    for (int mi = 0; mi < 2; mi++) {
        #pragma unroll
        for (int ni = 0; ni < 4; ni++) {
            int gr = bm + m0 + mi * 16 + erow;
            int gc = bn + n0 + ni * 8 + ecol;
            float v0x = acc[mi][ni][0] * DS + bias[gc];
            float v0y = acc[mi][ni][1] * DS + bias[gc + 1];
            float v1x = acc[mi][ni][2] * DS + bias[gc];
            float v1y = acc[mi][ni][3] * DS + bias[gc + 1];
            if (mode == 0) {
                float2 a = {v0x, v0y}, bb2 = {v1x, v1y};
                *(float2*)(C + (size_t)gr * DD + gc)       = a;
                *(float2*)(C + (size_t)(gr + 8) * DD + gc) = bb2;
            } else {
                int hh = gc >> 6, dh = gc & 63;
                int s0 = gr >> 2, bbi = gr & 3;
                if (mode == 1 || mode == 3) {
                    if (mode == 1) {
                        float f = 2.0f * __expf(-beta[hh]);
                        v0x *= f; v0y *= f; v1x *= f; v1y *= f;
                    }
                    size_t off0 = (((size_t)bbi * HH + hh) * SEQ + s0) * DH + dh;
                    size_t off1 = off0 + 2 * DH;
                    *(uint32_t*)(Oh + off0) = packh(v0x, v0y);
                    *(uint32_t*)(Oh + off1) = packh(v1x, v1y);
                } else {
                    size_t off = (((size_t)bbi * HH + hh) * DH + dh) * SEQ + s0;
                    Oh[off]           = __float2half_rn(v0x);
                    Oh[off + SEQ]     = __float2half_rn(v0y);
                    Oh[off + 2]       = __float2half_rn(v1x);
                    Oh[off + SEQ + 2] = __float2half_rn(v1y);
                }
            }
        }
    }
}

// Persistent fused Q/K/V projection: grid-stride over 3*64*16 tiles.
// bn fastest so consecutive tiles share the A (x) rows in L2.
__global__ __launch_bounds__(256, 3)
void gemm_qkv_kernel(const float* __restrict__ beta,
                     const float* __restrict__ bq,
                     const float* __restrict__ bk,
                     const float* __restrict__ bv)
{
    extern __shared__ char smc[];
    const int NT = 16 * 64 * 3;
    for (int t = blockIdx.x; t < NT; t += gridDim.x) {
        const int bn = (t & 15) * 64;
        const int bm = ((t >> 4) & 63) * 128;
        const int z  = t >> 10;
        if (z == 0)
            gemm_body(g_xh, g_wqh, bq, 1, beta, nullptr, g_qh, bn, bm, smc);
        else if (z == 1)
            gemm_body(g_xh, g_wkh, bk, 3, nullptr, nullptr, g_kh, bn, bm, smc);
        else
            gemm_body(g_xh, g_wvh, bv, 2, nullptr, nullptr, g_vh, bn, bm, smc);
    }
}

// Persistent output projection: grid-stride over 64*16 tiles.
__global__ __launch_bounds__(256, 3)
void gemm_out_kernel(const float* __restrict__ bo, float* __restrict__ out)
{
    extern __shared__ char smc[];
    const int NT = 16 * 64;
    for (int t = blockIdx.x; t < NT; t += gridDim.x) {
        const int bn = (t & 15) * 64;
        const int bm = (t >> 4) * 128;
        gemm_body(g_ah, g_woh, bo, 0, nullptr, out, nullptr, bn, bm, smc);
    }
}

// ---------------------------------------------------------------------------
// Flash attention, fp16: S raw = Qh Kh^T (x16 units); folded softmax:
//   p_scaled(=p*256) = exp2(S*C2 + (8 - m*C2)), m tracked in raw units.
// lrow carries the x256 scale (sink init 256). O = (p_scaled V) / lrow.
// Block 128 thr / 4 warps, 64 Q rows, LPT order. smem 45 KB.
// ---------------------------------------------------------------------------
#define FRB 144
#define QT_B (64 * FRB)            // 9216
#define STG_B (2 * QT_B)           // 18432
#define FLASH_SMEM (QT_B + 2 * STG_B)   // 46080
#define C2F 0.0901684856755f       // 0.0625 * log2(e)

static __device__ __forceinline__ void ldsm_b(uint32_t tile, int nbase, int ksb,
                                              int lane, uint32_t* r4)
{
    int g = lane >> 3, ntl = g >> 1, half = g & 1;
    uint32_t addr = tile + (uint32_t)(nbase + ntl * 8 + (lane & 7)) * FRB
                  + ksb + half * 16;
    ldsm_x4(addr, r4[0], r4[1], r4[2], r4[3]);
}

__global__ __launch_bounds__(128, 3)
void flash_mma_kernel(const __half* __restrict__ qh_g,
                      const __half* __restrict__ kh_g,
                      const __half* __restrict__ vh_g,
                      __half* __restrict__ ah_g)
{
    extern __shared__ char smf[];
    const int tid = threadIdx.x, lane = tid & 31, wid = tid >> 5;
    const int qb = (int)gridDim.x - 1 - (int)blockIdx.x;
    const int h = blockIdx.y, b = blockIdx.z;
    const int q0 = qb * 64;
    const uint32_t sb = s2u(smf);
    const uint32_t qhS = sb;

    const size_t bh = (size_t)b * HH + h;
    const char* qhp = (const char*)(qh_g + (bh * SEQ + q0) * DH);
    const __half* khp = kh_g + bh * SEQ * DH;
    const __half* vhp = vh_g + bh * (size_t)DH * SEQ;

    #pragma unroll
    for (int u = 0; u < 4; u++) {
        int lin = tid + u * 128; int row = lin >> 3, seg = lin & 7;
        CP_ASYNC16(qhS + row * FRB + seg * 16, qhp + row * 128 + seg * 16);
    }
    CP_COMMIT();

    {
        uint32_t base = sb + QT_B;
        #pragma unroll
        for (int u = 0; u < 4; u++) {
            int lin = tid + u * 128; int row = lin >> 3, seg = lin & 7;
            CP_ASYNC16(base + row * FRB + seg * 16, khp + (size_t)row * DH + seg * 8);
            CP_ASYNC16(base + QT_B + row * FRB + seg * 16, vhp + (size_t)row * SEQ + seg * 8);
        }
        CP_COMMIT();
    }
    CP_WAIT(0);
    __syncthreads();

    const int qrow0 = wid * 16;
    uint32_t qah[4][4];
    #pragma unroll
    for (int ks = 0; ks < 4; ks++) {
        uint32_t ah = qhS + (uint32_t)(qrow0 + (lane & 15)) * FRB + ks * 32 + (lane >> 4) * 16;
        ldsm_x4(ah, qah[ks][0], qah[ks][1], qah[ks][2], qah[ks][3]);
    }

    float Oa[8][4];
    #pragma unroll
    for (int nt = 0; nt < 8; nt++)
        #pragma unroll
        for (int f = 0; f < 4; f++) Oa[nt][f] = 0.0f;
    float mrow[2] = {0.0f, 0.0f};       // raw (x16) units; sink score 0
    float lrow[2] = {256.0f, 256.0f};   // x256 scale; sink exp(0)*256

    for (int jt = 0; jt <= qb; jt++) {
        const int s = jt & 1;
        if (jt < qb) {
            uint32_t base = sb + QT_B + (s ^ 1) * STG_B;
            const int j1 = (jt + 1) * 64;
            #pragma unroll
            for (int u = 0; u < 4; u++) {
                int lin = tid + u * 128; int row = lin >> 3, seg = lin & 7;
                CP_ASYNC16(base + row * FRB + seg * 16,
                           khp + (size_t)(j1 + row) * DH + seg * 8);
                CP_ASYNC16(base + QT_B + row * FRB + seg * 16,
                           vhp + (size_t)row * SEQ + j1 + seg * 8);
            }
            CP_COMMIT();
            CP_WAIT(1);
        } else {
            CP_WAIT(0);
        }
        __syncthreads();

        const uint32_t st = sb + QT_B + s * STG_B;
        const uint32_t khT = st, vhT = st + QT_B;

        // ---- S = Qh Kh^T (raw x16 units) ----
        float S[8][4];
        #pragma unroll
        for (int nt = 0; nt < 8; nt++)
            #pragma unroll
            for (int f = 0; f < 4; f++) S[nt][f] = 0.0f;

        #pragma unroll
        for (int ks = 0; ks < 4; ks++) {
            uint32_t kh4[16];
            #pragma unroll
            for (int p = 0; p < 4; p++)
                ldsm_b(khT, p * 16, ks * 32, lane, kh4 + p * 4);
            #pragma unroll
            for (int nt = 0; nt < 8; nt++)
                mma16816(S[nt], qah[ks][0], qah[ks][1], qah[ks][2], qah[ks][3],
                         kh4[2 * nt], kh4[2 * nt + 1]);
        }

        if (jt == qb) {
            const int j0 = jt * 64;
            #pragma unroll
            for (int nt = 0; nt < 8; nt++) {
                #pragma unroll
                for (int e = 0; e < 4; e++) {
                    int grow = q0 + qrow0 + (lane >> 2) + ((e >= 2) ? 8 : 0);
                    int gcol = j0 + nt * 8 + (lane & 3) * 2 + (e & 1);
                    if (gcol > grow) S[nt][e] = -1e30f;
                }
            }
        }

        // ---- online softmax (folded: 1 FMA + exp2 per score) ----
        #pragma unroll
        for (int i = 0; i < 2; i++) {
            float rm = -1e30f;
            #pragma unroll
            for (int nt = 0; nt < 8; nt++)
                rm = fmaxf(rm, fmaxf(S[nt][2 * i], S[nt][2 * i + 1]));
            rm = fmaxf(rm, __shfl_xor_sync(0xffffffffu, rm, 1));
            rm = fmaxf(rm, __shfl_xor_sync(0xffffffffu, rm, 2));
            float mn = fmaxf(mrow[i], rm);
            float alpha = exp2f((mrow[i] - mn) * C2F);
            float bfold = 8.0f - mn * C2F;    // exp2(S*C2 + bfold) = 256*exp(s - m)
            float rs = 0.0f;
            #pragma unroll
            for (int nt = 0; nt < 8; nt++) {
                float p0 = exp2f(fmaf(S[nt][2 * i],     C2F, bfold));
                float p1 = exp2f(fmaf(S[nt][2 * i + 1], C2F, bfold));
                S[nt][2 * i] = p0; S[nt][2 * i + 1] = p1;
                rs += p0 + p1;
            }
            rs += __shfl_xor_sync(0xffffffffu, rs, 1);
            rs += __shfl_xor_sync(0xffffffffu, rs, 2);
            lrow[i] = lrow[i] * alpha + rs;
            mrow[i] = mn;
            #pragma unroll
            for (int nt = 0; nt < 8; nt++) {
                Oa[nt][2 * i]     *= alpha;
                Oa[nt][2 * i + 1] *= alpha;
            }
        }

        // ---- O += P_scaled Vh (P already x256 from the exponent fold) ----
        #pragma unroll
        for (int ks = 0; ks < 4; ks++) {
            uint32_t ah0 = packh(S[2 * ks][0],     S[2 * ks][1]);
            uint32_t ah1 = packh(S[2 * ks][2],     S[2 * ks][3]);
            uint32_t ah2 = packh(S[2 * ks + 1][0], S[2 * ks + 1][1]);
            uint32_t ah3 = packh(S[2 * ks + 1][2], S[2 * ks + 1][3]);
            uint32_t vh4[16];
            #pragma unroll
            for (int p = 0; p < 4; p++)
                ldsm_b(vhT, p * 16, ks * 32, lane, vh4 + p * 4);
            #pragma unroll
            for (int nt = 0; nt < 8; nt++)
                mma16816(Oa[nt], ah0, ah1, ah2, ah3, vh4[2 * nt], vh4[2 * nt + 1]);
        }
        __syncthreads();
    }

    // ---- epilogue: O = Oa / lrow (scale cancels), store fp16 [s,b,D] ----
    const float inv0 = 1.0f / lrow[0];
    const float inv1 = 1.0f / lrow[1];
    const int r = lane >> 2, c2 = (lane & 3) * 2;
    const int srow0 = q0 + qrow0 + r;
    #pragma unroll
    for (int nt = 0; nt < 8; nt++) {
        int col = h * 64 + nt * 8 + c2;
        float o00 = Oa[nt][0] * inv0, o01 = Oa[nt][1] * inv0;
        float o10 = Oa[nt][2] * inv1, o11 = Oa[nt][3] * inv1;
        size_t off0 = ((size_t)srow0 * BB + b) * DD + col;
        size_t off1 = ((size_t)(srow0 + 8) * BB + b) * DD + col;
        *(uint32_t*)(ah_g + off0) = packh(o00, o01);
        *(uint32_t*)(ah_g + off1) = packh(o10, o11);
    }
}

// ---------------------------------------------------------------------------
extern "C" void kernel_launch(void* const* d_in, const int* in_sizes, int n_in,
                              void* d_out, int out_size)
{
    const float* x    = (const float*)d_in[0];
    const float* beta = (const float*)d_in[2];
    const float* Wq   = (const float*)d_in[3];
    const float* bq   = (const float*)d_in[4];
    const float* Wk   = (const float*)d_in[5];
    const float* bk   = (const float*)d_in[6];
    const float* Wv   = (const float*)d_in[7];
    const float* bv   = (const float*)d_in[8];
    const float* Wo   = (const float*)d_in[9];
    const float* bo   = (const float*)d_in[10];
    float* out = (float*)d_out;

    __half *xh, *qh, *kh, *vh, *ah;
    cudaGetSymbolAddress((void**)&xh, g_xh);
    cudaGetSymbolAddress((void**)&qh, g_qh);
    cudaGetSymbolAddress((void**)&kh, g_kh);
    cudaGetSymbolAddress((void**)&vh, g_vh);
    cudaGetSymbolAddress((void**)&ah, g_ah);

    int nsm = 148;
    cudaDeviceGetAttribute(&nsm, cudaDevAttrMultiProcessorCount, 0);
    const int pgrid = 3 * nsm;   // persistent GEMM grid (3 CTAs/SM)

    cudaFuncSetAttribute(gemm_qkv_kernel,
                         cudaFuncAttributeMaxDynamicSharedMemorySize, GEMM_SMEM);
    cudaFuncSetAttribute(gemm_out_kernel,
                         cudaFuncAttributeMaxDynamicSharedMemorySize, GEMM_SMEM);
    cudaFuncSetAttribute(flash_mma_kernel,
                         cudaFuncAttributeMaxDynamicSharedMemorySize, FLASH_SMEM);

    const int nx4 = MM * DD / 4;
    const int nw4 = DD * DD / 4;

    convx_kernel<<<(nx4 + 255) / 256, 256>>>(x, xh, nx4);
    {
        dim3 sg((nw4 + 255) / 256, 4);
        split4_kernel<<<sg, 256>>>(Wq, Wk, Wv, Wo, nw4);
    }

    gemm_qkv_kernel<<<pgrid, 256, GEMM_SMEM>>>(beta, bq, bk, bv);

    dim3 fgrid(SEQ / 64, HH, BB);   // (32, 16, 4)
    flash_mma_kernel<<<fgrid, 128, FLASH_SMEM>>>(qh, kh, vh, ah);

    gemm_out_kernel<<<pgrid, 256, GEMM_SMEM>>>(bo, out);
}

// round 13
// speedup vs baseline: 6.9119x; 1.1242x over previous
#include <cuda_runtime.h>
#include <cuda_fp16.h>
#include <stdint.h>
#include <math.h>

// Problem constants
#define SEQ 2048
#define BB  4
#define DD  1024
#define HH  16
#define DH  64
#define MM  (SEQ*BB)

// ---------------- scratch (device globals; allocation-free) ----------------
__device__ __half g_xh[MM*DD];
__device__ __half g_wqh[DD*DD], g_wkh[DD*DD], g_wvh[DD*DD], g_woh[DD*DD];
__device__ __half g_qh[MM*DD];   // scaled x16 incl beta, [b,h,s,dh]
__device__ __half g_kh[MM*DD];   // [b,h,s,dh]
__device__ __half g_vh[MM*DD];   // transposed [b,h,dh,s]
__device__ __half g_ah[MM*DD];   // att output [s,b,D]

// ---------------- PTX helpers (baseline ISA only) ----------------
static __device__ __forceinline__ uint32_t s2u(const void* p) {
    return (uint32_t)__cvta_generic_to_shared(p);
}

#define CP_ASYNC16(saddr, gptr) \
    asm volatile("cp.async.cg.shared.global [%0], [%1], 16;" :: "r"(saddr), "l"(gptr))
#define CP_COMMIT() asm volatile("cp.async.commit_group;" ::: "memory")
#define CP_WAIT(n)  asm volatile("cp.async.wait_group %0;" :: "n"(n) : "memory")

static __device__ __forceinline__ void ldsm_x4(uint32_t addr,
    uint32_t &r0, uint32_t &r1, uint32_t &r2, uint32_t &r3)
{
    asm volatile("ldmatrix.sync.aligned.m8n8.x4.shared.b16 {%0,%1,%2,%3}, [%4];"
        : "=r"(r0), "=r"(r1), "=r"(r2), "=r"(r3) : "r"(addr));
}

static __device__ __forceinline__ void mma16816(float* d,
    uint32_t a0, uint32_t a1, uint32_t a2, uint32_t a3, uint32_t b0, uint32_t b1)
{
    asm volatile("mma.sync.aligned.m16n8k16.row.col.f32.f16.f16.f32 "
        "{%0,%1,%2,%3}, {%4,%5,%6,%7}, {%8,%9}, {%0,%1,%2,%3};"
        : "+f"(d[0]), "+f"(d[1]), "+f"(d[2]), "+f"(d[3])
        : "r"(a0), "r"(a1), "r"(a2), "r"(a3), "r"(b0), "r"(b1));
}

static __device__ __forceinline__ uint32_t packh(float x, float y) {
    __half2 t = __floats2half2_rn(x, y);
    return *(uint32_t*)&t;
}

// ---------------- conversion kernels ----------------
__global__ void convx_kernel(const float* __restrict__ src,
                             __half* __restrict__ hi, int n4)
{
    int i = blockIdx.x * blockDim.x + threadIdx.x;
    if (i >= n4) return;
    float4 v = ((const float4*)src)[i];
    uint2 o;
    o.x = packh(v.x, v.y);
    o.y = packh(v.z, v.w);
    ((uint2*)hi)[i] = o;
}

__global__ void split4_kernel(const float* __restrict__ s0, const float* __restrict__ s1,
                              const float* __restrict__ s2, const float* __restrict__ s3,
                              int n4)
{
    int i = blockIdx.x * blockDim.x + threadIdx.x;
    if (i >= n4) return;
    const float* src; __half* hi;
    switch (blockIdx.y) {
        case 0:  src = s0; hi = g_wqh; break;
        case 1:  src = s1; hi = g_wkh; break;
        case 2:  src = s2; hi = g_wvh; break;
        default: src = s3; hi = g_woh; break;
    }
    float4 v = ((const float4*)src)[i];
    uint2 oh;
    oh.x = packh(v.x * 64.0f, v.y * 64.0f);
    oh.y = packh(v.z * 64.0f, v.w * 64.0f);
    ((uint2*)hi)[i] = oh;
}

// ---------------------------------------------------------------------------
// HMMA GEMM body (1-pass fp16): C = A[M,K] @ Bh[N,K]^T  (B pre-scaled x64).
// CTA tile 128(M)x64(N), 8 warps of 32x32, K-chunks of 64 (4 k16 steps).
// Descale 1/64 + bias in epilogue.
// mode 0: fp32 out [s,b,D]
// mode 1: fp16 out [b,h,s,dh], scaled by 2*exp(-beta_h)
// mode 2: fp16 out transposed [b,h,dh,s]
// mode 3: fp16 out [b,h,s,dh]
// ---------------------------------------------------------------------------
#define GBK 64
#define NCG (DD / GBK)            // 16
#define RSMEM 144                 // 128 B data + 16 B pad (4-bank row shift)
#define A_T (128 * RSMEM)         // 18432
#define B_T (64 * RSMEM)          // 9216
#define BUF_B (A_T + B_T)         // 27648
#define GEMM_SMEM (2 * BUF_B)     // 55296

static __device__ __forceinline__ void gemm_load_chunk(
    const __half* __restrict__ A, const __half* __restrict__ Bhi,
    int bm, int bn, int k0, uint32_t sa_base, int tid)
{
    const __half* ga = A   + (size_t)bm * DD + k0;
    const __half* gb = Bhi + (size_t)bn * DD + k0;
    #pragma unroll
    for (int u = 0; u < 4; u++) {
        int idx = tid + u * 256;           // 0..1023
        int row = idx >> 3, seg = idx & 7;
        CP_ASYNC16(sa_base + row * RSMEM + seg * 16,
                   ga + (size_t)row * DD + seg * 8);
    }
    #pragma unroll
    for (int u = 0; u < 2; u++) {
        int idx = tid + u * 256;           // 0..511
        int row = idx >> 3, seg = idx & 7;
        CP_ASYNC16(sa_base + A_T + row * RSMEM + seg * 16,
                   gb + (size_t)row * DD + seg * 8);
    }
}

static __device__ __forceinline__ void gemm_body(
    const __half* __restrict__ A, const __half* __restrict__ Bhi,
    const float* __restrict__ bias, int mode,
    const float* __restrict__ beta,
    float* __restrict__ C, __half* __restrict__ Oh,
    int bn, int bm, char* smc)
{
    const int tid  = threadIdx.x;
    const int wid  = tid >> 5;
    const int lane = tid & 31;
    const uint32_t sb = s2u(smc);

    const int m0 = (wid >> 1) * 32;
    const int n0 = (wid & 1) * 32;

    gemm_load_chunk(A, Bhi, bm, bn, 0, sb, tid);
    CP_COMMIT();

    float acc[2][4][4];
    #pragma unroll
    for (int mi = 0; mi < 2; mi++)
        #pragma unroll
        for (int ni = 0; ni < 4; ni++)
            #pragma unroll
            for (int f = 0; f < 4; f++) acc[mi][ni][f] = 0.0f;

    for (int c = 0; c < NCG; c++) {
        if (c + 1 < NCG) {
            gemm_load_chunk(A, Bhi, bm, bn, (c + 1) * GBK,
                            sb + ((c + 1) & 1) * BUF_B, tid);
            CP_COMMIT();
            CP_WAIT(1);
        } else {
            CP_WAIT(0);
        }
        __syncthreads();

        const uint32_t bufo = (c & 1) * BUF_B;
        const uint32_t AT  = sb + bufo;
        const uint32_t BhT = AT + A_T;

        #pragma unroll
        for (int s = 0; s < 4; s++) {
            const uint32_t kb = s * 32;
            uint32_t bh[4][2], ah[2][4];
            {
                int g = lane >> 3;
                int ntl = g >> 1, half = g & 1;
                uint32_t boff = (uint32_t)(n0 + ntl * 8 + (lane & 7)) * RSMEM
                              + kb + half * 16;
                ldsm_x4(BhT + boff,              bh[0][0], bh[0][1], bh[1][0], bh[1][1]);
                ldsm_x4(BhT + boff + 16 * RSMEM, bh[2][0], bh[2][1], bh[3][0], bh[3][1]);
            }
            #pragma unroll
            for (int mi = 0; mi < 2; mi++) {
                uint32_t aoff = (uint32_t)(m0 + mi * 16 + (lane & 15)) * RSMEM
                              + kb + (lane >> 4) * 16;
                ldsm_x4(AT + aoff, ah[mi][0], ah[mi][1], ah[mi][2], ah[mi][3]);
            }
            #pragma unroll
            for (int mi = 0; mi < 2; mi++)
                #pragma unroll
                for (int ni = 0; ni < 4; ni++)
                    mma16816(acc[mi][ni], ah[mi][0], ah[mi][1], ah[mi][2], ah[mi][3],
                             bh[ni][0], bh[ni][1]);
        }
        __syncthreads();
    }

    const float DS = 1.0f / 64.0f;
    const int erow = lane >> 2;
    const int ecol = (lane & 3) * 2;
    #pragma unroll
    for (int mi = 0; mi < 2; mi++) {
        #pragma unroll
        for (int ni = 0; ni < 4; ni++) {
            int gr = bm + m0 + mi * 16 + erow;
            int gc = bn + n0 + ni * 8 + ecol;
            float v0x = acc[mi][ni][0] * DS + bias[gc];
            float v0y = acc[mi][ni][1] * DS + bias[gc + 1];
            float v1x = acc[mi][ni][2] * DS + bias[gc];
            float v1y = acc[mi][ni][3] * DS + bias[gc + 1];
            if (mode == 0) {
                float2 a = {v0x, v0y}, bb2 = {v1x, v1y};
                *(float2*)(C + (size_t)gr * DD + gc)       = a;
                *(float2*)(C + (size_t)(gr + 8) * DD + gc) = bb2;
            } else {
                int hh = gc >> 6, dh = gc & 63;
                int s0 = gr >> 2, bbi = gr & 3;
                if (mode == 1 || mode == 3) {
                    if (mode == 1) {
                        float f = 2.0f * __expf(-beta[hh]);
                        v0x *= f; v0y *= f; v1x *= f; v1y *= f;
                    }
                    size_t off0 = (((size_t)bbi * HH + hh) * SEQ + s0) * DH + dh;
                    size_t off1 = off0 + 2 * DH;
                    *(uint32_t*)(Oh + off0) = packh(v0x, v0y);
                    *(uint32_t*)(Oh + off1) = packh(v1x, v1y);
                } else {
                    size_t off = (((size_t)bbi * HH + hh) * DH + dh) * SEQ + s0;
                    Oh[off]           = __float2half_rn(v0x);
                    Oh[off + SEQ]     = __float2half_rn(v0y);
                    Oh[off + 2]       = __float2half_rn(v1x);
                    Oh[off + SEQ + 2] = __float2half_rn(v1y);
                }
            }
        }
    }
}

// Fused Q/K/V projection (non-persistent; blockIdx.z selects tensor)
__global__ __launch_bounds__(256, 3)
void gemm_qkv_kernel(const float* __restrict__ beta,
                     const float* __restrict__ bq,
                     const float* __restrict__ bk,
                     const float* __restrict__ bv)
{
    extern __shared__ char smc[];
    const int bn = blockIdx.x * 64;
    const int bm = blockIdx.y * 128;
    if (blockIdx.z == 0)
        gemm_body(g_xh, g_wqh, bq, 1, beta, nullptr, g_qh, bn, bm, smc);
    else if (blockIdx.z == 1)
        gemm_body(g_xh, g_wkh, bk, 3, nullptr, nullptr, g_kh, bn, bm, smc);
    else
        gemm_body(g_xh, g_wvh, bv, 2, nullptr, nullptr, g_vh, bn, bm, smc);
}

// Output projection (non-persistent)
__global__ __launch_bounds__(256, 3)
void gemm_out_kernel(const float* __restrict__ bo, float* __restrict__ out)
{
    extern __shared__ char smc[];
    const int bn = blockIdx.x * 64;
    const int bm = blockIdx.y * 128;
    gemm_body(g_ah, g_woh, bo, 0, nullptr, out, nullptr, bn, bm, smc);
}

// ---------------------------------------------------------------------------
// Flash attention (unchanged from R12): S raw x16; folded softmax
//   p_scaled(=p*256) = exp2(S*C2 + (8 - m*C2)); lrow carries x256 (sink 256).
// Block 128 thr / 4 warps, 64 Q rows, LPT order. smem 45 KB.
// ---------------------------------------------------------------------------
#define FRB 144
#define QT_B (64 * FRB)            // 9216
#define STG_B (2 * QT_B)           // 18432
#define FLASH_SMEM (QT_B + 2 * STG_B)   // 46080
#define C2F 0.0901684856755f       // 0.0625 * log2(e)

static __device__ __forceinline__ void ldsm_b(uint32_t tile, int nbase, int ksb,
                                              int lane, uint32_t* r4)
{
    int g = lane >> 3, ntl = g >> 1, half = g & 1;
    uint32_t addr = tile + (uint32_t)(nbase + ntl * 8 + (lane & 7)) * FRB
                  + ksb + half * 16;
    ldsm_x4(addr, r4[0], r4[1], r4[2], r4[3]);
}

__global__ __launch_bounds__(128, 3)
void flash_mma_kernel(const __half* __restrict__ qh_g,
                      const __half* __restrict__ kh_g,
                      const __half* __restrict__ vh_g,
                      __half* __restrict__ ah_g)
{
    extern __shared__ char smf[];
    const int tid = threadIdx.x, lane = tid & 31, wid = tid >> 5;
    const int qb = (int)gridDim.x - 1 - (int)blockIdx.x;
    const int h = blockIdx.y, b = blockIdx.z;
    const int q0 = qb * 64;
    const uint32_t sb = s2u(smf);
    const uint32_t qhS = sb;

    const size_t bh = (size_t)b * HH + h;
    const char* qhp = (const char*)(qh_g + (bh * SEQ + q0) * DH);
    const __half* khp = kh_g + bh * SEQ * DH;
    const __half* vhp = vh_g + bh * (size_t)DH * SEQ;

    #pragma unroll
    for (int u = 0; u < 4; u++) {
        int lin = tid + u * 128; int row = lin >> 3, seg = lin & 7;
        CP_ASYNC16(qhS + row * FRB + seg * 16, qhp + row * 128 + seg * 16);
    }
    CP_COMMIT();

    {
        uint32_t base = sb + QT_B;
        #pragma unroll
        for (int u = 0; u < 4; u++) {
            int lin = tid + u * 128; int row = lin >> 3, seg = lin & 7;
            CP_ASYNC16(base + row * FRB + seg * 16, khp + (size_t)row * DH + seg * 8);
            CP_ASYNC16(base + QT_B + row * FRB + seg * 16, vhp + (size_t)row * SEQ + seg * 8);
        }
        CP_COMMIT();
    }
    CP_WAIT(0);
    __syncthreads();

    const int qrow0 = wid * 16;
    uint32_t qah[4][4];
    #pragma unroll
    for (int ks = 0; ks < 4; ks++) {
        uint32_t ah = qhS + (uint32_t)(qrow0 + (lane & 15)) * FRB + ks * 32 + (lane >> 4) * 16;
        ldsm_x4(ah, qah[ks][0], qah[ks][1], qah[ks][2], qah[ks][3]);
    }

    float Oa[8][4];
    #pragma unroll
    for (int nt = 0; nt < 8; nt++)
        #pragma unroll
        for (int f = 0; f < 4; f++) Oa[nt][f] = 0.0f;
    float mrow[2] = {0.0f, 0.0f};       // raw (x16) units; sink score 0
    float lrow[2] = {256.0f, 256.0f};   // x256 scale; sink exp(0)*256

    for (int jt = 0; jt <= qb; jt++) {
        const int s = jt & 1;
        if (jt < qb) {
            uint32_t base = sb + QT_B + (s ^ 1) * STG_B;
            const int j1 = (jt + 1) * 64;
            #pragma unroll
            for (int u = 0; u < 4; u++) {
                int lin = tid + u * 128; int row = lin >> 3, seg = lin & 7;
                CP_ASYNC16(base + row * FRB + seg * 16,
                           khp + (size_t)(j1 + row) * DH + seg * 8);
                CP_ASYNC16(base + QT_B + row * FRB + seg * 16,
                           vhp + (size_t)row * SEQ + j1 + seg * 8);
            }
            CP_COMMIT();
            CP_WAIT(1);
        } else {
            CP_WAIT(0);
        }
        __syncthreads();

        const uint32_t st = sb + QT_B + s * STG_B;
        const uint32_t khT = st, vhT = st + QT_B;

        // ---- S = Qh Kh^T (raw x16 units) ----
        float S[8][4];
        #pragma unroll
        for (int nt = 0; nt < 8; nt++)
            #pragma unroll
            for (int f = 0; f < 4; f++) S[nt][f] = 0.0f;

        #pragma unroll
        for (int ks = 0; ks < 4; ks++) {
            uint32_t kh4[16];
            #pragma unroll
            for (int p = 0; p < 4; p++)
                ldsm_b(khT, p * 16, ks * 32, lane, kh4 + p * 4);
            #pragma unroll
            for (int nt = 0; nt < 8; nt++)
                mma16816(S[nt], qah[ks][0], qah[ks][1], qah[ks][2], qah[ks][3],
                         kh4[2 * nt], kh4[2 * nt + 1]);
        }

        if (jt == qb) {
            const int j0 = jt * 64;
            #pragma unroll
            for (int nt = 0; nt < 8; nt++) {
                #pragma unroll
                for (int e = 0; e < 4; e++) {
                    int grow = q0 + qrow0 + (lane >> 2) + ((e >= 2) ? 8 : 0);
                    int gcol = j0 + nt * 8 + (lane & 3) * 2 + (e & 1);
                    if (gcol > grow) S[nt][e] = -1e30f;
                }
            }
        }

        // ---- online softmax (folded: 1 FMA + exp2 per score) ----
        #pragma unroll
        for (int i = 0; i < 2; i++) {
            float rm = -1e30f;
            #pragma unroll
            for (int nt = 0; nt < 8; nt++)
                rm = fmaxf(rm, fmaxf(S[nt][2 * i], S[nt][2 * i + 1]));
            rm = fmaxf(rm, __shfl_xor_sync(0xffffffffu, rm, 1));
            rm = fmaxf(rm, __shfl_xor_sync(0xffffffffu, rm, 2));
            float mn = fmaxf(mrow[i], rm);
            float alpha = exp2f((mrow[i] - mn) * C2F);
            float bfold = 8.0f - mn * C2F;
            float rs = 0.0f;
            #pragma unroll
            for (int nt = 0; nt < 8; nt++) {
                float p0 = exp2f(fmaf(S[nt][2 * i],     C2F, bfold));
                float p1 = exp2f(fmaf(S[nt][2 * i + 1], C2F, bfold));
                S[nt][2 * i] = p0; S[nt][2 * i + 1] = p1;
                rs += p0 + p1;
            }
            rs += __shfl_xor_sync(0xffffffffu, rs, 1);
            rs += __shfl_xor_sync(0xffffffffu, rs, 2);
            lrow[i] = lrow[i] * alpha + rs;
            mrow[i] = mn;
            #pragma unroll
            for (int nt = 0; nt < 8; nt++) {
                Oa[nt][2 * i]     *= alpha;
                Oa[nt][2 * i + 1] *= alpha;
            }
        }

        // ---- O += P_scaled Vh ----
        #pragma unroll
        for (int ks = 0; ks < 4; ks++) {
            uint32_t ah0 = packh(S[2 * ks][0],     S[2 * ks][1]);
            uint32_t ah1 = packh(S[2 * ks][2],     S[2 * ks][3]);
            uint32_t ah2 = packh(S[2 * ks + 1][0], S[2 * ks + 1][1]);
            uint32_t ah3 = packh(S[2 * ks + 1][2], S[2 * ks + 1][3]);
            uint32_t vh4[16];
            #pragma unroll
            for (int p = 0; p < 4; p++)
                ldsm_b(vhT, p * 16, ks * 32, lane, vh4 + p * 4);
            #pragma unroll
            for (int nt = 0; nt < 8; nt++)
                mma16816(Oa[nt], ah0, ah1, ah2, ah3, vh4[2 * nt], vh4[2 * nt + 1]);
        }
        __syncthreads();
    }

    // ---- epilogue ----
    const float inv0 = 1.0f / lrow[0];
    const float inv1 = 1.0f / lrow[1];
    const int r = lane >> 2, c2 = (lane & 3) * 2;
    const int srow0 = q0 + qrow0 + r;
    #pragma unroll
    for (int nt = 0; nt < 8; nt++) {
        int col = h * 64 + nt * 8 + c2;
        float o00 = Oa[nt][0] * inv0, o01 = Oa[nt][1] * inv0;
        float o10 = Oa[nt][2] * inv1, o11 = Oa[nt][3] * inv1;
        size_t off0 = ((size_t)srow0 * BB + b) * DD + col;
        size_t off1 = ((size_t)(srow0 + 8) * BB + b) * DD + col;
        *(uint32_t*)(ah_g + off0) = packh(o00, o01);
        *(uint32_t*)(ah_g + off1) = packh(o10, o11);
    }
}

// ---------------------------------------------------------------------------
extern "C" void kernel_launch(void* const* d_in, const int* in_sizes, int n_in,
                              void* d_out, int out_size)
{
    const float* x    = (const float*)d_in[0];
    const float* beta = (const float*)d_in[2];
    const float* Wq   = (const float*)d_in[3];
    const float* bq   = (const float*)d_in[4];
    const float* Wk   = (const float*)d_in[5];
    const float* bk   = (const float*)d_in[6];
    const float* Wv   = (const float*)d_in[7];
    const float* bv   = (const float*)d_in[8];
    const float* Wo   = (const float*)d_in[9];
    const float* bo   = (const float*)d_in[10];
    float* out = (float*)d_out;

    __half *xh, *qh, *kh, *vh, *ah;
    cudaGetSymbolAddress((void**)&xh, g_xh);
    cudaGetSymbolAddress((void**)&qh, g_qh);
    cudaGetSymbolAddress((void**)&kh, g_kh);
    cudaGetSymbolAddress((void**)&vh, g_vh);
    cudaGetSymbolAddress((void**)&ah, g_ah);

    cudaFuncSetAttribute(gemm_qkv_kernel,
                         cudaFuncAttributeMaxDynamicSharedMemorySize, GEMM_SMEM);
    cudaFuncSetAttribute(gemm_out_kernel,
                         cudaFuncAttributeMaxDynamicSharedMemorySize, GEMM_SMEM);
    cudaFuncSetAttribute(flash_mma_kernel,
                         cudaFuncAttributeMaxDynamicSharedMemorySize, FLASH_SMEM);

    const int nx4 = MM * DD / 4;
    const int nw4 = DD * DD / 4;

    convx_kernel<<<(nx4 + 255) / 256, 256>>>(x, xh, nx4);
    {
        dim3 sg((nw4 + 255) / 256, 4);
        split4_kernel<<<sg, 256>>>(Wq, Wk, Wv, Wo, nw4);
    }

    dim3 qkvgrid(DD / 64, MM / 128, 3);   // (16, 64, 3)
    gemm_qkv_kernel<<<qkvgrid, 256, GEMM_SMEM>>>(beta, bq, bk, bv);

    dim3 fgrid(SEQ / 64, HH, BB);   // (32, 16, 4)
    flash_mma_kernel<<<fgrid, 128, FLASH_SMEM>>>(qh, kh, vh, ah);

    dim3 ogrid(DD / 64, MM / 128);   // (16, 64)
    gemm_out_kernel<<<ogrid, 256, GEMM_SMEM>>>(bo, out);
}

// round 14
// speedup vs baseline: 7.0867x; 1.0253x over previous
#include <cuda_runtime.h>
#include <cuda_fp16.h>
#include <stdint.h>
#include <math.h>

// Problem constants
#define SEQ 2048
#define BB  4
#define DD  1024
#define HH  16
#define DH  64
#define MM  (SEQ*BB)

// ---------------- scratch (device globals; allocation-free) ----------------
__device__ __half g_xh[MM*DD];
__device__ __half g_wqh[DD*DD], g_wkh[DD*DD], g_wvh[DD*DD], g_woh[DD*DD];
__device__ __half g_qh[MM*DD];   // scaled x16 incl beta, [b,h,s,dh]
__device__ __half g_kh[MM*DD];   // [b,h,s,dh]
__device__ __half g_vh[MM*DD];   // transposed [b,h,dh,s]
__device__ __half g_ah[MM*DD];   // att output [s,b,D]

// ---------------- PTX helpers (baseline ISA only) ----------------
static __device__ __forceinline__ uint32_t s2u(const void* p) {
    return (uint32_t)__cvta_generic_to_shared(p);
}

#define CP_ASYNC16(saddr, gptr) \
    asm volatile("cp.async.cg.shared.global [%0], [%1], 16;" :: "r"(saddr), "l"(gptr))
#define CP_COMMIT() asm volatile("cp.async.commit_group;" ::: "memory")
#define CP_WAIT(n)  asm volatile("cp.async.wait_group %0;" :: "n"(n) : "memory")

static __device__ __forceinline__ void ldsm_x4(uint32_t addr,
    uint32_t &r0, uint32_t &r1, uint32_t &r2, uint32_t &r3)
{
    asm volatile("ldmatrix.sync.aligned.m8n8.x4.shared.b16 {%0,%1,%2,%3}, [%4];"
        : "=r"(r0), "=r"(r1), "=r"(r2), "=r"(r3) : "r"(addr));
}

static __device__ __forceinline__ void mma16816(float* d,
    uint32_t a0, uint32_t a1, uint32_t a2, uint32_t a3, uint32_t b0, uint32_t b1)
{
    asm volatile("mma.sync.aligned.m16n8k16.row.col.f32.f16.f16.f32 "
        "{%0,%1,%2,%3}, {%4,%5,%6,%7}, {%8,%9}, {%0,%1,%2,%3};"
        : "+f"(d[0]), "+f"(d[1]), "+f"(d[2]), "+f"(d[3])
        : "r"(a0), "r"(a1), "r"(a2), "r"(a3), "r"(b0), "r"(b1));
}

static __device__ __forceinline__ uint32_t packh(float x, float y) {
    __half2 t = __floats2half2_rn(x, y);
    return *(uint32_t*)&t;
}

// ---------------- conversion kernels ----------------
__global__ void convx_kernel(const float* __restrict__ src,
                             __half* __restrict__ hi, int n4)
{
    int i = blockIdx.x * blockDim.x + threadIdx.x;
    if (i >= n4) return;
    float4 v = ((const float4*)src)[i];
    uint2 o;
    o.x = packh(v.x, v.y);
    o.y = packh(v.z, v.w);
    ((uint2*)hi)[i] = o;
}

__global__ void split4_kernel(const float* __restrict__ s0, const float* __restrict__ s1,
                              const float* __restrict__ s2, const float* __restrict__ s3,
                              int n4)
{
    int i = blockIdx.x * blockDim.x + threadIdx.x;
    if (i >= n4) return;
    const float* src; __half* hi;
    switch (blockIdx.y) {
        case 0:  src = s0; hi = g_wqh; break;
        case 1:  src = s1; hi = g_wkh; break;
        case 2:  src = s2; hi = g_wvh; break;
        default: src = s3; hi = g_woh; break;
    }
    float4 v = ((const float4*)src)[i];
    uint2 oh;
    oh.x = packh(v.x * 64.0f, v.y * 64.0f);
    oh.y = packh(v.z * 64.0f, v.w * 64.0f);
    ((uint2*)hi)[i] = oh;
}

// ---------------------------------------------------------------------------
// HMMA GEMM body (1-pass fp16): C = A[M,K] @ Bh[N,K]^T  (B pre-scaled x64).
// CTA tile 128(M)x64(N), 8 warps of 32x32, K-chunks of 64 (4 k16 steps).
// Descale 1/64 + bias in epilogue. (Unchanged from R13.)
// ---------------------------------------------------------------------------
#define GBK 64
#define NCG (DD / GBK)            // 16
#define RSMEM 144                 // 128 B data + 16 B pad
#define A_T (128 * RSMEM)         // 18432
#define B_T (64 * RSMEM)          // 9216
#define BUF_B (A_T + B_T)         // 27648
#define GEMM_SMEM (2 * BUF_B)     // 55296

static __device__ __forceinline__ void gemm_load_chunk(
    const __half* __restrict__ A, const __half* __restrict__ Bhi,
    int bm, int bn, int k0, uint32_t sa_base, int tid)
{
    const __half* ga = A   + (size_t)bm * DD + k0;
    const __half* gb = Bhi + (size_t)bn * DD + k0;
    #pragma unroll
    for (int u = 0; u < 4; u++) {
        int idx = tid + u * 256;
        int row = idx >> 3, seg = idx & 7;
        CP_ASYNC16(sa_base + row * RSMEM + seg * 16,
                   ga + (size_t)row * DD + seg * 8);
    }
    #pragma unroll
    for (int u = 0; u < 2; u++) {
        int idx = tid + u * 256;
        int row = idx >> 3, seg = idx & 7;
        CP_ASYNC16(sa_base + A_T + row * RSMEM + seg * 16,
                   gb + (size_t)row * DD + seg * 8);
    }
}

static __device__ __forceinline__ void gemm_body(
    const __half* __restrict__ A, const __half* __restrict__ Bhi,
    const float* __restrict__ bias, int mode,
    const float* __restrict__ beta,
    float* __restrict__ C, __half* __restrict__ Oh,
    int bn, int bm, char* smc)
{
    const int tid  = threadIdx.x;
    const int wid  = tid >> 5;
    const int lane = tid & 31;
    const uint32_t sb = s2u(smc);

    const int m0 = (wid >> 1) * 32;
    const int n0 = (wid & 1) * 32;

    gemm_load_chunk(A, Bhi, bm, bn, 0, sb, tid);
    CP_COMMIT();

    float acc[2][4][4];
    #pragma unroll
    for (int mi = 0; mi < 2; mi++)
        #pragma unroll
        for (int ni = 0; ni < 4; ni++)
            #pragma unroll
            for (int f = 0; f < 4; f++) acc[mi][ni][f] = 0.0f;

    for (int c = 0; c < NCG; c++) {
        if (c + 1 < NCG) {
            gemm_load_chunk(A, Bhi, bm, bn, (c + 1) * GBK,
                            sb + ((c + 1) & 1) * BUF_B, tid);
            CP_COMMIT();
            CP_WAIT(1);
        } else {
            CP_WAIT(0);
        }
        __syncthreads();

        const uint32_t bufo = (c & 1) * BUF_B;
        const uint32_t AT  = sb + bufo;
        const uint32_t BhT = AT + A_T;

        #pragma unroll
        for (int s = 0; s < 4; s++) {
            const uint32_t kb = s * 32;
            uint32_t bh[4][2], ah[2][4];
            {
                int g = lane >> 3;
                int ntl = g >> 1, half = g & 1;
                uint32_t boff = (uint32_t)(n0 + ntl * 8 + (lane & 7)) * RSMEM
                              + kb + half * 16;
                ldsm_x4(BhT + boff,              bh[0][0], bh[0][1], bh[1][0], bh[1][1]);
                ldsm_x4(BhT + boff + 16 * RSMEM, bh[2][0], bh[2][1], bh[3][0], bh[3][1]);
            }
            #pragma unroll
            for (int mi = 0; mi < 2; mi++) {
                uint32_t aoff = (uint32_t)(m0 + mi * 16 + (lane & 15)) * RSMEM
                              + kb + (lane >> 4) * 16;
                ldsm_x4(AT + aoff, ah[mi][0], ah[mi][1], ah[mi][2], ah[mi][3]);
            }
            #pragma unroll
            for (int mi = 0; mi < 2; mi++)
                #pragma unroll
                for (int ni = 0; ni < 4; ni++)
                    mma16816(acc[mi][ni], ah[mi][0], ah[mi][1], ah[mi][2], ah[mi][3],
                             bh[ni][0], bh[ni][1]);
        }
        __syncthreads();
    }

    const float DS = 1.0f / 64.0f;
    const int erow = lane >> 2;
    const int ecol = (lane & 3) * 2;
    #pragma unroll
    for (int mi = 0; mi < 2; mi++) {
        #pragma unroll
        for (int ni = 0; ni < 4; ni++) {
            int gr = bm + m0 + mi * 16 + erow;
            int gc = bn + n0 + ni * 8 + ecol;
            float v0x = acc[mi][ni][0] * DS + bias[gc];
            float v0y = acc[mi][ni][1] * DS + bias[gc + 1];
            float v1x = acc[mi][ni][2] * DS + bias[gc];
            float v1y = acc[mi][ni][3] * DS + bias[gc + 1];
            if (mode == 0) {
                float2 a = {v0x, v0y}, bb2 = {v1x, v1y};
                *(float2*)(C + (size_t)gr * DD + gc)       = a;
                *(float2*)(C + (size_t)(gr + 8) * DD + gc) = bb2;
            } else {
                int hh = gc >> 6, dh = gc & 63;
                int s0 = gr >> 2, bbi = gr & 3;
                if (mode == 1 || mode == 3) {
                    if (mode == 1) {
                        float f = 2.0f * __expf(-beta[hh]);
                        v0x *= f; v0y *= f; v1x *= f; v1y *= f;
                    }
                    size_t off0 = (((size_t)bbi * HH + hh) * SEQ + s0) * DH + dh;
                    size_t off1 = off0 + 2 * DH;
                    *(uint32_t*)(Oh + off0) = packh(v0x, v0y);
                    *(uint32_t*)(Oh + off1) = packh(v1x, v1y);
                } else {
                    size_t off = (((size_t)bbi * HH + hh) * DH + dh) * SEQ + s0;
                    Oh[off]           = __float2half_rn(v0x);
                    Oh[off + SEQ]     = __float2half_rn(v0y);
                    Oh[off + 2]       = __float2half_rn(v1x);
                    Oh[off + SEQ + 2] = __float2half_rn(v1y);
                }
            }
        }
    }
}

__global__ __launch_bounds__(256, 3)
void gemm_qkv_kernel(const float* __restrict__ beta,
                     const float* __restrict__ bq,
                     const float* __restrict__ bk,
                     const float* __restrict__ bv)
{
    extern __shared__ char smc[];
    const int bn = blockIdx.x * 64;
    const int bm = blockIdx.y * 128;
    if (blockIdx.z == 0)
        gemm_body(g_xh, g_wqh, bq, 1, beta, nullptr, g_qh, bn, bm, smc);
    else if (blockIdx.z == 1)
        gemm_body(g_xh, g_wkh, bk, 3, nullptr, nullptr, g_kh, bn, bm, smc);
    else
        gemm_body(g_xh, g_wvh, bv, 2, nullptr, nullptr, g_vh, bn, bm, smc);
}

__global__ __launch_bounds__(256, 3)
void gemm_out_kernel(const float* __restrict__ bo, float* __restrict__ out)
{
    extern __shared__ char smc[];
    const int bn = blockIdx.x * 64;
    const int bm = blockIdx.y * 128;
    gemm_body(g_ah, g_woh, bo, 0, nullptr, out, nullptr, bn, bm, smc);
}

// ---------------------------------------------------------------------------
// Flash attention, sink-anchored MAX-FREE softmax:
//   The zero-score sink is in every row => true row max in [0, ~8].
//   Fixed reference m0=10: p_scaled = 256*exp(s-10) = exp2(S*C2F + BFOLD),
//   one FMA+EX2 per score; no max tree, no alpha, no Oa rescale.
//   lrow = sum(p_scaled) incl sink (init 256*exp(-10)); O = Oa / lrow.
//   Masked scores S=-1e30 -> exp2(-inf) = 0 exactly.
// Block 128 thr / 4 warps, 64 Q rows, LPT order. smem 45 KB.
// ---------------------------------------------------------------------------
#define FRB 144
#define QT_B (64 * FRB)            // 9216
#define STG_B (2 * QT_B)           // 18432
#define FLASH_SMEM (QT_B + 2 * STG_B)   // 46080
#define C2F   0.0901684400556f     // 0.0625 * log2(e)
#define BFOLD (-6.4269504089f)     // 8 - 10*log2(e)
#define LSINK 0.0116223822f        // 256*exp(-10): sink's p_scaled

static __device__ __forceinline__ void ldsm_b(uint32_t tile, int nbase, int ksb,
                                              int lane, uint32_t* r4)
{
    int g = lane >> 3, ntl = g >> 1, half = g & 1;
    uint32_t addr = tile + (uint32_t)(nbase + ntl * 8 + (lane & 7)) * FRB
                  + ksb + half * 16;
    ldsm_x4(addr, r4[0], r4[1], r4[2], r4[3]);
}

__global__ __launch_bounds__(128, 3)
void flash_mma_kernel(const __half* __restrict__ qh_g,
                      const __half* __restrict__ kh_g,
                      const __half* __restrict__ vh_g,
                      __half* __restrict__ ah_g)
{
    extern __shared__ char smf[];
    const int tid = threadIdx.x, lane = tid & 31, wid = tid >> 5;
    const int qb = (int)gridDim.x - 1 - (int)blockIdx.x;
    const int h = blockIdx.y, b = blockIdx.z;
    const int q0 = qb * 64;
    const uint32_t sb = s2u(smf);
    const uint32_t qhS = sb;

    const size_t bh = (size_t)b * HH + h;
    const char* qhp = (const char*)(qh_g + (bh * SEQ + q0) * DH);
    const __half* khp = kh_g + bh * SEQ * DH;
    const __half* vhp = vh_g + bh * (size_t)DH * SEQ;

    #pragma unroll
    for (int u = 0; u < 4; u++) {
        int lin = tid + u * 128; int row = lin >> 3, seg = lin & 7;
        CP_ASYNC16(qhS + row * FRB + seg * 16, qhp + row * 128 + seg * 16);
    }
    CP_COMMIT();

    {
        uint32_t base = sb + QT_B;
        #pragma unroll
        for (int u = 0; u < 4; u++) {
            int lin = tid + u * 128; int row = lin >> 3, seg = lin & 7;
            CP_ASYNC16(base + row * FRB + seg * 16, khp + (size_t)row * DH + seg * 8);
            CP_ASYNC16(base + QT_B + row * FRB + seg * 16, vhp + (size_t)row * SEQ + seg * 8);
        }
        CP_COMMIT();
    }
    CP_WAIT(0);
    __syncthreads();

    const int qrow0 = wid * 16;
    uint32_t qah[4][4];
    #pragma unroll
    for (int ks = 0; ks < 4; ks++) {
        uint32_t ah = qhS + (uint32_t)(qrow0 + (lane & 15)) * FRB + ks * 32 + (lane >> 4) * 16;
        ldsm_x4(ah, qah[ks][0], qah[ks][1], qah[ks][2], qah[ks][3]);
    }

    float Oa[8][4];
    #pragma unroll
    for (int nt = 0; nt < 8; nt++)
        #pragma unroll
        for (int f = 0; f < 4; f++) Oa[nt][f] = 0.0f;
    float lrow[2] = {LSINK, LSINK};   // sink contribution

    for (int jt = 0; jt <= qb; jt++) {
        const int s = jt & 1;
        if (jt < qb) {
            uint32_t base = sb + QT_B + (s ^ 1) * STG_B;
            const int j1 = (jt + 1) * 64;
            #pragma unroll
            for (int u = 0; u < 4; u++) {
                int lin = tid + u * 128; int row = lin >> 3, seg = lin & 7;
                CP_ASYNC16(base + row * FRB + seg * 16,
                           khp + (size_t)(j1 + row) * DH + seg * 8);
                CP_ASYNC16(base + QT_B + row * FRB + seg * 16,
                           vhp + (size_t)row * SEQ + j1 + seg * 8);
            }
            CP_COMMIT();
            CP_WAIT(1);
        } else {
            CP_WAIT(0);
        }
        __syncthreads();

        const uint32_t st = sb + QT_B + s * STG_B;
        const uint32_t khT = st, vhT = st + QT_B;

        // ---- S = Qh Kh^T (raw x16 units) ----
        float S[8][4];
        #pragma unroll
        for (int nt = 0; nt < 8; nt++)
            #pragma unroll
            for (int f = 0; f < 4; f++) S[nt][f] = 0.0f;

        #pragma unroll
        for (int ks = 0; ks < 4; ks++) {
            uint32_t kh4[16];
            #pragma unroll
            for (int p = 0; p < 4; p++)
                ldsm_b(khT, p * 16, ks * 32, lane, kh4 + p * 4);
            #pragma unroll
            for (int nt = 0; nt < 8; nt++)
                mma16816(S[nt], qah[ks][0], qah[ks][1], qah[ks][2], qah[ks][3],
                         kh4[2 * nt], kh4[2 * nt + 1]);
        }

        if (jt == qb) {
            const int j0 = jt * 64;
            #pragma unroll
            for (int nt = 0; nt < 8; nt++) {
                #pragma unroll
                for (int e = 0; e < 4; e++) {
                    int grow = q0 + qrow0 + (lane >> 2) + ((e >= 2) ? 8 : 0);
                    int gcol = j0 + nt * 8 + (lane & 3) * 2 + (e & 1);
                    if (gcol > grow) S[nt][e] = -1e30f;
                }
            }
        }

        // ---- max-free softmax: p_scaled = exp2(S*C2F + BFOLD) ----
        #pragma unroll
        for (int i = 0; i < 2; i++) {
            float rs = 0.0f;
            #pragma unroll
            for (int nt = 0; nt < 8; nt++) {
                float p0 = exp2f(fmaf(S[nt][2 * i],     C2F, BFOLD));
                float p1 = exp2f(fmaf(S[nt][2 * i + 1], C2F, BFOLD));
                S[nt][2 * i] = p0; S[nt][2 * i + 1] = p1;
                rs += p0 + p1;
            }
            rs += __shfl_xor_sync(0xffffffffu, rs, 1);
            rs += __shfl_xor_sync(0xffffffffu, rs, 2);
            lrow[i] += rs;
        }

        // ---- O += P_scaled Vh ----
        #pragma unroll
        for (int ks = 0; ks < 4; ks++) {
            uint32_t ah0 = packh(S[2 * ks][0],     S[2 * ks][1]);
            uint32_t ah1 = packh(S[2 * ks][2],     S[2 * ks][3]);
            uint32_t ah2 = packh(S[2 * ks + 1][0], S[2 * ks + 1][1]);
            uint32_t ah3 = packh(S[2 * ks + 1][2], S[2 * ks + 1][3]);
            uint32_t vh4[16];
            #pragma unroll
            for (int p = 0; p < 4; p++)
                ldsm_b(vhT, p * 16, ks * 32, lane, vh4 + p * 4);
            #pragma unroll
            for (int nt = 0; nt < 8; nt++)
                mma16816(Oa[nt], ah0, ah1, ah2, ah3, vh4[2 * nt], vh4[2 * nt + 1]);
        }
        __syncthreads();
    }

    // ---- epilogue: O = Oa / lrow, store fp16 [s,b,D] ----
    const float inv0 = 1.0f / lrow[0];
    const float inv1 = 1.0f / lrow[1];
    const int r = lane >> 2, c2 = (lane & 3) * 2;
    const int srow0 = q0 + qrow0 + r;
    #pragma unroll
    for (int nt = 0; nt < 8; nt++) {
        int col = h * 64 + nt * 8 + c2;
        float o00 = Oa[nt][0] * inv0, o01 = Oa[nt][1] * inv0;
        float o10 = Oa[nt][2] * inv1, o11 = Oa[nt][3] * inv1;
        size_t off0 = ((size_t)srow0 * BB + b) * DD + col;
        size_t off1 = ((size_t)(srow0 + 8) * BB + b) * DD + col;
        *(uint32_t*)(ah_g + off0) = packh(o00, o01);
        *(uint32_t*)(ah_g + off1) = packh(o10, o11);
    }
}

// ---------------------------------------------------------------------------
extern "C" void kernel_launch(void* const* d_in, const int* in_sizes, int n_in,
                              void* d_out, int out_size)
{
    const float* x    = (const float*)d_in[0];
    const float* beta = (const float*)d_in[2];
    const float* Wq   = (const float*)d_in[3];
    const float* bq   = (const float*)d_in[4];
    const float* Wk   = (const float*)d_in[5];
    const float* bk   = (const float*)d_in[6];
    const float* Wv   = (const float*)d_in[7];
    const float* bv   = (const float*)d_in[8];
    const float* Wo   = (const float*)d_in[9];
    const float* bo   = (const float*)d_in[10];
    float* out = (float*)d_out;

    __half *xh, *qh, *kh, *vh, *ah;
    cudaGetSymbolAddress((void**)&xh, g_xh);
    cudaGetSymbolAddress((void**)&qh, g_qh);
    cudaGetSymbolAddress((void**)&kh, g_kh);
    cudaGetSymbolAddress((void**)&vh, g_vh);
    cudaGetSymbolAddress((void**)&ah, g_ah);

    cudaFuncSetAttribute(gemm_qkv_kernel,
                         cudaFuncAttributeMaxDynamicSharedMemorySize, GEMM_SMEM);
    cudaFuncSetAttribute(gemm_out_kernel,
                         cudaFuncAttributeMaxDynamicSharedMemorySize, GEMM_SMEM);
    cudaFuncSetAttribute(flash_mma_kernel,
                         cudaFuncAttributeMaxDynamicSharedMemorySize, FLASH_SMEM);

    const int nx4 = MM * DD / 4;
    const int nw4 = DD * DD / 4;

    convx_kernel<<<(nx4 + 255) / 256, 256>>>(x, xh, nx4);
    {
        dim3 sg((nw4 + 255) / 256, 4);
        split4_kernel<<<sg, 256>>>(Wq, Wk, Wv, Wo, nw4);
    }

    dim3 qkvgrid(DD / 64, MM / 128, 3);   // (16, 64, 3)
    gemm_qkv_kernel<<<qkvgrid, 256, GEMM_SMEM>>>(beta, bq, bk, bv);

    dim3 fgrid(SEQ / 64, HH, BB);   // (32, 16, 4)
    flash_mma_kernel<<<fgrid, 128, FLASH_SMEM>>>(qh, kh, vh, ah);

    dim3 ogrid(DD / 64, MM / 128);   // (16, 64)
    gemm_out_kernel<<<ogrid, 256, GEMM_SMEM>>>(bo, out);
}